// round 10
// baseline (speedup 1.0000x reference)
#include <cuda_runtime.h>
#include <cuda_bf16.h>
#include <math.h>
#include <stdint.h>

#define E_DIM 2048
#define SEQ 2048
#define NBATCH 2
#define NHEAD 16
#define HD 128
#define MROWS (NBATCH * SEQ) /* 4096 */

// ---------------- scratch (device globals; no allocation allowed) ----------
__device__ __nv_bfloat16 g_x_hi[MROWS * E_DIM];
__device__ __nv_bfloat16 g_x_lo[MROWS * E_DIM];
__device__ __nv_bfloat16 g_w_hi[4 * E_DIM * E_DIM];
__device__ __nv_bfloat16 g_w_lo[4 * E_DIM * E_DIM];
__device__ __nv_bfloat16 g_qhi[MROWS * E_DIM];
__device__ __nv_bfloat16 g_qlo[MROWS * E_DIM];
__device__ __nv_bfloat16 g_khi[MROWS * E_DIM];
__device__ __nv_bfloat16 g_klo[MROWS * E_DIM];
__device__ __nv_bfloat16 g_vhi[MROWS * E_DIM];
__device__ __nv_bfloat16 g_vlo[MROWS * E_DIM];
__device__ __nv_bfloat16 g_vthi[MROWS * E_DIM];
__device__ __nv_bfloat16 g_vtlo[MROWS * E_DIM];
__device__ __nv_bfloat16 g_attn_hi[MROWS * E_DIM];
__device__ __nv_bfloat16 g_attn_lo[MROWS * E_DIM];
__device__ float g_cos[SEQ * (HD / 2)];
__device__ float g_sin[SEQ * (HD / 2)];

// ---------------- helpers ----------------------------------------------------
__device__ __forceinline__ uint32_t smem_u32(const void* p) {
    uint32_t a;
    asm("{ .reg .u64 t; cvta.to.shared.u64 t, %1; cvt.u32.u64 %0, t; }"
        : "=r"(a) : "l"(p));
    return a;
}
__device__ __forceinline__ void cp_async16(uint32_t dst, const void* src) {
    asm volatile("cp.async.cg.shared.global [%0], [%1], 16;"
                 :: "r"(dst), "l"(src));
}
#define CP_COMMIT() asm volatile("cp.async.commit_group;" ::: "memory")
#define CP_WAIT2() asm volatile("cp.async.wait_group 2;" ::: "memory")
#define CP_WAIT1() asm volatile("cp.async.wait_group 1;" ::: "memory")

__device__ __forceinline__ void ldsm_x4(uint32_t addr, uint32_t* r) {
    asm volatile("ldmatrix.sync.aligned.m8n8.x4.shared.b16 {%0,%1,%2,%3}, [%4];"
                 : "=r"(r[0]), "=r"(r[1]), "=r"(r[2]), "=r"(r[3]) : "r"(addr));
}

__device__ __forceinline__ void mma_bf16(float* d, const uint32_t* a,
                                         const uint32_t* b) {
    asm volatile(
        "mma.sync.aligned.m16n8k16.row.col.f32.bf16.bf16.f32 "
        "{%0,%1,%2,%3}, {%4,%5,%6,%7}, {%8,%9}, {%0,%1,%2,%3};"
        : "+f"(d[0]), "+f"(d[1]), "+f"(d[2]), "+f"(d[3])
        : "r"(a[0]), "r"(a[1]), "r"(a[2]), "r"(a[3]), "r"(b[0]), "r"(b[1]));
}

__device__ __forceinline__ void split_pack(float x, float y, uint32_t& hi,
                                           uint32_t& lo) {
    __nv_bfloat16 hx = __float2bfloat16(x), hy = __float2bfloat16(y);
    __nv_bfloat162 h2(hx, hy);
    hi = *(uint32_t*)&h2;
    __nv_bfloat162 l2(__float2bfloat16(x - __bfloat162float(hx)),
                      __float2bfloat16(y - __bfloat162float(hy)));
    lo = *(uint32_t*)&l2;
}

__device__ __forceinline__ void split_store2(__nv_bfloat16* hi,
                                             __nv_bfloat16* lo, size_t idx,
                                             float x, float y) {
    uint32_t h, l;
    split_pack(x, y, h, l);
    *(uint32_t*)(hi + idx) = h;
    *(uint32_t*)(lo + idx) = l;
}

// ---------------- RoPE table ------------------------------------------------
__global__ void rope_init_kernel() {
    int idx = blockIdx.x * blockDim.x + threadIdx.x;
    if (idx >= SEQ * (HD / 2)) return;
    int pos = idx / (HD / 2);
    int i = idx % (HD / 2);
    double invd = pow(10000.0, -(double)(2 * i) / (double)HD);
    float inv = (float)invd;
    float ang = (float)pos * inv;
    g_cos[idx] = (float)cos((double)ang);
    g_sin[idx] = (float)sin((double)ang);
}

// ---------------- fp32 -> split bf16 conversion -----------------------------
__device__ __forceinline__ void split_store4(__nv_bfloat162* hi,
                                             __nv_bfloat162* lo, int i,
                                             float4 v) {
    __nv_bfloat16 h0 = __float2bfloat16(v.x);
    __nv_bfloat16 h1 = __float2bfloat16(v.y);
    __nv_bfloat16 h2 = __float2bfloat16(v.z);
    __nv_bfloat16 h3 = __float2bfloat16(v.w);
    hi[i * 2 + 0] = __nv_bfloat162(h0, h1);
    hi[i * 2 + 1] = __nv_bfloat162(h2, h3);
    lo[i * 2 + 0] = __nv_bfloat162(__float2bfloat16(v.x - __bfloat162float(h0)),
                                   __float2bfloat16(v.y - __bfloat162float(h1)));
    lo[i * 2 + 1] = __nv_bfloat162(__float2bfloat16(v.z - __bfloat162float(h2)),
                                   __float2bfloat16(v.w - __bfloat162float(h3)));
}

__global__ void convert_x_kernel(const float4* __restrict__ src) {
    int i = blockIdx.x * blockDim.x + threadIdx.x;
    if (i >= MROWS * E_DIM / 4) return;
    split_store4((__nv_bfloat162*)g_x_hi, (__nv_bfloat162*)g_x_lo, i, src[i]);
}

__global__ void convert_w_kernel(const float4* __restrict__ w0,
                                 const float4* __restrict__ w1,
                                 const float4* __restrict__ w2,
                                 const float4* __restrict__ w3) {
    int i = blockIdx.x * blockDim.x + threadIdx.x;
    if (i >= E_DIM * E_DIM / 4) return;
    int z = blockIdx.y;
    const float4* src = (z == 0) ? w0 : (z == 1) ? w1 : (z == 2) ? w2 : w3;
    split_store4((__nv_bfloat162*)(g_w_hi + (size_t)z * E_DIM * E_DIM),
                 (__nv_bfloat162*)(g_w_lo + (size_t)z * E_DIM * E_DIM), i, src[i]);
}

// ---------------- HMMA GEMM: 128x256 tile, 512 thr, cp.async 4-stage --------
#define GBM 128
#define GBN 256
#define GBK 16
#define NCHUNK (E_DIM / GBK) /* 128 */
#define BSTR 48
#define A_TILE (128 * BSTR)              /* 6144 */
#define B_TILE (256 * BSTR)              /* 12288 */
#define STAGE_BYTES (2 * A_TILE + 2 * B_TILE) /* 36864 */
#define NSTAGE 4
#define GEMM_SMEM (NSTAGE * STAGE_BYTES) /* 147456 */
/* stage layout: A_hi @0, A_lo @6144, B_hi @12288, B_lo @24576 */

// mode: 0=Q (rope+scale), 1=K (rope), 2=V, 3=fp32 out
__device__ __forceinline__ void gemm_mma_body(
    const __nv_bfloat16* __restrict__ Ahi, const __nv_bfloat16* __restrict__ Alo,
    const __nv_bfloat16* __restrict__ Bhi, const __nv_bfloat16* __restrict__ Blo,
    float* __restrict__ Cout, int mode) {
    extern __shared__ char smem[];
    uint32_t sbase = smem_u32(smem);
    int tid = threadIdx.x;
    int wid = tid >> 5;
    int lane = tid & 31;
    int m0 = blockIdx.y * GBM;
    int n0 = blockIdx.x * GBN;
    int warp_m = (wid & 3) * 32;
    int warp_n = (wid >> 2) * 64;

    int gidx = lane >> 2;

    int a_row = (lane & 7) + ((lane >> 3) & 1) * 8;
    int a_col = (lane >> 4) * 16;
    uint32_t a_off[2];
#pragma unroll
    for (int mi = 0; mi < 2; mi++)
        a_off[mi] = (uint32_t)((warp_m + mi * 16 + a_row) * BSTR + a_col);
    int b_row = (lane & 7) + ((lane >> 4) & 1) * 8;
    int b_col = ((lane >> 3) & 1) * 16;
    uint32_t b_off[4];
#pragma unroll
    for (int njp = 0; njp < 4; njp++)
        b_off[njp] = (uint32_t)((warp_n + njp * 16 + b_row) * BSTR + b_col);

    // staging: A: 1 xfer/thread (tid<256 hi, else lo); B: 2 xfers/thread
    int a_sel = tid >> 8;          // 0 = hi, 1 = lo
    int a_r = tid & 255;
    int a_grow = a_r >> 1;
    int a_ge = (a_r & 1) * 8;
    uint32_t a_soff = (uint32_t)(a_sel * A_TILE + a_grow * BSTR + (a_r & 1) * 16);
    const __nv_bfloat16* pa =
        (a_sel ? Alo : Ahi) + (size_t)(m0 + a_grow) * E_DIM + a_ge;

    uint32_t b_soff[2];
    const __nv_bfloat16* pb[2];
#pragma unroll
    for (int i = 0; i < 2; i++) {
        int idx = tid + i * 512;
        int sel = idx >> 9;
        int r = idx & 511;
        int grow = r >> 1;
        b_soff[i] = (uint32_t)(2 * A_TILE + sel * B_TILE + grow * BSTR + (r & 1) * 16);
        pb[i] = (sel ? Blo : Bhi) + (size_t)(n0 + grow) * E_DIM + (r & 1) * 8;
    }

    float acc[2][8][4];
#pragma unroll
    for (int mi = 0; mi < 2; mi++)
#pragma unroll
        for (int nj = 0; nj < 8; nj++)
#pragma unroll
            for (int q = 0; q < 4; q++) acc[mi][nj][q] = 0.f;

#pragma unroll
    for (int s = 0; s < NSTAGE - 1; s++) {
        uint32_t st = sbase + s * STAGE_BYTES;
        int k0 = s * GBK;
        cp_async16(st + a_soff, pa + k0);
        cp_async16(st + b_soff[0], pb[0] + k0);
        cp_async16(st + b_soff[1], pb[1] + k0);
        CP_COMMIT();
    }

    for (int c = 0; c < NCHUNK; c++) {
        CP_WAIT2();
        __syncthreads();

        uint32_t st = sbase + (uint32_t)(c & (NSTAGE - 1)) * STAGE_BYTES;

        uint32_t ahi[2][4], alo[2][4];
#pragma unroll
        for (int mi = 0; mi < 2; mi++) {
            ldsm_x4(st + a_off[mi], ahi[mi]);
            ldsm_x4(st + A_TILE + a_off[mi], alo[mi]);
        }
#pragma unroll
        for (int njp = 0; njp < 4; njp++) {
            uint32_t bh4[4], bl4[4];
            ldsm_x4(st + 2 * A_TILE + b_off[njp], bh4);
            ldsm_x4(st + 2 * A_TILE + B_TILE + b_off[njp], bl4);
            int nj0 = njp * 2, nj1 = njp * 2 + 1;
            mma_bf16(acc[0][nj0], ahi[0], bh4 + 0);
            mma_bf16(acc[1][nj0], ahi[1], bh4 + 0);
            mma_bf16(acc[0][nj1], ahi[0], bh4 + 2);
            mma_bf16(acc[1][nj1], ahi[1], bh4 + 2);
            mma_bf16(acc[0][nj0], ahi[0], bl4 + 0);
            mma_bf16(acc[1][nj0], ahi[1], bl4 + 0);
            mma_bf16(acc[0][nj1], ahi[0], bl4 + 2);
            mma_bf16(acc[1][nj1], ahi[1], bl4 + 2);
            mma_bf16(acc[0][nj0], alo[0], bh4 + 0);
            mma_bf16(acc[1][nj0], alo[1], bh4 + 0);
            mma_bf16(acc[0][nj1], alo[0], bh4 + 2);
            mma_bf16(acc[1][nj1], alo[1], bh4 + 2);
        }

        if (c + NSTAGE - 1 < NCHUNK) {
            uint32_t sw = sbase + ((c + NSTAGE - 1) & (NSTAGE - 1)) * STAGE_BYTES;
            int k0 = (c + NSTAGE - 1) * GBK;
            cp_async16(sw + a_soff, pa + k0);
            cp_async16(sw + b_soff[0], pb[0] + k0);
            cp_async16(sw + b_soff[1], pb[1] + k0);
        }
        CP_COMMIT();
    }

    int tig = lane & 3;
    __nv_bfloat16* dhi = (mode == 0) ? g_qhi : (mode == 1) ? g_khi : g_vhi;
    __nv_bfloat16* dlo = (mode == 0) ? g_qlo : (mode == 1) ? g_klo : g_vlo;
    const float qsc = (mode == 0) ? 0.08838834764831845f : 1.0f;

#pragma unroll
    for (int mi = 0; mi < 2; mi++) {
#pragma unroll
        for (int nj = 0; nj < 8; nj++) {
            int m = m0 + warp_m + mi * 16 + gidx;
            int n = n0 + warp_n + nj * 8 + tig * 2;
            float v0 = acc[mi][nj][0], v1 = acc[mi][nj][1];
            float v2 = acc[mi][nj][2], v3 = acc[mi][nj][3];
            if (mode <= 1) {
                int pi = (n & (HD - 1)) >> 1;
                int p0 = m & (SEQ - 1);
                int p8 = p0 + 8;
                float c0 = g_cos[p0 * (HD / 2) + pi], s0 = g_sin[p0 * (HD / 2) + pi];
                float c8 = g_cos[p8 * (HD / 2) + pi], s8 = g_sin[p8 * (HD / 2) + pi];
                float t0 = v0 * c0 - v1 * s0, t1 = v0 * s0 + v1 * c0;
                float t2 = v2 * c8 - v3 * s8, t3 = v2 * s8 + v3 * c8;
                v0 = t0 * qsc; v1 = t1 * qsc; v2 = t2 * qsc; v3 = t3 * qsc;
            }
            if (mode == 3) {
                *(float2*)&Cout[(size_t)m * E_DIM + n] = make_float2(v0, v1);
                *(float2*)&Cout[(size_t)(m + 8) * E_DIM + n] = make_float2(v2, v3);
            } else {
                int b = m >> 11, s = m & 2047, h = n >> 7, d = n & 127;
                size_t base0 = ((size_t)(b * NHEAD + h) * SEQ + s) * HD + d;
                size_t base1 = base0 + 8 * HD;
                split_store2(dhi, dlo, base0, v0, v1);
                split_store2(dhi, dlo, base1, v2, v3);
            }
        }
    }
}

__global__ __launch_bounds__(512, 1) void gemm_qkv_tc(void) {
    int z = blockIdx.z;
    const __nv_bfloat16* bh = g_w_hi + (size_t)z * E_DIM * E_DIM;
    const __nv_bfloat16* bl = g_w_lo + (size_t)z * E_DIM * E_DIM;
    gemm_mma_body(g_x_hi, g_x_lo, bh, bl, nullptr, z);
}

__global__ __launch_bounds__(512, 1) void gemm_out_tc(float* __restrict__ out) {
    const __nv_bfloat16* bh = g_w_hi + (size_t)3 * E_DIM * E_DIM;
    const __nv_bfloat16* bl = g_w_lo + (size_t)3 * E_DIM * E_DIM;
    gemm_mma_body(g_attn_hi, g_attn_lo, bh, bl, out, 3);
}

// ---------------- V transpose: [bh][s][d] -> [bh][d][s] ---------------------
__global__ void transpose_v_kernel() {
    __shared__ __nv_bfloat16 t[32][33];
    int bh = blockIdx.z >> 1;
    const __nv_bfloat16* src = (blockIdx.z & 1) ? g_vlo : g_vhi;
    __nv_bfloat16* dst = (blockIdx.z & 1) ? g_vtlo : g_vthi;
    int tx = threadIdx.x, ty = threadIdx.y;
    int s0 = blockIdx.x * 32, d0 = blockIdx.y * 32;
#pragma unroll
    for (int i = 0; i < 32; i += 8)
        t[ty + i][tx] = src[((size_t)bh * SEQ + s0 + ty + i) * HD + d0 + tx];
    __syncthreads();
#pragma unroll
    for (int i = 0; i < 32; i += 8)
        dst[((size_t)bh * HD + d0 + ty + i) * SEQ + s0 + tx] = t[tx][ty + i];
}

// ---------------- Tensor-core flash attention (causal, cp.async DB) ---------
// 8 warps, q-tile 128, k-tile 32, 2-stage double buffer.
#define KSTR2 272
#define VSTR2 80
#define F_KHI 0
#define F_KLO 8704
#define F_VHI (2 * 8704)
#define F_VLO (F_VHI + 128 * VSTR2)
#define F_STAGE (F_VLO + 128 * VSTR2) /* 37888 */
#define FLASH_SMEM (2 * F_STAGE)      /* 75776 */
#define FQT 128                        /* q-tile rows */

__device__ __forceinline__ void flash_stage_load(
    uint32_t sst, const __nv_bfloat16* Kh, const __nv_bfloat16* Kl,
    const __nv_bfloat16* Vh, const __nv_bfloat16* Vl, int kt2, int tid) {
    int k0 = kt2 * 32;
#pragma unroll
    for (int i = 0; i < 2; i++) {
        int idx = tid + i * 256;
        int row = idx >> 4, cc = idx & 15;
        uint32_t d = sst + (uint32_t)(row * KSTR2 + cc * 16);
        cp_async16(d + F_KHI, Kh + (size_t)(k0 + row) * HD + cc * 8);
        cp_async16(d + F_KLO, Kl + (size_t)(k0 + row) * HD + cc * 8);
    }
#pragma unroll
    for (int i = 0; i < 2; i++) {
        int idx = tid + i * 256;
        int row = idx >> 2, cc = idx & 3;
        uint32_t d = sst + (uint32_t)(row * VSTR2 + cc * 16);
        cp_async16(d + F_VHI, Vh + (size_t)row * SEQ + k0 + cc * 8);
        cp_async16(d + F_VLO, Vl + (size_t)row * SEQ + k0 + cc * 8);
    }
}

__global__ __launch_bounds__(256) void flash_mma_kernel() {
    extern __shared__ char sm[];
    uint32_t sm32 = smem_u32(sm);

    int tid = threadIdx.x;
    int wid = tid >> 5;
    int lane = tid & 31;
    int qt = (int)gridDim.x - 1 - (int)blockIdx.x;  // heavy tiles first
    int bh = blockIdx.y;
    int g = lane >> 2;
    int c = lane & 3;
    int warp_m = wid * 16;
    int nkt = 4 * (qt + 1);

    int b_row = (lane & 7) + ((lane >> 4) & 1) * 8;
    int b_col = ((lane >> 3) & 1) * 16;
    uint32_t k_off[2], v_off[8];
#pragma unroll
    for (int njp = 0; njp < 2; njp++)
        k_off[njp] = (uint32_t)((njp * 16 + b_row) * KSTR2 + b_col);
#pragma unroll
    for (int njp = 0; njp < 8; njp++)
        v_off[njp] = (uint32_t)((njp * 16 + b_row) * VSTR2 + b_col);

    const __nv_bfloat16* Kh = g_khi + (size_t)bh * SEQ * HD;
    const __nv_bfloat16* Kl = g_klo + (size_t)bh * SEQ * HD;
    const __nv_bfloat16* Vh = g_vthi + (size_t)bh * HD * SEQ;
    const __nv_bfloat16* Vl = g_vtlo + (size_t)bh * HD * SEQ;

    flash_stage_load(sm32, Kh, Kl, Vh, Vl, 0, tid);
    CP_COMMIT();

    uint32_t qh[8][4], ql[8][4];
    {
        const __nv_bfloat16* Qh =
            g_qhi + (size_t)bh * SEQ * HD + (size_t)qt * FQT * HD;
        const __nv_bfloat16* Ql =
            g_qlo + (size_t)bh * SEQ * HD + (size_t)qt * FQT * HD;
        int r0 = (warp_m + g) * HD, r1 = (warp_m + g + 8) * HD;
#pragma unroll
        for (int kc = 0; kc < 8; kc++) {
            int c0 = kc * 16 + c * 2, c1 = c0 + 8;
            qh[kc][0] = *(const uint32_t*)(Qh + r0 + c0);
            qh[kc][1] = *(const uint32_t*)(Qh + r1 + c0);
            qh[kc][2] = *(const uint32_t*)(Qh + r0 + c1);
            qh[kc][3] = *(const uint32_t*)(Qh + r1 + c1);
            ql[kc][0] = *(const uint32_t*)(Ql + r0 + c0);
            ql[kc][1] = *(const uint32_t*)(Ql + r1 + c0);
            ql[kc][2] = *(const uint32_t*)(Ql + r0 + c1);
            ql[kc][3] = *(const uint32_t*)(Ql + r1 + c1);
        }
    }

    float o[16][4];
#pragma unroll
    for (int t = 0; t < 16; t++)
#pragma unroll
        for (int q = 0; q < 4; q++) o[t][q] = 0.f;
    float m0 = -1e30f, m1 = -1e30f, l0 = 0.f, l1 = 0.f;

    for (int kt2 = 0; kt2 < nkt; kt2++) {
        if (kt2 + 1 < nkt)
            flash_stage_load(sm32 + ((kt2 + 1) & 1) * F_STAGE, Kh, Kl, Vh, Vl,
                             kt2 + 1, tid);
        CP_COMMIT();
        CP_WAIT1();
        __syncthreads();

        uint32_t st = sm32 + (uint32_t)(kt2 & 1) * F_STAGE;

        float s_acc[4][4];
#pragma unroll
        for (int nj = 0; nj < 4; nj++)
#pragma unroll
            for (int q = 0; q < 4; q++) s_acc[nj][q] = 0.f;

#pragma unroll
        for (int kc = 0; kc < 8; kc++) {
#pragma unroll
            for (int njp = 0; njp < 2; njp++) {
                uint32_t bh4[4], bl4[4];
                ldsm_x4(st + F_KHI + k_off[njp] + kc * 32, bh4);
                ldsm_x4(st + F_KLO + k_off[njp] + kc * 32, bl4);
                int nj0 = njp * 2, nj1 = njp * 2 + 1;
                mma_bf16(s_acc[nj0], qh[kc], bh4 + 0);
                mma_bf16(s_acc[nj1], qh[kc], bh4 + 2);
                mma_bf16(s_acc[nj0], qh[kc], bl4 + 0);
                mma_bf16(s_acc[nj1], qh[kc], bl4 + 2);
                mma_bf16(s_acc[nj0], ql[kc], bh4 + 0);
                mma_bf16(s_acc[nj1], ql[kc], bh4 + 2);
            }
        }

        if (kt2 >= 4 * qt) {
            int row0 = qt * FQT + warp_m + g, row1 = row0 + 8;
            int colb = kt2 * 32;
#pragma unroll
            for (int nj = 0; nj < 4; nj++) {
                int col = colb + nj * 8 + c * 2;
                if (col > row0) s_acc[nj][0] = -1e30f;
                if (col + 1 > row0) s_acc[nj][1] = -1e30f;
                if (col > row1) s_acc[nj][2] = -1e30f;
                if (col + 1 > row1) s_acc[nj][3] = -1e30f;
            }
        }

        float mt0 = -1e30f, mt1 = -1e30f;
#pragma unroll
        for (int nj = 0; nj < 4; nj++) {
            mt0 = fmaxf(mt0, fmaxf(s_acc[nj][0], s_acc[nj][1]));
            mt1 = fmaxf(mt1, fmaxf(s_acc[nj][2], s_acc[nj][3]));
        }
        mt0 = fmaxf(mt0, __shfl_xor_sync(0xffffffffu, mt0, 1));
        mt0 = fmaxf(mt0, __shfl_xor_sync(0xffffffffu, mt0, 2));
        mt1 = fmaxf(mt1, __shfl_xor_sync(0xffffffffu, mt1, 1));
        mt1 = fmaxf(mt1, __shfl_xor_sync(0xffffffffu, mt1, 2));
        float mn0 = fmaxf(m0, mt0), mn1 = fmaxf(m1, mt1);
        float a0 = __expf(m0 - mn0), a1 = __expf(m1 - mn1);
        m0 = mn0; m1 = mn1;
#pragma unroll
        for (int t = 0; t < 16; t++) {
            o[t][0] *= a0; o[t][1] *= a0;
            o[t][2] *= a1; o[t][3] *= a1;
        }
        float rs0 = 0.f, rs1 = 0.f;
#pragma unroll
        for (int nj = 0; nj < 4; nj++) {
            float p0 = __expf(s_acc[nj][0] - mn0);
            float p1 = __expf(s_acc[nj][1] - mn0);
            float p2 = __expf(s_acc[nj][2] - mn1);
            float p3 = __expf(s_acc[nj][3] - mn1);
            s_acc[nj][0] = p0; s_acc[nj][1] = p1;
            s_acc[nj][2] = p2; s_acc[nj][3] = p3;
            rs0 += p0 + p1; rs1 += p2 + p3;
        }
        l0 = l0 * a0 + rs0;
        l1 = l1 * a1 + rs1;

        uint32_t ph[2][4], pl[2][4];
#pragma unroll
        for (int kc = 0; kc < 2; kc++) {
            split_pack(s_acc[2 * kc][0], s_acc[2 * kc][1], ph[kc][0], pl[kc][0]);
            split_pack(s_acc[2 * kc][2], s_acc[2 * kc][3], ph[kc][1], pl[kc][1]);
            split_pack(s_acc[2 * kc + 1][0], s_acc[2 * kc + 1][1], ph[kc][2], pl[kc][2]);
            split_pack(s_acc[2 * kc + 1][2], s_acc[2 * kc + 1][3], ph[kc][3], pl[kc][3]);
        }

#pragma unroll
        for (int njp = 0; njp < 8; njp++) {
#pragma unroll
            for (int kc = 0; kc < 2; kc++) {
                uint32_t vh4[4], vl4[4];
                ldsm_x4(st + F_VHI + v_off[njp] + kc * 32, vh4);
                ldsm_x4(st + F_VLO + v_off[njp] + kc * 32, vl4);
                int nj0 = njp * 2, nj1 = njp * 2 + 1;
                mma_bf16(o[nj0], ph[kc], vh4 + 0);
                mma_bf16(o[nj1], ph[kc], vh4 + 2);
                mma_bf16(o[nj0], ph[kc], vl4 + 0);
                mma_bf16(o[nj1], ph[kc], vl4 + 2);
                mma_bf16(o[nj0], pl[kc], vh4 + 0);
                mma_bf16(o[nj1], pl[kc], vh4 + 2);
            }
        }
        __syncthreads();
    }

    l0 += __shfl_xor_sync(0xffffffffu, l0, 1);
    l0 += __shfl_xor_sync(0xffffffffu, l0, 2);
    l1 += __shfl_xor_sync(0xffffffffu, l1, 1);
    l1 += __shfl_xor_sync(0xffffffffu, l1, 2);
    float i0 = 1.0f / l0, i1 = 1.0f / l1;
    int b = bh >> 4, h = bh & 15;
    int s0 = qt * FQT + warp_m + g;
    size_t r0 = ((size_t)b * SEQ + s0) * E_DIM + h * HD;
    size_t r1 = ((size_t)b * SEQ + s0 + 8) * E_DIM + h * HD;
#pragma unroll
    for (int nj = 0; nj < 16; nj++) {
        int d = nj * 8 + c * 2;
        split_store2(g_attn_hi, g_attn_lo, r0 + d, o[nj][0] * i0, o[nj][1] * i0);
        split_store2(g_attn_hi, g_attn_lo, r1 + d, o[nj][2] * i1, o[nj][3] * i1);
    }
}

// ---------------- launcher ---------------------------------------------------
extern "C" void kernel_launch(void* const* d_in, const int* in_sizes, int n_in,
                              void* d_out, int out_size) {
    const float* x = (const float*)d_in[0];
    const float* Wq = (const float*)d_in[1];
    const float* Wk = (const float*)d_in[2];
    const float* Wv = (const float*)d_in[3];
    const float* Wo = (const float*)d_in[4];
    float* out = (float*)d_out;

    cudaFuncSetAttribute(gemm_qkv_tc, cudaFuncAttributeMaxDynamicSharedMemorySize,
                         GEMM_SMEM);
    cudaFuncSetAttribute(gemm_out_tc, cudaFuncAttributeMaxDynamicSharedMemorySize,
                         GEMM_SMEM);
    cudaFuncSetAttribute(flash_mma_kernel,
                         cudaFuncAttributeMaxDynamicSharedMemorySize, FLASH_SMEM);

    rope_init_kernel<<<(SEQ * (HD / 2) + 255) / 256, 256>>>();

    {
        int n4 = MROWS * E_DIM / 4;
        convert_x_kernel<<<(n4 + 255) / 256, 256>>>((const float4*)x);
        int w4 = E_DIM * E_DIM / 4;
        dim3 gw((w4 + 255) / 256, 4);
        convert_w_kernel<<<gw, 256>>>((const float4*)Wq, (const float4*)Wk,
                                      (const float4*)Wv, (const float4*)Wo);
    }

    dim3 gqkv(E_DIM / GBN, MROWS / GBM, 3);
    gemm_qkv_tc<<<gqkv, 512, GEMM_SMEM>>>();

    dim3 gtr(SEQ / 32, HD / 32, NBATCH * NHEAD * 2);
    transpose_v_kernel<<<gtr, dim3(32, 8)>>>();

    dim3 gfa(SEQ / FQT, NBATCH * NHEAD);
    flash_mma_kernel<<<gfa, 256, FLASH_SMEM>>>();

    dim3 gout(E_DIM / GBN, MROWS / GBM);
    gemm_out_tc<<<gout, 512, GEMM_SMEM>>>(out);
}

// round 11
// speedup vs baseline: 1.0683x; 1.0683x over previous
#include <cuda_runtime.h>
#include <cuda_bf16.h>
#include <math.h>
#include <stdint.h>

#define E_DIM 2048
#define SEQ 2048
#define NBATCH 2
#define NHEAD 16
#define HD 128
#define MROWS (NBATCH * SEQ) /* 4096 */

// ---------------- scratch (device globals; no allocation allowed) ----------
__device__ __nv_bfloat16 g_x_hi[MROWS * E_DIM];
__device__ __nv_bfloat16 g_x_lo[MROWS * E_DIM];
__device__ __nv_bfloat16 g_w_hi[4 * E_DIM * E_DIM];
__device__ __nv_bfloat16 g_w_lo[4 * E_DIM * E_DIM];
__device__ __nv_bfloat16 g_qhi[MROWS * E_DIM];
__device__ __nv_bfloat16 g_qlo[MROWS * E_DIM];
__device__ __nv_bfloat16 g_khi[MROWS * E_DIM];
__device__ __nv_bfloat16 g_klo[MROWS * E_DIM];
__device__ __nv_bfloat16 g_vhi[MROWS * E_DIM];
__device__ __nv_bfloat16 g_vlo[MROWS * E_DIM];
__device__ __nv_bfloat16 g_vthi[MROWS * E_DIM];
__device__ __nv_bfloat16 g_vtlo[MROWS * E_DIM];
__device__ __nv_bfloat16 g_attn_hi[MROWS * E_DIM];
__device__ __nv_bfloat16 g_attn_lo[MROWS * E_DIM];
__device__ float g_cos[SEQ * (HD / 2)];
__device__ float g_sin[SEQ * (HD / 2)];

// ---------------- helpers ----------------------------------------------------
__device__ __forceinline__ uint32_t smem_u32(const void* p) {
    uint32_t a;
    asm("{ .reg .u64 t; cvta.to.shared.u64 t, %1; cvt.u32.u64 %0, t; }"
        : "=r"(a) : "l"(p));
    return a;
}
__device__ __forceinline__ void cp_async16(uint32_t dst, const void* src) {
    asm volatile("cp.async.cg.shared.global [%0], [%1], 16;"
                 :: "r"(dst), "l"(src));
}
#define CP_COMMIT() asm volatile("cp.async.commit_group;" ::: "memory")
#define CP_WAIT2() asm volatile("cp.async.wait_group 2;" ::: "memory")
#define CP_WAIT1() asm volatile("cp.async.wait_group 1;" ::: "memory")

__device__ __forceinline__ void ldsm_x4(uint32_t addr, uint32_t* r) {
    asm volatile("ldmatrix.sync.aligned.m8n8.x4.shared.b16 {%0,%1,%2,%3}, [%4];"
                 : "=r"(r[0]), "=r"(r[1]), "=r"(r[2]), "=r"(r[3]) : "r"(addr));
}

__device__ __forceinline__ void mma_bf16(float* d, const uint32_t* a,
                                         const uint32_t* b) {
    asm volatile(
        "mma.sync.aligned.m16n8k16.row.col.f32.bf16.bf16.f32 "
        "{%0,%1,%2,%3}, {%4,%5,%6,%7}, {%8,%9}, {%0,%1,%2,%3};"
        : "+f"(d[0]), "+f"(d[1]), "+f"(d[2]), "+f"(d[3])
        : "r"(a[0]), "r"(a[1]), "r"(a[2]), "r"(a[3]), "r"(b[0]), "r"(b[1]));
}

__device__ __forceinline__ void split_pack(float x, float y, uint32_t& hi,
                                           uint32_t& lo) {
    __nv_bfloat16 hx = __float2bfloat16(x), hy = __float2bfloat16(y);
    __nv_bfloat162 h2(hx, hy);
    hi = *(uint32_t*)&h2;
    __nv_bfloat162 l2(__float2bfloat16(x - __bfloat162float(hx)),
                      __float2bfloat16(y - __bfloat162float(hy)));
    lo = *(uint32_t*)&l2;
}

__device__ __forceinline__ void split_store2(__nv_bfloat16* hi,
                                             __nv_bfloat16* lo, size_t idx,
                                             float x, float y) {
    uint32_t h, l;
    split_pack(x, y, h, l);
    *(uint32_t*)(hi + idx) = h;
    *(uint32_t*)(lo + idx) = l;
}

// ---------------- RoPE table ------------------------------------------------
__global__ void rope_init_kernel() {
    int idx = blockIdx.x * blockDim.x + threadIdx.x;
    if (idx >= SEQ * (HD / 2)) return;
    int pos = idx / (HD / 2);
    int i = idx % (HD / 2);
    double invd = pow(10000.0, -(double)(2 * i) / (double)HD);
    float inv = (float)invd;
    float ang = (float)pos * inv;
    g_cos[idx] = (float)cos((double)ang);
    g_sin[idx] = (float)sin((double)ang);
}

// ---------------- fp32 -> split bf16 conversion -----------------------------
__device__ __forceinline__ void split_store4(__nv_bfloat162* hi,
                                             __nv_bfloat162* lo, int i,
                                             float4 v) {
    __nv_bfloat16 h0 = __float2bfloat16(v.x);
    __nv_bfloat16 h1 = __float2bfloat16(v.y);
    __nv_bfloat16 h2 = __float2bfloat16(v.z);
    __nv_bfloat16 h3 = __float2bfloat16(v.w);
    hi[i * 2 + 0] = __nv_bfloat162(h0, h1);
    hi[i * 2 + 1] = __nv_bfloat162(h2, h3);
    lo[i * 2 + 0] = __nv_bfloat162(__float2bfloat16(v.x - __bfloat162float(h0)),
                                   __float2bfloat16(v.y - __bfloat162float(h1)));
    lo[i * 2 + 1] = __nv_bfloat162(__float2bfloat16(v.z - __bfloat162float(h2)),
                                   __float2bfloat16(v.w - __bfloat162float(h3)));
}

__global__ void convert_x_kernel(const float4* __restrict__ src) {
    int i = blockIdx.x * blockDim.x + threadIdx.x;
    if (i >= MROWS * E_DIM / 4) return;
    split_store4((__nv_bfloat162*)g_x_hi, (__nv_bfloat162*)g_x_lo, i, src[i]);
}

__global__ void convert_w_kernel(const float4* __restrict__ w0,
                                 const float4* __restrict__ w1,
                                 const float4* __restrict__ w2,
                                 const float4* __restrict__ w3) {
    int i = blockIdx.x * blockDim.x + threadIdx.x;
    if (i >= E_DIM * E_DIM / 4) return;
    int z = blockIdx.y;
    const float4* src = (z == 0) ? w0 : (z == 1) ? w1 : (z == 2) ? w2 : w3;
    split_store4((__nv_bfloat162*)(g_w_hi + (size_t)z * E_DIM * E_DIM),
                 (__nv_bfloat162*)(g_w_lo + (size_t)z * E_DIM * E_DIM), i, src[i]);
}

// ---------------- HMMA GEMM: 128x128, 256 thr, cp.async 4-stage (R9 cfg) ----
#define GBM 128
#define GBN 128
#define GBK 16
#define NCHUNK (E_DIM / GBK) /* 128 */
#define BSTR 48
#define TILE_BYTES (128 * BSTR)      /* 6144 */
#define STAGE_BYTES (4 * TILE_BYTES) /* 24576 */
#define NSTAGE 4
#define GEMM_SMEM (NSTAGE * STAGE_BYTES) /* 98304 */

// mode: 0=Q (rope+scale), 1=K (rope), 2=V, 3=fp32 out
__device__ __forceinline__ void gemm_mma_body(
    const __nv_bfloat16* __restrict__ Ahi, const __nv_bfloat16* __restrict__ Alo,
    const __nv_bfloat16* __restrict__ Bhi, const __nv_bfloat16* __restrict__ Blo,
    float* __restrict__ Cout, int mode) {
    extern __shared__ char smem[];
    uint32_t sbase = smem_u32(smem);
    int tid = threadIdx.x;
    int wid = tid >> 5;
    int lane = tid & 31;
    int m0 = blockIdx.y * GBM;
    int n0 = blockIdx.x * GBN;
    int warp_m = (wid & 3) * 32;
    int warp_n = (wid >> 2) * 64;

    int gidx = lane >> 2;

    int a_row = (lane & 7) + ((lane >> 3) & 1) * 8;
    int a_col = (lane >> 4) * 16;
    uint32_t a_off[2];
#pragma unroll
    for (int mi = 0; mi < 2; mi++)
        a_off[mi] = (uint32_t)((warp_m + mi * 16 + a_row) * BSTR + a_col);
    int b_row = (lane & 7) + ((lane >> 4) & 1) * 8;
    int b_col = ((lane >> 3) & 1) * 16;
    uint32_t b_off[4];
#pragma unroll
    for (int njp = 0; njp < 4; njp++)
        b_off[njp] = (uint32_t)((warp_n + njp * 16 + b_row) * BSTR + b_col);

    int row = tid >> 1;
    int ce = (tid & 1) * 8;
    uint32_t soff = (uint32_t)(row * BSTR + (tid & 1) * 16);
    const __nv_bfloat16* pa_hi = Ahi + (size_t)(m0 + row) * E_DIM + ce;
    const __nv_bfloat16* pa_lo = Alo + (size_t)(m0 + row) * E_DIM + ce;
    const __nv_bfloat16* pb_hi = Bhi + (size_t)(n0 + row) * E_DIM + ce;
    const __nv_bfloat16* pb_lo = Blo + (size_t)(n0 + row) * E_DIM + ce;

    float acc[2][8][4];
#pragma unroll
    for (int mi = 0; mi < 2; mi++)
#pragma unroll
        for (int nj = 0; nj < 8; nj++)
#pragma unroll
            for (int q = 0; q < 4; q++) acc[mi][nj][q] = 0.f;

#pragma unroll
    for (int s = 0; s < NSTAGE - 1; s++) {
        uint32_t st = sbase + s * STAGE_BYTES + soff;
        int k0 = s * GBK;
        cp_async16(st + 0 * TILE_BYTES, pa_hi + k0);
        cp_async16(st + 1 * TILE_BYTES, pa_lo + k0);
        cp_async16(st + 2 * TILE_BYTES, pb_hi + k0);
        cp_async16(st + 3 * TILE_BYTES, pb_lo + k0);
        CP_COMMIT();
    }

    for (int c = 0; c < NCHUNK; c++) {
        CP_WAIT2();
        __syncthreads();

        uint32_t st = sbase + (uint32_t)(c & (NSTAGE - 1)) * STAGE_BYTES;

        uint32_t ahi[2][4], alo[2][4];
#pragma unroll
        for (int mi = 0; mi < 2; mi++) {
            ldsm_x4(st + a_off[mi], ahi[mi]);
            ldsm_x4(st + TILE_BYTES + a_off[mi], alo[mi]);
        }
#pragma unroll
        for (int njp = 0; njp < 4; njp++) {
            uint32_t bh4[4], bl4[4];
            ldsm_x4(st + 2 * TILE_BYTES + b_off[njp], bh4);
            ldsm_x4(st + 3 * TILE_BYTES + b_off[njp], bl4);
            int nj0 = njp * 2, nj1 = njp * 2 + 1;
            mma_bf16(acc[0][nj0], ahi[0], bh4 + 0);
            mma_bf16(acc[1][nj0], ahi[1], bh4 + 0);
            mma_bf16(acc[0][nj1], ahi[0], bh4 + 2);
            mma_bf16(acc[1][nj1], ahi[1], bh4 + 2);
            mma_bf16(acc[0][nj0], ahi[0], bl4 + 0);
            mma_bf16(acc[1][nj0], ahi[1], bl4 + 0);
            mma_bf16(acc[0][nj1], ahi[0], bl4 + 2);
            mma_bf16(acc[1][nj1], ahi[1], bl4 + 2);
            mma_bf16(acc[0][nj0], alo[0], bh4 + 0);
            mma_bf16(acc[1][nj0], alo[1], bh4 + 0);
            mma_bf16(acc[0][nj1], alo[0], bh4 + 2);
            mma_bf16(acc[1][nj1], alo[1], bh4 + 2);
        }

        if (c + NSTAGE - 1 < NCHUNK) {
            uint32_t sw = sbase + ((c + NSTAGE - 1) & (NSTAGE - 1)) * STAGE_BYTES + soff;
            int k0 = (c + NSTAGE - 1) * GBK;
            cp_async16(sw + 0 * TILE_BYTES, pa_hi + k0);
            cp_async16(sw + 1 * TILE_BYTES, pa_lo + k0);
            cp_async16(sw + 2 * TILE_BYTES, pb_hi + k0);
            cp_async16(sw + 3 * TILE_BYTES, pb_lo + k0);
        }
        CP_COMMIT();
    }

    int tig = lane & 3;
    __nv_bfloat16* dhi = (mode == 0) ? g_qhi : (mode == 1) ? g_khi : g_vhi;
    __nv_bfloat16* dlo = (mode == 0) ? g_qlo : (mode == 1) ? g_klo : g_vlo;
    const float qsc = (mode == 0) ? 0.08838834764831845f : 1.0f;

#pragma unroll
    for (int mi = 0; mi < 2; mi++) {
#pragma unroll
        for (int nj = 0; nj < 8; nj++) {
            int m = m0 + warp_m + mi * 16 + gidx;
            int n = n0 + warp_n + nj * 8 + tig * 2;
            float v0 = acc[mi][nj][0], v1 = acc[mi][nj][1];
            float v2 = acc[mi][nj][2], v3 = acc[mi][nj][3];
            if (mode <= 1) {
                int pi = (n & (HD - 1)) >> 1;
                int p0 = m & (SEQ - 1);
                int p8 = p0 + 8;
                float c0 = g_cos[p0 * (HD / 2) + pi], s0 = g_sin[p0 * (HD / 2) + pi];
                float c8 = g_cos[p8 * (HD / 2) + pi], s8 = g_sin[p8 * (HD / 2) + pi];
                float t0 = v0 * c0 - v1 * s0, t1 = v0 * s0 + v1 * c0;
                float t2 = v2 * c8 - v3 * s8, t3 = v2 * s8 + v3 * c8;
                v0 = t0 * qsc; v1 = t1 * qsc; v2 = t2 * qsc; v3 = t3 * qsc;
            }
            if (mode == 3) {
                *(float2*)&Cout[(size_t)m * E_DIM + n] = make_float2(v0, v1);
                *(float2*)&Cout[(size_t)(m + 8) * E_DIM + n] = make_float2(v2, v3);
            } else {
                int b = m >> 11, s = m & 2047, h = n >> 7, d = n & 127;
                size_t base0 = ((size_t)(b * NHEAD + h) * SEQ + s) * HD + d;
                size_t base1 = base0 + 8 * HD;
                split_store2(dhi, dlo, base0, v0, v1);
                split_store2(dhi, dlo, base1, v2, v3);
            }
        }
    }
}

__global__ __launch_bounds__(256, 2) void gemm_qkv_tc(void) {
    int z = blockIdx.z;
    const __nv_bfloat16* bh = g_w_hi + (size_t)z * E_DIM * E_DIM;
    const __nv_bfloat16* bl = g_w_lo + (size_t)z * E_DIM * E_DIM;
    gemm_mma_body(g_x_hi, g_x_lo, bh, bl, nullptr, z);
}

__global__ __launch_bounds__(256, 2) void gemm_out_tc(float* __restrict__ out) {
    const __nv_bfloat16* bh = g_w_hi + (size_t)3 * E_DIM * E_DIM;
    const __nv_bfloat16* bl = g_w_lo + (size_t)3 * E_DIM * E_DIM;
    gemm_mma_body(g_attn_hi, g_attn_lo, bh, bl, out, 3);
}

// ---------------- V transpose: [bh][s][d] -> [bh][d][s] ---------------------
__global__ void transpose_v_kernel() {
    __shared__ __nv_bfloat16 t[32][33];
    int bh = blockIdx.z >> 1;
    const __nv_bfloat16* src = (blockIdx.z & 1) ? g_vlo : g_vhi;
    __nv_bfloat16* dst = (blockIdx.z & 1) ? g_vtlo : g_vthi;
    int tx = threadIdx.x, ty = threadIdx.y;
    int s0 = blockIdx.x * 32, d0 = blockIdx.y * 32;
#pragma unroll
    for (int i = 0; i < 32; i += 8)
        t[ty + i][tx] = src[((size_t)bh * SEQ + s0 + ty + i) * HD + d0 + tx];
    __syncthreads();
#pragma unroll
    for (int i = 0; i < 32; i += 8)
        dst[((size_t)bh * HD + d0 + ty + i) * SEQ + s0 + tx] = t[tx][ty + i];
}

// ---------------- Tensor-core flash attention (causal, cp.async DB) ---------
// 8 warps, q-tile 128, k-tile 32, 2-stage double buffer.
#define KSTR2 272
#define VSTR2 80
#define F_KHI 0
#define F_KLO 8704
#define F_VHI (2 * 8704)
#define F_VLO (F_VHI + 128 * VSTR2)
#define F_STAGE (F_VLO + 128 * VSTR2) /* 37888 */
#define FLASH_SMEM (2 * F_STAGE)      /* 75776 */
#define FQT 128                        /* q-tile rows */

__device__ __forceinline__ void flash_stage_load(
    uint32_t sst, const __nv_bfloat16* Kh, const __nv_bfloat16* Kl,
    const __nv_bfloat16* Vh, const __nv_bfloat16* Vl, int kt2, int tid) {
    int k0 = kt2 * 32;
#pragma unroll
    for (int i = 0; i < 2; i++) {
        int idx = tid + i * 256;
        int row = idx >> 4, cc = idx & 15;
        uint32_t d = sst + (uint32_t)(row * KSTR2 + cc * 16);
        cp_async16(d + F_KHI, Kh + (size_t)(k0 + row) * HD + cc * 8);
        cp_async16(d + F_KLO, Kl + (size_t)(k0 + row) * HD + cc * 8);
    }
#pragma unroll
    for (int i = 0; i < 2; i++) {
        int idx = tid + i * 256;
        int row = idx >> 2, cc = idx & 3;
        uint32_t d = sst + (uint32_t)(row * VSTR2 + cc * 16);
        cp_async16(d + F_VHI, Vh + (size_t)row * SEQ + k0 + cc * 8);
        cp_async16(d + F_VLO, Vl + (size_t)row * SEQ + k0 + cc * 8);
    }
}

__global__ __launch_bounds__(256) void flash_mma_kernel() {
    extern __shared__ char sm[];
    uint32_t sm32 = smem_u32(sm);

    int tid = threadIdx.x;
    int wid = tid >> 5;
    int lane = tid & 31;
    int qt = (int)gridDim.x - 1 - (int)blockIdx.x;  // heavy tiles first
    int bh = blockIdx.y;
    int g = lane >> 2;
    int c = lane & 3;
    int warp_m = wid * 16;
    int nkt = 4 * (qt + 1);

    int b_row = (lane & 7) + ((lane >> 4) & 1) * 8;
    int b_col = ((lane >> 3) & 1) * 16;
    uint32_t k_off[2], v_off[8];
#pragma unroll
    for (int njp = 0; njp < 2; njp++)
        k_off[njp] = (uint32_t)((njp * 16 + b_row) * KSTR2 + b_col);
#pragma unroll
    for (int njp = 0; njp < 8; njp++)
        v_off[njp] = (uint32_t)((njp * 16 + b_row) * VSTR2 + b_col);

    const __nv_bfloat16* Kh = g_khi + (size_t)bh * SEQ * HD;
    const __nv_bfloat16* Kl = g_klo + (size_t)bh * SEQ * HD;
    const __nv_bfloat16* Vh = g_vthi + (size_t)bh * HD * SEQ;
    const __nv_bfloat16* Vl = g_vtlo + (size_t)bh * HD * SEQ;

    flash_stage_load(sm32, Kh, Kl, Vh, Vl, 0, tid);
    CP_COMMIT();

    uint32_t qh[8][4], ql[8][4];
    {
        const __nv_bfloat16* Qh =
            g_qhi + (size_t)bh * SEQ * HD + (size_t)qt * FQT * HD;
        const __nv_bfloat16* Ql =
            g_qlo + (size_t)bh * SEQ * HD + (size_t)qt * FQT * HD;
        int r0 = (warp_m + g) * HD, r1 = (warp_m + g + 8) * HD;
#pragma unroll
        for (int kc = 0; kc < 8; kc++) {
            int c0 = kc * 16 + c * 2, c1 = c0 + 8;
            qh[kc][0] = *(const uint32_t*)(Qh + r0 + c0);
            qh[kc][1] = *(const uint32_t*)(Qh + r1 + c0);
            qh[kc][2] = *(const uint32_t*)(Qh + r0 + c1);
            qh[kc][3] = *(const uint32_t*)(Qh + r1 + c1);
            ql[kc][0] = *(const uint32_t*)(Ql + r0 + c0);
            ql[kc][1] = *(const uint32_t*)(Ql + r1 + c0);
            ql[kc][2] = *(const uint32_t*)(Ql + r0 + c1);
            ql[kc][3] = *(const uint32_t*)(Ql + r1 + c1);
        }
    }

    float o[16][4];
#pragma unroll
    for (int t = 0; t < 16; t++)
#pragma unroll
        for (int q = 0; q < 4; q++) o[t][q] = 0.f;
    float m0 = -1e30f, m1 = -1e30f, l0 = 0.f, l1 = 0.f;

    for (int kt2 = 0; kt2 < nkt; kt2++) {
        if (kt2 + 1 < nkt)
            flash_stage_load(sm32 + ((kt2 + 1) & 1) * F_STAGE, Kh, Kl, Vh, Vl,
                             kt2 + 1, tid);
        CP_COMMIT();
        CP_WAIT1();
        __syncthreads();

        uint32_t st = sm32 + (uint32_t)(kt2 & 1) * F_STAGE;

        float s_acc[4][4];
#pragma unroll
        for (int nj = 0; nj < 4; nj++)
#pragma unroll
            for (int q = 0; q < 4; q++) s_acc[nj][q] = 0.f;

#pragma unroll
        for (int kc = 0; kc < 8; kc++) {
#pragma unroll
            for (int njp = 0; njp < 2; njp++) {
                uint32_t bh4[4], bl4[4];
                ldsm_x4(st + F_KHI + k_off[njp] + kc * 32, bh4);
                ldsm_x4(st + F_KLO + k_off[njp] + kc * 32, bl4);
                int nj0 = njp * 2, nj1 = njp * 2 + 1;
                mma_bf16(s_acc[nj0], qh[kc], bh4 + 0);
                mma_bf16(s_acc[nj1], qh[kc], bh4 + 2);
                mma_bf16(s_acc[nj0], qh[kc], bl4 + 0);
                mma_bf16(s_acc[nj1], qh[kc], bl4 + 2);
                mma_bf16(s_acc[nj0], ql[kc], bh4 + 0);
                mma_bf16(s_acc[nj1], ql[kc], bh4 + 2);
            }
        }

        if (kt2 >= 4 * qt) {
            int row0 = qt * FQT + warp_m + g, row1 = row0 + 8;
            int colb = kt2 * 32;
#pragma unroll
            for (int nj = 0; nj < 4; nj++) {
                int col = colb + nj * 8 + c * 2;
                if (col > row0) s_acc[nj][0] = -1e30f;
                if (col + 1 > row0) s_acc[nj][1] = -1e30f;
                if (col > row1) s_acc[nj][2] = -1e30f;
                if (col + 1 > row1) s_acc[nj][3] = -1e30f;
            }
        }

        float mt0 = -1e30f, mt1 = -1e30f;
#pragma unroll
        for (int nj = 0; nj < 4; nj++) {
            mt0 = fmaxf(mt0, fmaxf(s_acc[nj][0], s_acc[nj][1]));
            mt1 = fmaxf(mt1, fmaxf(s_acc[nj][2], s_acc[nj][3]));
        }
        mt0 = fmaxf(mt0, __shfl_xor_sync(0xffffffffu, mt0, 1));
        mt0 = fmaxf(mt0, __shfl_xor_sync(0xffffffffu, mt0, 2));
        mt1 = fmaxf(mt1, __shfl_xor_sync(0xffffffffu, mt1, 1));
        mt1 = fmaxf(mt1, __shfl_xor_sync(0xffffffffu, mt1, 2));
        float mn0 = fmaxf(m0, mt0), mn1 = fmaxf(m1, mt1);
        float a0 = __expf(m0 - mn0), a1 = __expf(m1 - mn1);
        m0 = mn0; m1 = mn1;
#pragma unroll
        for (int t = 0; t < 16; t++) {
            o[t][0] *= a0; o[t][1] *= a0;
            o[t][2] *= a1; o[t][3] *= a1;
        }
        float rs0 = 0.f, rs1 = 0.f;
#pragma unroll
        for (int nj = 0; nj < 4; nj++) {
            float p0 = __expf(s_acc[nj][0] - mn0);
            float p1 = __expf(s_acc[nj][1] - mn0);
            float p2 = __expf(s_acc[nj][2] - mn1);
            float p3 = __expf(s_acc[nj][3] - mn1);
            s_acc[nj][0] = p0; s_acc[nj][1] = p1;
            s_acc[nj][2] = p2; s_acc[nj][3] = p3;
            rs0 += p0 + p1; rs1 += p2 + p3;
        }
        l0 = l0 * a0 + rs0;
        l1 = l1 * a1 + rs1;

        uint32_t ph[2][4], pl[2][4];
#pragma unroll
        for (int kc = 0; kc < 2; kc++) {
            split_pack(s_acc[2 * kc][0], s_acc[2 * kc][1], ph[kc][0], pl[kc][0]);
            split_pack(s_acc[2 * kc][2], s_acc[2 * kc][3], ph[kc][1], pl[kc][1]);
            split_pack(s_acc[2 * kc + 1][0], s_acc[2 * kc + 1][1], ph[kc][2], pl[kc][2]);
            split_pack(s_acc[2 * kc + 1][2], s_acc[2 * kc + 1][3], ph[kc][3], pl[kc][3]);
        }

#pragma unroll
        for (int njp = 0; njp < 8; njp++) {
#pragma unroll
            for (int kc = 0; kc < 2; kc++) {
                uint32_t vh4[4], vl4[4];
                ldsm_x4(st + F_VHI + v_off[njp] + kc * 32, vh4);
                ldsm_x4(st + F_VLO + v_off[njp] + kc * 32, vl4);
                int nj0 = njp * 2, nj1 = njp * 2 + 1;
                mma_bf16(o[nj0], ph[kc], vh4 + 0);
                mma_bf16(o[nj1], ph[kc], vh4 + 2);
                mma_bf16(o[nj0], ph[kc], vl4 + 0);
                mma_bf16(o[nj1], ph[kc], vl4 + 2);
                mma_bf16(o[nj0], pl[kc], vh4 + 0);
                mma_bf16(o[nj1], pl[kc], vh4 + 2);
            }
        }
        __syncthreads();
    }

    l0 += __shfl_xor_sync(0xffffffffu, l0, 1);
    l0 += __shfl_xor_sync(0xffffffffu, l0, 2);
    l1 += __shfl_xor_sync(0xffffffffu, l1, 1);
    l1 += __shfl_xor_sync(0xffffffffu, l1, 2);
    float i0 = 1.0f / l0, i1 = 1.0f / l1;
    int b = bh >> 4, h = bh & 15;
    int s0 = qt * FQT + warp_m + g;
    size_t r0 = ((size_t)b * SEQ + s0) * E_DIM + h * HD;
    size_t r1 = ((size_t)b * SEQ + s0 + 8) * E_DIM + h * HD;
#pragma unroll
    for (int nj = 0; nj < 16; nj++) {
        int d = nj * 8 + c * 2;
        split_store2(g_attn_hi, g_attn_lo, r0 + d, o[nj][0] * i0, o[nj][1] * i0);
        split_store2(g_attn_hi, g_attn_lo, r1 + d, o[nj][2] * i1, o[nj][3] * i1);
    }
}

// ---------------- launcher ---------------------------------------------------
extern "C" void kernel_launch(void* const* d_in, const int* in_sizes, int n_in,
                              void* d_out, int out_size) {
    const float* x = (const float*)d_in[0];
    const float* Wq = (const float*)d_in[1];
    const float* Wk = (const float*)d_in[2];
    const float* Wv = (const float*)d_in[3];
    const float* Wo = (const float*)d_in[4];
    float* out = (float*)d_out;

    cudaFuncSetAttribute(gemm_qkv_tc, cudaFuncAttributeMaxDynamicSharedMemorySize,
                         GEMM_SMEM);
    cudaFuncSetAttribute(gemm_out_tc, cudaFuncAttributeMaxDynamicSharedMemorySize,
                         GEMM_SMEM);
    cudaFuncSetAttribute(flash_mma_kernel,
                         cudaFuncAttributeMaxDynamicSharedMemorySize, FLASH_SMEM);

    rope_init_kernel<<<(SEQ * (HD / 2) + 255) / 256, 256>>>();

    {
        int n4 = MROWS * E_DIM / 4;
        convert_x_kernel<<<(n4 + 255) / 256, 256>>>((const float4*)x);
        int w4 = E_DIM * E_DIM / 4;
        dim3 gw((w4 + 255) / 256, 4);
        convert_w_kernel<<<gw, 256>>>((const float4*)Wq, (const float4*)Wk,
                                      (const float4*)Wv, (const float4*)Wo);
    }

    dim3 gqkv(E_DIM / GBN, MROWS / GBM, 3);
    gemm_qkv_tc<<<gqkv, 256, GEMM_SMEM>>>();

    dim3 gtr(SEQ / 32, HD / 32, NBATCH * NHEAD * 2);
    transpose_v_kernel<<<gtr, dim3(32, 8)>>>();

    dim3 gfa(SEQ / FQT, NBATCH * NHEAD);
    flash_mma_kernel<<<gfa, 256, FLASH_SMEM>>>();

    dim3 gout(E_DIM / GBN, MROWS / GBM);
    gemm_out_tc<<<gout, 256, GEMM_SMEM>>>(out);
}

// round 12
// speedup vs baseline: 1.5366x; 1.4383x over previous
#include <cuda_runtime.h>
#include <cuda_fp16.h>
#include <math.h>
#include <stdint.h>

#define E_DIM 2048
#define SEQ 2048
#define NBATCH 2
#define NHEAD 16
#define HD 128
#define MROWS (NBATCH * SEQ) /* 4096 */

// ---------------- scratch (device globals; no allocation allowed) ----------
__device__ __half g_x_hi[MROWS * E_DIM];
__device__ __half g_x_lo[MROWS * E_DIM];
__device__ __half g_w[4 * E_DIM * E_DIM];      // weights: single fp16
__device__ __half g_qhi[MROWS * E_DIM];        // Q: split (A-role)
__device__ __half g_qlo[MROWS * E_DIM];
__device__ __half g_k[MROWS * E_DIM];          // K: single (B-role)
__device__ __half g_v[MROWS * E_DIM];          // V: single
__device__ __half g_vt[MROWS * E_DIM];         // V transposed [bh][d][s]
__device__ __half g_attn_hi[MROWS * E_DIM];    // attn: split (A-role)
__device__ __half g_attn_lo[MROWS * E_DIM];
__device__ float g_cos[SEQ * (HD / 2)];
__device__ float g_sin[SEQ * (HD / 2)];

// ---------------- helpers ----------------------------------------------------
__device__ __forceinline__ uint32_t smem_u32(const void* p) {
    uint32_t a;
    asm("{ .reg .u64 t; cvta.to.shared.u64 t, %1; cvt.u32.u64 %0, t; }"
        : "=r"(a) : "l"(p));
    return a;
}
__device__ __forceinline__ void cp_async16(uint32_t dst, const void* src) {
    asm volatile("cp.async.cg.shared.global [%0], [%1], 16;"
                 :: "r"(dst), "l"(src));
}
#define CP_COMMIT() asm volatile("cp.async.commit_group;" ::: "memory")
#define CP_WAIT2() asm volatile("cp.async.wait_group 2;" ::: "memory")
#define CP_WAIT1() asm volatile("cp.async.wait_group 1;" ::: "memory")

__device__ __forceinline__ void ldsm_x4(uint32_t addr, uint32_t* r) {
    asm volatile("ldmatrix.sync.aligned.m8n8.x4.shared.b16 {%0,%1,%2,%3}, [%4];"
                 : "=r"(r[0]), "=r"(r[1]), "=r"(r[2]), "=r"(r[3]) : "r"(addr));
}

// D (fp32) += A (fp16 16x16) * B (fp16 16x8)
__device__ __forceinline__ void mma_f16(float* d, const uint32_t* a,
                                        const uint32_t* b) {
    asm volatile(
        "mma.sync.aligned.m16n8k16.row.col.f32.f16.f16.f32 "
        "{%0,%1,%2,%3}, {%4,%5,%6,%7}, {%8,%9}, {%0,%1,%2,%3};"
        : "+f"(d[0]), "+f"(d[1]), "+f"(d[2]), "+f"(d[3])
        : "r"(a[0]), "r"(a[1]), "r"(a[2]), "r"(a[3]), "r"(b[0]), "r"(b[1]));
}

__device__ __forceinline__ void split_pack_h(float x, float y, uint32_t& hi,
                                             uint32_t& lo) {
    __half hx = __float2half_rn(x), hy = __float2half_rn(y);
    __half2 h2(hx, hy);
    hi = *(uint32_t*)&h2;
    __half2 l2(__float2half_rn(x - __half2float(hx)),
               __float2half_rn(y - __half2float(hy)));
    lo = *(uint32_t*)&l2;
}

__device__ __forceinline__ void split_store2h(__half* hi, __half* lo,
                                              size_t idx, float x, float y) {
    uint32_t h, l;
    split_pack_h(x, y, h, l);
    *(uint32_t*)(hi + idx) = h;
    *(uint32_t*)(lo + idx) = l;
}

__device__ __forceinline__ void store2h(__half* dst, size_t idx, float x,
                                        float y) {
    __half2 h(__float2half_rn(x), __float2half_rn(y));
    *(__half2*)(dst + idx) = h;
}

// ---------------- RoPE table ------------------------------------------------
__global__ void rope_init_kernel() {
    int idx = blockIdx.x * blockDim.x + threadIdx.x;
    if (idx >= SEQ * (HD / 2)) return;
    int pos = idx / (HD / 2);
    int i = idx % (HD / 2);
    double invd = pow(10000.0, -(double)(2 * i) / (double)HD);
    float inv = (float)invd;
    float ang = (float)pos * inv;
    g_cos[idx] = (float)cos((double)ang);
    g_sin[idx] = (float)sin((double)ang);
}

// ---------------- conversions ------------------------------------------------
__global__ void convert_x_kernel(const float4* __restrict__ src) {
    int i = blockIdx.x * blockDim.x + threadIdx.x;
    if (i >= MROWS * E_DIM / 4) return;
    float4 v = src[i];
    uint32_t h0, l0, h1, l1;
    split_pack_h(v.x, v.y, h0, l0);
    split_pack_h(v.z, v.w, h1, l1);
    ((uint32_t*)g_x_hi)[i * 2 + 0] = h0;
    ((uint32_t*)g_x_hi)[i * 2 + 1] = h1;
    ((uint32_t*)g_x_lo)[i * 2 + 0] = l0;
    ((uint32_t*)g_x_lo)[i * 2 + 1] = l1;
}

__global__ void convert_w_kernel(const float4* __restrict__ w0,
                                 const float4* __restrict__ w1,
                                 const float4* __restrict__ w2,
                                 const float4* __restrict__ w3) {
    int i = blockIdx.x * blockDim.x + threadIdx.x;
    if (i >= E_DIM * E_DIM / 4) return;
    int z = blockIdx.y;
    const float4* src = (z == 0) ? w0 : (z == 1) ? w1 : (z == 2) ? w2 : w3;
    float4 v = src[i];
    __half2 a(__float2half_rn(v.x), __float2half_rn(v.y));
    __half2 b(__float2half_rn(v.z), __float2half_rn(v.w));
    __half2* dst = (__half2*)(g_w + (size_t)z * E_DIM * E_DIM);
    dst[i * 2 + 0] = a;
    dst[i * 2 + 1] = b;
}

// ---------------- HMMA GEMM: 128x128, fp16 2-term, cp.async 4-stage ---------
#define GBM 128
#define GBN 128
#define GBK 16
#define NCHUNK (E_DIM / GBK) /* 128 */
#define BSTR 48
#define TILE_BYTES (128 * BSTR)      /* 6144 */
#define STAGE_BYTES (3 * TILE_BYTES) /* 18432: A_hi, A_lo, B */
#define NSTAGE 4
#define GEMM_SMEM (NSTAGE * STAGE_BYTES) /* 73728 */

// mode: 0=Q (rope+scale, split out), 1=K (rope, single), 2=V (single), 3=fp32 out
__device__ __forceinline__ void gemm_mma_body(
    const __half* __restrict__ Ahi, const __half* __restrict__ Alo,
    const __half* __restrict__ B, float* __restrict__ Cout, int mode) {
    extern __shared__ char smem[];
    uint32_t sbase = smem_u32(smem);
    int tid = threadIdx.x;
    int wid = tid >> 5;
    int lane = tid & 31;
    int m0 = blockIdx.y * GBM;
    int n0 = blockIdx.x * GBN;
    int warp_m = (wid & 3) * 32;
    int warp_n = (wid >> 2) * 64;

    int gidx = lane >> 2;

    int a_row = (lane & 7) + ((lane >> 3) & 1) * 8;
    int a_col = (lane >> 4) * 16;
    uint32_t a_off[2];
#pragma unroll
    for (int mi = 0; mi < 2; mi++)
        a_off[mi] = (uint32_t)((warp_m + mi * 16 + a_row) * BSTR + a_col);
    int b_row = (lane & 7) + ((lane >> 4) & 1) * 8;
    int b_col = ((lane >> 3) & 1) * 16;
    uint32_t b_off[4];
#pragma unroll
    for (int njp = 0; njp < 4; njp++)
        b_off[njp] = (uint32_t)((warp_n + njp * 16 + b_row) * BSTR + b_col);

    int row = tid >> 1;
    int ce = (tid & 1) * 8;
    uint32_t soff = (uint32_t)(row * BSTR + (tid & 1) * 16);
    const __half* pa_hi = Ahi + (size_t)(m0 + row) * E_DIM + ce;
    const __half* pa_lo = Alo + (size_t)(m0 + row) * E_DIM + ce;
    const __half* pb = B + (size_t)(n0 + row) * E_DIM + ce;

    float acc[2][8][4];
#pragma unroll
    for (int mi = 0; mi < 2; mi++)
#pragma unroll
        for (int nj = 0; nj < 8; nj++)
#pragma unroll
            for (int q = 0; q < 4; q++) acc[mi][nj][q] = 0.f;

#pragma unroll
    for (int s = 0; s < NSTAGE - 1; s++) {
        uint32_t st = sbase + s * STAGE_BYTES + soff;
        int k0 = s * GBK;
        cp_async16(st + 0 * TILE_BYTES, pa_hi + k0);
        cp_async16(st + 1 * TILE_BYTES, pa_lo + k0);
        cp_async16(st + 2 * TILE_BYTES, pb + k0);
        CP_COMMIT();
    }

    for (int c = 0; c < NCHUNK; c++) {
        CP_WAIT2();
        __syncthreads();

        uint32_t st = sbase + (uint32_t)(c & (NSTAGE - 1)) * STAGE_BYTES;

        uint32_t ahi[2][4], alo[2][4];
#pragma unroll
        for (int mi = 0; mi < 2; mi++) {
            ldsm_x4(st + a_off[mi], ahi[mi]);
            ldsm_x4(st + TILE_BYTES + a_off[mi], alo[mi]);
        }
#pragma unroll
        for (int njp = 0; njp < 4; njp++) {
            uint32_t b4[4];
            ldsm_x4(st + 2 * TILE_BYTES + b_off[njp], b4);
            int nj0 = njp * 2, nj1 = njp * 2 + 1;
            mma_f16(acc[0][nj0], ahi[0], b4 + 0);
            mma_f16(acc[1][nj0], ahi[1], b4 + 0);
            mma_f16(acc[0][nj1], ahi[0], b4 + 2);
            mma_f16(acc[1][nj1], ahi[1], b4 + 2);
            mma_f16(acc[0][nj0], alo[0], b4 + 0);
            mma_f16(acc[1][nj0], alo[1], b4 + 0);
            mma_f16(acc[0][nj1], alo[0], b4 + 2);
            mma_f16(acc[1][nj1], alo[1], b4 + 2);
        }

        if (c + NSTAGE - 1 < NCHUNK) {
            uint32_t sw = sbase + ((c + NSTAGE - 1) & (NSTAGE - 1)) * STAGE_BYTES + soff;
            int k0 = (c + NSTAGE - 1) * GBK;
            cp_async16(sw + 0 * TILE_BYTES, pa_hi + k0);
            cp_async16(sw + 1 * TILE_BYTES, pa_lo + k0);
            cp_async16(sw + 2 * TILE_BYTES, pb + k0);
        }
        CP_COMMIT();
    }

    int tig = lane & 3;
    const float qsc = (mode == 0) ? 0.08838834764831845f : 1.0f;

#pragma unroll
    for (int mi = 0; mi < 2; mi++) {
#pragma unroll
        for (int nj = 0; nj < 8; nj++) {
            int m = m0 + warp_m + mi * 16 + gidx;
            int n = n0 + warp_n + nj * 8 + tig * 2;
            float v0 = acc[mi][nj][0], v1 = acc[mi][nj][1];
            float v2 = acc[mi][nj][2], v3 = acc[mi][nj][3];
            if (mode <= 1) {
                int pi = (n & (HD - 1)) >> 1;
                int p0 = m & (SEQ - 1);
                int p8 = p0 + 8;
                float c0 = g_cos[p0 * (HD / 2) + pi], s0 = g_sin[p0 * (HD / 2) + pi];
                float c8 = g_cos[p8 * (HD / 2) + pi], s8 = g_sin[p8 * (HD / 2) + pi];
                float t0 = v0 * c0 - v1 * s0, t1 = v0 * s0 + v1 * c0;
                float t2 = v2 * c8 - v3 * s8, t3 = v2 * s8 + v3 * c8;
                v0 = t0 * qsc; v1 = t1 * qsc; v2 = t2 * qsc; v3 = t3 * qsc;
            }
            if (mode == 3) {
                *(float2*)&Cout[(size_t)m * E_DIM + n] = make_float2(v0, v1);
                *(float2*)&Cout[(size_t)(m + 8) * E_DIM + n] = make_float2(v2, v3);
            } else {
                int b = m >> 11, s = m & 2047, h = n >> 7, d = n & 127;
                size_t base0 = ((size_t)(b * NHEAD + h) * SEQ + s) * HD + d;
                size_t base1 = base0 + 8 * HD;
                if (mode == 0) {
                    split_store2h(g_qhi, g_qlo, base0, v0, v1);
                    split_store2h(g_qhi, g_qlo, base1, v2, v3);
                } else if (mode == 1) {
                    store2h(g_k, base0, v0, v1);
                    store2h(g_k, base1, v2, v3);
                } else {
                    store2h(g_v, base0, v0, v1);
                    store2h(g_v, base1, v2, v3);
                }
            }
        }
    }
}

__global__ __launch_bounds__(256, 2) void gemm_qkv_tc(void) {
    int z = blockIdx.z;
    const __half* b = g_w + (size_t)z * E_DIM * E_DIM;
    gemm_mma_body(g_x_hi, g_x_lo, b, nullptr, z);
}

__global__ __launch_bounds__(256, 2) void gemm_out_tc(float* __restrict__ out) {
    const __half* b = g_w + (size_t)3 * E_DIM * E_DIM;
    gemm_mma_body(g_attn_hi, g_attn_lo, b, out, 3);
}

// ---------------- V transpose: [bh][s][d] -> [bh][d][s] ---------------------
__global__ void transpose_v_kernel() {
    __shared__ __half t[32][33];
    int bh = blockIdx.z;
    int tx = threadIdx.x, ty = threadIdx.y;
    int s0 = blockIdx.x * 32, d0 = blockIdx.y * 32;
#pragma unroll
    for (int i = 0; i < 32; i += 8)
        t[ty + i][tx] = g_v[((size_t)bh * SEQ + s0 + ty + i) * HD + d0 + tx];
    __syncthreads();
#pragma unroll
    for (int i = 0; i < 32; i += 8)
        g_vt[((size_t)bh * HD + d0 + ty + i) * SEQ + s0 + tx] = t[tx][ty + i];
}

// ---------------- Tensor-core flash attention (causal, cp.async DB) ---------
// 4 warps, q-tile 64, k-tile 32, 2-stage double buffer. fp16 2-term.
#define KSTR2 272 /* K row stride bytes (128 fp16 + pad) */
#define VSTR2 80  /* Vt row stride bytes (32 fp16 + pad) */
#define F_K 0
#define F_V 8704                    /* 32*272 */
#define F_STAGE (F_V + 128 * VSTR2) /* 18944 */
#define FLASH_SMEM (2 * F_STAGE)    /* 37888 */

__device__ __forceinline__ void flash_stage_load(uint32_t sst,
                                                 const __half* K,
                                                 const __half* Vt, int kt2,
                                                 int tid) {
    int k0 = kt2 * 32;
#pragma unroll
    for (int i = 0; i < 4; i++) {
        int idx = tid + i * 128;
        int row = idx >> 4, cc = idx & 15;
        cp_async16(sst + F_K + (uint32_t)(row * KSTR2 + cc * 16),
                   K + (size_t)(k0 + row) * HD + cc * 8);
    }
#pragma unroll
    for (int i = 0; i < 4; i++) {
        int idx = tid + i * 128;
        int row = idx >> 2, cc = idx & 3;
        cp_async16(sst + F_V + (uint32_t)(row * VSTR2 + cc * 16),
                   Vt + (size_t)row * SEQ + k0 + cc * 8);
    }
}

__global__ __launch_bounds__(128) void flash_mma_kernel() {
    extern __shared__ char sm[];
    uint32_t sm32 = smem_u32(sm);

    int tid = threadIdx.x;
    int wid = tid >> 5;
    int lane = tid & 31;
    int qt = (int)gridDim.x - 1 - (int)blockIdx.x;  // heavy tiles first
    int bh = blockIdx.y;
    int g = lane >> 2;
    int c = lane & 3;
    int warp_m = wid * 16;
    int nkt = 2 * (qt + 1);

    int b_row = (lane & 7) + ((lane >> 4) & 1) * 8;
    int b_col = ((lane >> 3) & 1) * 16;
    uint32_t k_off[2], v_off[8];
#pragma unroll
    for (int njp = 0; njp < 2; njp++)
        k_off[njp] = (uint32_t)((njp * 16 + b_row) * KSTR2 + b_col);
#pragma unroll
    for (int njp = 0; njp < 8; njp++)
        v_off[njp] = (uint32_t)((njp * 16 + b_row) * VSTR2 + b_col);

    const __half* K = g_k + (size_t)bh * SEQ * HD;
    const __half* Vt = g_vt + (size_t)bh * HD * SEQ;

    flash_stage_load(sm32, K, Vt, 0, tid);
    CP_COMMIT();

    uint32_t qh[8][4], ql[8][4];
    {
        const __half* Qh = g_qhi + (size_t)bh * SEQ * HD + (size_t)qt * 64 * HD;
        const __half* Ql = g_qlo + (size_t)bh * SEQ * HD + (size_t)qt * 64 * HD;
        int r0 = (warp_m + g) * HD, r1 = (warp_m + g + 8) * HD;
#pragma unroll
        for (int kc = 0; kc < 8; kc++) {
            int c0 = kc * 16 + c * 2, c1 = c0 + 8;
            qh[kc][0] = *(const uint32_t*)(Qh + r0 + c0);
            qh[kc][1] = *(const uint32_t*)(Qh + r1 + c0);
            qh[kc][2] = *(const uint32_t*)(Qh + r0 + c1);
            qh[kc][3] = *(const uint32_t*)(Qh + r1 + c1);
            ql[kc][0] = *(const uint32_t*)(Ql + r0 + c0);
            ql[kc][1] = *(const uint32_t*)(Ql + r1 + c0);
            ql[kc][2] = *(const uint32_t*)(Ql + r0 + c1);
            ql[kc][3] = *(const uint32_t*)(Ql + r1 + c1);
        }
    }

    float o[16][4];
#pragma unroll
    for (int t = 0; t < 16; t++)
#pragma unroll
        for (int q = 0; q < 4; q++) o[t][q] = 0.f;
    float m0 = -1e30f, m1 = -1e30f, l0 = 0.f, l1 = 0.f;

    for (int kt2 = 0; kt2 < nkt; kt2++) {
        if (kt2 + 1 < nkt)
            flash_stage_load(sm32 + ((kt2 + 1) & 1) * F_STAGE, K, Vt, kt2 + 1,
                             tid);
        CP_COMMIT();
        CP_WAIT1();
        __syncthreads();

        uint32_t st = sm32 + (uint32_t)(kt2 & 1) * F_STAGE;

        // ---- S = Q @ K^T (16q x 32k per warp) ----
        float s_acc[4][4];
#pragma unroll
        for (int nj = 0; nj < 4; nj++)
#pragma unroll
            for (int q = 0; q < 4; q++) s_acc[nj][q] = 0.f;

#pragma unroll
        for (int kc = 0; kc < 8; kc++) {
#pragma unroll
            for (int njp = 0; njp < 2; njp++) {
                uint32_t b4[4];
                ldsm_x4(st + F_K + k_off[njp] + kc * 32, b4);
                int nj0 = njp * 2, nj1 = njp * 2 + 1;
                mma_f16(s_acc[nj0], qh[kc], b4 + 0);
                mma_f16(s_acc[nj1], qh[kc], b4 + 2);
                mma_f16(s_acc[nj0], ql[kc], b4 + 0);
                mma_f16(s_acc[nj1], ql[kc], b4 + 2);
            }
        }

        // ---- causal mask (diagonal k-tiles only) ----
        if (kt2 >= 2 * qt) {
            int row0 = qt * 64 + warp_m + g, row1 = row0 + 8;
            int colb = kt2 * 32;
#pragma unroll
            for (int nj = 0; nj < 4; nj++) {
                int col = colb + nj * 8 + c * 2;
                if (col > row0) s_acc[nj][0] = -1e30f;
                if (col + 1 > row0) s_acc[nj][1] = -1e30f;
                if (col > row1) s_acc[nj][2] = -1e30f;
                if (col + 1 > row1) s_acc[nj][3] = -1e30f;
            }
        }

        // ---- online softmax ----
        float mt0 = -1e30f, mt1 = -1e30f;
#pragma unroll
        for (int nj = 0; nj < 4; nj++) {
            mt0 = fmaxf(mt0, fmaxf(s_acc[nj][0], s_acc[nj][1]));
            mt1 = fmaxf(mt1, fmaxf(s_acc[nj][2], s_acc[nj][3]));
        }
        mt0 = fmaxf(mt0, __shfl_xor_sync(0xffffffffu, mt0, 1));
        mt0 = fmaxf(mt0, __shfl_xor_sync(0xffffffffu, mt0, 2));
        mt1 = fmaxf(mt1, __shfl_xor_sync(0xffffffffu, mt1, 1));
        mt1 = fmaxf(mt1, __shfl_xor_sync(0xffffffffu, mt1, 2));
        float mn0 = fmaxf(m0, mt0), mn1 = fmaxf(m1, mt1);
        float a0 = __expf(m0 - mn0), a1 = __expf(m1 - mn1);
        m0 = mn0; m1 = mn1;
#pragma unroll
        for (int t = 0; t < 16; t++) {
            o[t][0] *= a0; o[t][1] *= a0;
            o[t][2] *= a1; o[t][3] *= a1;
        }
        float rs0 = 0.f, rs1 = 0.f;
#pragma unroll
        for (int nj = 0; nj < 4; nj++) {
            float p0 = __expf(s_acc[nj][0] - mn0);
            float p1 = __expf(s_acc[nj][1] - mn0);
            float p2 = __expf(s_acc[nj][2] - mn1);
            float p3 = __expf(s_acc[nj][3] - mn1);
            s_acc[nj][0] = p0; s_acc[nj][1] = p1;
            s_acc[nj][2] = p2; s_acc[nj][3] = p3;
            rs0 += p0 + p1; rs1 += p2 + p3;
        }
        l0 = l0 * a0 + rs0;
        l1 = l1 * a1 + rs1;

        // ---- P fragments (A-layout, fp16 split) ----
        uint32_t ph[2][4], pl[2][4];
#pragma unroll
        for (int kc = 0; kc < 2; kc++) {
            split_pack_h(s_acc[2 * kc][0], s_acc[2 * kc][1], ph[kc][0], pl[kc][0]);
            split_pack_h(s_acc[2 * kc][2], s_acc[2 * kc][3], ph[kc][1], pl[kc][1]);
            split_pack_h(s_acc[2 * kc + 1][0], s_acc[2 * kc + 1][1], ph[kc][2], pl[kc][2]);
            split_pack_h(s_acc[2 * kc + 1][2], s_acc[2 * kc + 1][3], ph[kc][3], pl[kc][3]);
        }

        // ---- O += P @ V ----
#pragma unroll
        for (int njp = 0; njp < 8; njp++) {
#pragma unroll
            for (int kc = 0; kc < 2; kc++) {
                uint32_t v4[4];
                ldsm_x4(st + F_V + v_off[njp] + kc * 32, v4);
                int nj0 = njp * 2, nj1 = njp * 2 + 1;
                mma_f16(o[nj0], ph[kc], v4 + 0);
                mma_f16(o[nj1], ph[kc], v4 + 2);
                mma_f16(o[nj0], pl[kc], v4 + 0);
                mma_f16(o[nj1], pl[kc], v4 + 2);
            }
        }
        __syncthreads();  // reads of this stage done before it is rewritten
    }

    l0 += __shfl_xor_sync(0xffffffffu, l0, 1);
    l0 += __shfl_xor_sync(0xffffffffu, l0, 2);
    l1 += __shfl_xor_sync(0xffffffffu, l1, 1);
    l1 += __shfl_xor_sync(0xffffffffu, l1, 2);
    float i0 = 1.0f / l0, i1 = 1.0f / l1;
    int b = bh >> 4, h = bh & 15;
    int s0 = qt * 64 + warp_m + g;
    size_t r0 = ((size_t)b * SEQ + s0) * E_DIM + h * HD;
    size_t r1 = ((size_t)b * SEQ + s0 + 8) * E_DIM + h * HD;
#pragma unroll
    for (int nj = 0; nj < 16; nj++) {
        int d = nj * 8 + c * 2;
        split_store2h(g_attn_hi, g_attn_lo, r0 + d, o[nj][0] * i0, o[nj][1] * i0);
        split_store2h(g_attn_hi, g_attn_lo, r1 + d, o[nj][2] * i1, o[nj][3] * i1);
    }
}

// ---------------- launcher ---------------------------------------------------
extern "C" void kernel_launch(void* const* d_in, const int* in_sizes, int n_in,
                              void* d_out, int out_size) {
    const float* x = (const float*)d_in[0];
    const float* Wq = (const float*)d_in[1];
    const float* Wk = (const float*)d_in[2];
    const float* Wv = (const float*)d_in[3];
    const float* Wo = (const float*)d_in[4];
    float* out = (float*)d_out;

    cudaFuncSetAttribute(gemm_qkv_tc, cudaFuncAttributeMaxDynamicSharedMemorySize,
                         GEMM_SMEM);
    cudaFuncSetAttribute(gemm_out_tc, cudaFuncAttributeMaxDynamicSharedMemorySize,
                         GEMM_SMEM);
    cudaFuncSetAttribute(flash_mma_kernel,
                         cudaFuncAttributeMaxDynamicSharedMemorySize, FLASH_SMEM);

    rope_init_kernel<<<(SEQ * (HD / 2) + 255) / 256, 256>>>();

    {
        int n4 = MROWS * E_DIM / 4;
        convert_x_kernel<<<(n4 + 255) / 256, 256>>>((const float4*)x);
        int w4 = E_DIM * E_DIM / 4;
        dim3 gw((w4 + 255) / 256, 4);
        convert_w_kernel<<<gw, 256>>>((const float4*)Wq, (const float4*)Wk,
                                      (const float4*)Wv, (const float4*)Wo);
    }

    dim3 gqkv(E_DIM / GBN, MROWS / GBM, 3);
    gemm_qkv_tc<<<gqkv, 256, GEMM_SMEM>>>();

    dim3 gtr(SEQ / 32, HD / 32, NBATCH * NHEAD);
    transpose_v_kernel<<<gtr, dim3(32, 8)>>>();

    dim3 gfa(SEQ / 64, NBATCH * NHEAD);
    flash_mma_kernel<<<gfa, 128, FLASH_SMEM>>>();

    dim3 gout(E_DIM / GBN, MROWS / GBM);
    gemm_out_tc<<<gout, 256, GEMM_SMEM>>>(out);
}

// round 13
// speedup vs baseline: 1.7679x; 1.1505x over previous
#include <cuda_runtime.h>
#include <cuda_fp16.h>
#include <math.h>
#include <stdint.h>

#define E_DIM 2048
#define SEQ 2048
#define NBATCH 2
#define NHEAD 16
#define HD 128
#define MROWS (NBATCH * SEQ) /* 4096 */

// ---------------- scratch (device globals; no allocation allowed) ----------
__device__ __half g_x_hi[MROWS * E_DIM];
__device__ __half g_x_lo[MROWS * E_DIM];
__device__ __half g_w[4 * E_DIM * E_DIM];
__device__ __half g_qhi[MROWS * E_DIM];
__device__ __half g_qlo[MROWS * E_DIM];
__device__ __half g_k[MROWS * E_DIM];
__device__ __half g_v[MROWS * E_DIM];
__device__ __half g_vt[MROWS * E_DIM];
__device__ __half g_attn_hi[MROWS * E_DIM];
__device__ __half g_attn_lo[MROWS * E_DIM];
__device__ float g_cos[SEQ * (HD / 2)];
__device__ float g_sin[SEQ * (HD / 2)];

// ---------------- helpers ----------------------------------------------------
__device__ __forceinline__ uint32_t smem_u32(const void* p) {
    uint32_t a;
    asm("{ .reg .u64 t; cvta.to.shared.u64 t, %1; cvt.u32.u64 %0, t; }"
        : "=r"(a) : "l"(p));
    return a;
}
__device__ __forceinline__ void cp_async16(uint32_t dst, const void* src) {
    asm volatile("cp.async.cg.shared.global [%0], [%1], 16;"
                 :: "r"(dst), "l"(src));
}
#define CP_COMMIT() asm volatile("cp.async.commit_group;" ::: "memory")
#define CP_WAIT1() asm volatile("cp.async.wait_group 1;" ::: "memory")

__device__ __forceinline__ void ldsm_x4(uint32_t addr, uint32_t* r) {
    asm volatile("ldmatrix.sync.aligned.m8n8.x4.shared.b16 {%0,%1,%2,%3}, [%4];"
                 : "=r"(r[0]), "=r"(r[1]), "=r"(r[2]), "=r"(r[3]) : "r"(addr));
}

__device__ __forceinline__ void mma_f16(float* d, const uint32_t* a,
                                        const uint32_t* b) {
    asm volatile(
        "mma.sync.aligned.m16n8k16.row.col.f32.f16.f16.f32 "
        "{%0,%1,%2,%3}, {%4,%5,%6,%7}, {%8,%9}, {%0,%1,%2,%3};"
        : "+f"(d[0]), "+f"(d[1]), "+f"(d[2]), "+f"(d[3])
        : "r"(a[0]), "r"(a[1]), "r"(a[2]), "r"(a[3]), "r"(b[0]), "r"(b[1]));
}

__device__ __forceinline__ void split_pack_h(float x, float y, uint32_t& hi,
                                             uint32_t& lo) {
    __half hx = __float2half_rn(x), hy = __float2half_rn(y);
    __half2 h2(hx, hy);
    hi = *(uint32_t*)&h2;
    __half2 l2(__float2half_rn(x - __half2float(hx)),
               __float2half_rn(y - __half2float(hy)));
    lo = *(uint32_t*)&l2;
}

__device__ __forceinline__ void split_store2h(__half* hi, __half* lo,
                                              size_t idx, float x, float y) {
    uint32_t h, l;
    split_pack_h(x, y, h, l);
    *(uint32_t*)(hi + idx) = h;
    *(uint32_t*)(lo + idx) = l;
}

__device__ __forceinline__ void store2h(__half* dst, size_t idx, float x,
                                        float y) {
    __half2 h(__float2half_rn(x), __float2half_rn(y));
    *(__half2*)(dst + idx) = h;
}

// ---------------- RoPE table ------------------------------------------------
__global__ void rope_init_kernel() {
    int idx = blockIdx.x * blockDim.x + threadIdx.x;
    if (idx >= SEQ * (HD / 2)) return;
    int pos = idx / (HD / 2);
    int i = idx % (HD / 2);
    double invd = pow(10000.0, -(double)(2 * i) / (double)HD);
    float inv = (float)invd;
    float ang = (float)pos * inv;
    g_cos[idx] = (float)cos((double)ang);
    g_sin[idx] = (float)sin((double)ang);
}

// ---------------- conversions ------------------------------------------------
__global__ void convert_x_kernel(const float4* __restrict__ src) {
    int i = blockIdx.x * blockDim.x + threadIdx.x;
    if (i >= MROWS * E_DIM / 4) return;
    float4 v = src[i];
    uint32_t h0, l0, h1, l1;
    split_pack_h(v.x, v.y, h0, l0);
    split_pack_h(v.z, v.w, h1, l1);
    ((uint32_t*)g_x_hi)[i * 2 + 0] = h0;
    ((uint32_t*)g_x_hi)[i * 2 + 1] = h1;
    ((uint32_t*)g_x_lo)[i * 2 + 0] = l0;
    ((uint32_t*)g_x_lo)[i * 2 + 1] = l1;
}

__global__ void convert_w_kernel(const float4* __restrict__ w0,
                                 const float4* __restrict__ w1,
                                 const float4* __restrict__ w2,
                                 const float4* __restrict__ w3) {
    int i = blockIdx.x * blockDim.x + threadIdx.x;
    if (i >= E_DIM * E_DIM / 4) return;
    int z = blockIdx.y;
    const float4* src = (z == 0) ? w0 : (z == 1) ? w1 : (z == 2) ? w2 : w3;
    float4 v = src[i];
    __half2 a(__float2half_rn(v.x), __float2half_rn(v.y));
    __half2 b(__float2half_rn(v.z), __float2half_rn(v.w));
    __half2* dst = (__half2*)(g_w + (size_t)z * E_DIM * E_DIM);
    dst[i * 2 + 0] = a;
    dst[i * 2 + 1] = b;
}

// ---------------- HMMA GEMM: 128x128, BK=32, fp16 2-term, 3-stage -----------
#define GBM 128
#define GBN 128
#define GBK 32
#define NCHUNK (E_DIM / GBK) /* 64 */
#define BSTR 80                      /* bytes per 32-fp16 row (64B data + pad) */
#define TILE_BYTES (128 * BSTR)      /* 10240 */
#define STAGE_BYTES (3 * TILE_BYTES) /* 30720: A_hi, A_lo, B */
#define NSTAGE 3
#define GEMM_SMEM (NSTAGE * STAGE_BYTES) /* 92160 */

// mode: 0=Q (rope+scale, split out), 1=K (rope), 2=V, 3=fp32 out
__device__ __forceinline__ void gemm_mma_body(
    const __half* __restrict__ Ahi, const __half* __restrict__ Alo,
    const __half* __restrict__ B, float* __restrict__ Cout, int mode) {
    extern __shared__ char smem[];
    uint32_t sbase = smem_u32(smem);
    int tid = threadIdx.x;
    int wid = tid >> 5;
    int lane = tid & 31;
    int m0 = blockIdx.y * GBM;
    int n0 = blockIdx.x * GBN;
    int warp_m = (wid & 3) * 32;
    int warp_n = (wid >> 2) * 64;

    int gidx = lane >> 2;

    int a_row = (lane & 7) + ((lane >> 3) & 1) * 8;
    int a_col = (lane >> 4) * 16;
    uint32_t a_off[2];
#pragma unroll
    for (int mi = 0; mi < 2; mi++)
        a_off[mi] = (uint32_t)((warp_m + mi * 16 + a_row) * BSTR + a_col);
    int b_row = (lane & 7) + ((lane >> 4) & 1) * 8;
    int b_col = ((lane >> 3) & 1) * 16;
    uint32_t b_off[4];
#pragma unroll
    for (int njp = 0; njp < 4; njp++)
        b_off[njp] = (uint32_t)((warp_n + njp * 16 + b_row) * BSTR + b_col);

    // staging: per tile 512 x 16B; 256 threads -> 2 xfers/thread/tile
    int r0i = tid >> 2;            // rows 0..63   (idx = tid)
    int c0i = tid & 3;
    int r1i = (tid + 256) >> 2;    // rows 64..127 (idx = tid+256)
    int c1i = tid & 3;
    uint32_t s0 = (uint32_t)(r0i * BSTR + c0i * 16);
    uint32_t s1 = (uint32_t)(r1i * BSTR + c1i * 16);
    const __half* pa_hi0 = Ahi + (size_t)(m0 + r0i) * E_DIM + c0i * 8;
    const __half* pa_hi1 = Ahi + (size_t)(m0 + r1i) * E_DIM + c1i * 8;
    const __half* pa_lo0 = Alo + (size_t)(m0 + r0i) * E_DIM + c0i * 8;
    const __half* pa_lo1 = Alo + (size_t)(m0 + r1i) * E_DIM + c1i * 8;
    const __half* pb0 = B + (size_t)(n0 + r0i) * E_DIM + c0i * 8;
    const __half* pb1 = B + (size_t)(n0 + r1i) * E_DIM + c1i * 8;

    float acc[2][8][4];
#pragma unroll
    for (int mi = 0; mi < 2; mi++)
#pragma unroll
        for (int nj = 0; nj < 8; nj++)
#pragma unroll
            for (int q = 0; q < 4; q++) acc[mi][nj][q] = 0.f;

#pragma unroll
    for (int s = 0; s < NSTAGE - 1; s++) {
        uint32_t st = sbase + s * STAGE_BYTES;
        int k0 = s * GBK;
        cp_async16(st + 0 * TILE_BYTES + s0, pa_hi0 + k0);
        cp_async16(st + 0 * TILE_BYTES + s1, pa_hi1 + k0);
        cp_async16(st + 1 * TILE_BYTES + s0, pa_lo0 + k0);
        cp_async16(st + 1 * TILE_BYTES + s1, pa_lo1 + k0);
        cp_async16(st + 2 * TILE_BYTES + s0, pb0 + k0);
        cp_async16(st + 2 * TILE_BYTES + s1, pb1 + k0);
        CP_COMMIT();
    }

    int slot = 0, wslot = NSTAGE - 1;
    for (int c = 0; c < NCHUNK; c++) {
        CP_WAIT1();
        __syncthreads();

        uint32_t st = sbase + (uint32_t)slot * STAGE_BYTES;

#pragma unroll
        for (int kc = 0; kc < 2; kc++) {
            uint32_t ko = (uint32_t)(kc * 32);
            uint32_t ahi[2][4], alo[2][4];
#pragma unroll
            for (int mi = 0; mi < 2; mi++) {
                ldsm_x4(st + a_off[mi] + ko, ahi[mi]);
                ldsm_x4(st + TILE_BYTES + a_off[mi] + ko, alo[mi]);
            }
#pragma unroll
            for (int njp = 0; njp < 4; njp++) {
                uint32_t b4[4];
                ldsm_x4(st + 2 * TILE_BYTES + b_off[njp] + ko, b4);
                int nj0 = njp * 2, nj1 = njp * 2 + 1;
                mma_f16(acc[0][nj0], ahi[0], b4 + 0);
                mma_f16(acc[1][nj0], ahi[1], b4 + 0);
                mma_f16(acc[0][nj1], ahi[0], b4 + 2);
                mma_f16(acc[1][nj1], ahi[1], b4 + 2);
                mma_f16(acc[0][nj0], alo[0], b4 + 0);
                mma_f16(acc[1][nj0], alo[1], b4 + 0);
                mma_f16(acc[0][nj1], alo[0], b4 + 2);
                mma_f16(acc[1][nj1], alo[1], b4 + 2);
            }
        }

        if (c + NSTAGE - 1 < NCHUNK) {
            uint32_t sw = sbase + (uint32_t)wslot * STAGE_BYTES;
            int k0 = (c + NSTAGE - 1) * GBK;
            cp_async16(sw + 0 * TILE_BYTES + s0, pa_hi0 + k0);
            cp_async16(sw + 0 * TILE_BYTES + s1, pa_hi1 + k0);
            cp_async16(sw + 1 * TILE_BYTES + s0, pa_lo0 + k0);
            cp_async16(sw + 1 * TILE_BYTES + s1, pa_lo1 + k0);
            cp_async16(sw + 2 * TILE_BYTES + s0, pb0 + k0);
            cp_async16(sw + 2 * TILE_BYTES + s1, pb1 + k0);
        }
        CP_COMMIT();
        slot = (slot + 1 == NSTAGE) ? 0 : slot + 1;
        wslot = (wslot + 1 == NSTAGE) ? 0 : wslot + 1;
    }

    int tig = lane & 3;
    const float qsc = (mode == 0) ? 0.08838834764831845f : 1.0f;

#pragma unroll
    for (int mi = 0; mi < 2; mi++) {
#pragma unroll
        for (int nj = 0; nj < 8; nj++) {
            int m = m0 + warp_m + mi * 16 + gidx;
            int n = n0 + warp_n + nj * 8 + tig * 2;
            float v0 = acc[mi][nj][0], v1 = acc[mi][nj][1];
            float v2 = acc[mi][nj][2], v3 = acc[mi][nj][3];
            if (mode <= 1) {
                int pi = (n & (HD - 1)) >> 1;
                int p0 = m & (SEQ - 1);
                int p8 = p0 + 8;
                float c0 = g_cos[p0 * (HD / 2) + pi], sn0 = g_sin[p0 * (HD / 2) + pi];
                float c8 = g_cos[p8 * (HD / 2) + pi], sn8 = g_sin[p8 * (HD / 2) + pi];
                float t0 = v0 * c0 - v1 * sn0, t1 = v0 * sn0 + v1 * c0;
                float t2 = v2 * c8 - v3 * sn8, t3 = v2 * sn8 + v3 * c8;
                v0 = t0 * qsc; v1 = t1 * qsc; v2 = t2 * qsc; v3 = t3 * qsc;
            }
            if (mode == 3) {
                *(float2*)&Cout[(size_t)m * E_DIM + n] = make_float2(v0, v1);
                *(float2*)&Cout[(size_t)(m + 8) * E_DIM + n] = make_float2(v2, v3);
            } else {
                int b = m >> 11, s = m & 2047, h = n >> 7, d = n & 127;
                size_t base0 = ((size_t)(b * NHEAD + h) * SEQ + s) * HD + d;
                size_t base1 = base0 + 8 * HD;
                if (mode == 0) {
                    split_store2h(g_qhi, g_qlo, base0, v0, v1);
                    split_store2h(g_qhi, g_qlo, base1, v2, v3);
                } else if (mode == 1) {
                    store2h(g_k, base0, v0, v1);
                    store2h(g_k, base1, v2, v3);
                } else {
                    store2h(g_v, base0, v0, v1);
                    store2h(g_v, base1, v2, v3);
                }
            }
        }
    }
}

__global__ __launch_bounds__(256, 2) void gemm_qkv_tc(void) {
    int z = blockIdx.z;
    const __half* b = g_w + (size_t)z * E_DIM * E_DIM;
    gemm_mma_body(g_x_hi, g_x_lo, b, nullptr, z);
}

__global__ __launch_bounds__(256, 2) void gemm_out_tc(float* __restrict__ out) {
    const __half* b = g_w + (size_t)3 * E_DIM * E_DIM;
    gemm_mma_body(g_attn_hi, g_attn_lo, b, out, 3);
}

// ---------------- V transpose: [bh][s][d] -> [bh][d][s] ---------------------
__global__ void transpose_v_kernel() {
    __shared__ __half t[32][33];
    int bh = blockIdx.z;
    int tx = threadIdx.x, ty = threadIdx.y;
    int s0 = blockIdx.x * 32, d0 = blockIdx.y * 32;
#pragma unroll
    for (int i = 0; i < 32; i += 8)
        t[ty + i][tx] = g_v[((size_t)bh * SEQ + s0 + ty + i) * HD + d0 + tx];
    __syncthreads();
#pragma unroll
    for (int i = 0; i < 32; i += 8)
        g_vt[((size_t)bh * HD + d0 + ty + i) * SEQ + s0 + tx] = t[tx][ty + i];
}

// ---------------- Tensor-core flash attention (causal, cp.async DB) ---------
// 4 warps, q-tile 64, k-tile 64, 2-stage double buffer. fp16 2-term.
#define FKT 64
#define KSTR2 272 /* K row stride bytes (128 fp16 + pad) */
#define VSTR3 144 /* Vt row stride bytes (64 fp16 + pad) */
#define F_K 0
#define F_V (64 * KSTR2)            /* 17408 */
#define F_STAGE (F_V + 128 * VSTR3) /* 35840 */
#define FLASH_SMEM (2 * F_STAGE)    /* 71680 */

__device__ __forceinline__ void flash_stage_load(uint32_t sst,
                                                 const __half* K,
                                                 const __half* Vt, int kt,
                                                 int tid) {
    int k0 = kt * FKT;
#pragma unroll
    for (int i = 0; i < 8; i++) {
        int idx = tid + i * 128;
        int row = idx >> 4, cc = idx & 15;
        cp_async16(sst + F_K + (uint32_t)(row * KSTR2 + cc * 16),
                   K + (size_t)(k0 + row) * HD + cc * 8);
    }
#pragma unroll
    for (int i = 0; i < 8; i++) {
        int idx = tid + i * 128;
        int row = idx >> 3, cc = idx & 7;
        cp_async16(sst + F_V + (uint32_t)(row * VSTR3 + cc * 16),
                   Vt + (size_t)row * SEQ + k0 + cc * 8);
    }
}

__global__ __launch_bounds__(128) void flash_mma_kernel() {
    extern __shared__ char sm[];
    uint32_t sm32 = smem_u32(sm);

    int tid = threadIdx.x;
    int wid = tid >> 5;
    int lane = tid & 31;
    int qt = (int)gridDim.x - 1 - (int)blockIdx.x;  // heavy tiles first
    int bh = blockIdx.y;
    int g = lane >> 2;
    int c = lane & 3;
    int warp_m = wid * 16;
    int nkt = qt + 1;

    int b_row = (lane & 7) + ((lane >> 4) & 1) * 8;
    int b_col = ((lane >> 3) & 1) * 16;
    uint32_t k_off[4], v_off[8];
#pragma unroll
    for (int njp = 0; njp < 4; njp++)
        k_off[njp] = (uint32_t)((njp * 16 + b_row) * KSTR2 + b_col);
#pragma unroll
    for (int njp = 0; njp < 8; njp++)
        v_off[njp] = (uint32_t)((njp * 16 + b_row) * VSTR3 + b_col);

    const __half* K = g_k + (size_t)bh * SEQ * HD;
    const __half* Vt = g_vt + (size_t)bh * HD * SEQ;

    flash_stage_load(sm32, K, Vt, 0, tid);
    CP_COMMIT();

    uint32_t qh[8][4], ql[8][4];
    {
        const __half* Qh = g_qhi + (size_t)bh * SEQ * HD + (size_t)qt * 64 * HD;
        const __half* Ql = g_qlo + (size_t)bh * SEQ * HD + (size_t)qt * 64 * HD;
        int r0 = (warp_m + g) * HD, r1 = (warp_m + g + 8) * HD;
#pragma unroll
        for (int kc = 0; kc < 8; kc++) {
            int c0 = kc * 16 + c * 2, c1 = c0 + 8;
            qh[kc][0] = *(const uint32_t*)(Qh + r0 + c0);
            qh[kc][1] = *(const uint32_t*)(Qh + r1 + c0);
            qh[kc][2] = *(const uint32_t*)(Qh + r0 + c1);
            qh[kc][3] = *(const uint32_t*)(Qh + r1 + c1);
            ql[kc][0] = *(const uint32_t*)(Ql + r0 + c0);
            ql[kc][1] = *(const uint32_t*)(Ql + r1 + c0);
            ql[kc][2] = *(const uint32_t*)(Ql + r0 + c1);
            ql[kc][3] = *(const uint32_t*)(Ql + r1 + c1);
        }
    }

    float o[16][4];
#pragma unroll
    for (int t = 0; t < 16; t++)
#pragma unroll
        for (int q = 0; q < 4; q++) o[t][q] = 0.f;
    float m0 = -1e30f, m1 = -1e30f, l0 = 0.f, l1 = 0.f;

    for (int kt = 0; kt < nkt; kt++) {
        if (kt + 1 < nkt)
            flash_stage_load(sm32 + ((kt + 1) & 1) * F_STAGE, K, Vt, kt + 1, tid);
        CP_COMMIT();
        CP_WAIT1();
        __syncthreads();

        uint32_t st = sm32 + (uint32_t)(kt & 1) * F_STAGE;

        // ---- S = Q @ K^T (16q x 64k per warp) ----
        float s_acc[8][4];
#pragma unroll
        for (int nj = 0; nj < 8; nj++)
#pragma unroll
            for (int q = 0; q < 4; q++) s_acc[nj][q] = 0.f;

#pragma unroll
        for (int kc = 0; kc < 8; kc++) {
#pragma unroll
            for (int njp = 0; njp < 4; njp++) {
                uint32_t b4[4];
                ldsm_x4(st + F_K + k_off[njp] + kc * 32, b4);
                int nj0 = njp * 2, nj1 = njp * 2 + 1;
                mma_f16(s_acc[nj0], qh[kc], b4 + 0);
                mma_f16(s_acc[nj1], qh[kc], b4 + 2);
                mma_f16(s_acc[nj0], ql[kc], b4 + 0);
                mma_f16(s_acc[nj1], ql[kc], b4 + 2);
            }
        }

        // ---- causal mask (diagonal tile only) ----
        if (kt == qt) {
            int row0 = qt * 64 + warp_m + g, row1 = row0 + 8;
            int colb = kt * FKT;
#pragma unroll
            for (int nj = 0; nj < 8; nj++) {
                int col = colb + nj * 8 + c * 2;
                if (col > row0) s_acc[nj][0] = -1e30f;
                if (col + 1 > row0) s_acc[nj][1] = -1e30f;
                if (col > row1) s_acc[nj][2] = -1e30f;
                if (col + 1 > row1) s_acc[nj][3] = -1e30f;
            }
        }

        // ---- online softmax ----
        float mt0 = -1e30f, mt1 = -1e30f;
#pragma unroll
        for (int nj = 0; nj < 8; nj++) {
            mt0 = fmaxf(mt0, fmaxf(s_acc[nj][0], s_acc[nj][1]));
            mt1 = fmaxf(mt1, fmaxf(s_acc[nj][2], s_acc[nj][3]));
        }
        mt0 = fmaxf(mt0, __shfl_xor_sync(0xffffffffu, mt0, 1));
        mt0 = fmaxf(mt0, __shfl_xor_sync(0xffffffffu, mt0, 2));
        mt1 = fmaxf(mt1, __shfl_xor_sync(0xffffffffu, mt1, 1));
        mt1 = fmaxf(mt1, __shfl_xor_sync(0xffffffffu, mt1, 2));
        float mn0 = fmaxf(m0, mt0), mn1 = fmaxf(m1, mt1);
        float a0 = __expf(m0 - mn0), a1 = __expf(m1 - mn1);
        m0 = mn0; m1 = mn1;
#pragma unroll
        for (int t = 0; t < 16; t++) {
            o[t][0] *= a0; o[t][1] *= a0;
            o[t][2] *= a1; o[t][3] *= a1;
        }
        float rs0 = 0.f, rs1 = 0.f;
#pragma unroll
        for (int nj = 0; nj < 8; nj++) {
            float p0 = __expf(s_acc[nj][0] - mn0);
            float p1 = __expf(s_acc[nj][1] - mn0);
            float p2 = __expf(s_acc[nj][2] - mn1);
            float p3 = __expf(s_acc[nj][3] - mn1);
            s_acc[nj][0] = p0; s_acc[nj][1] = p1;
            s_acc[nj][2] = p2; s_acc[nj][3] = p3;
            rs0 += p0 + p1; rs1 += p2 + p3;
        }
        l0 = l0 * a0 + rs0;
        l1 = l1 * a1 + rs1;

        // ---- P fragments (A-layout, fp16 split) ----
        uint32_t ph[4][4], pl[4][4];
#pragma unroll
        for (int kc = 0; kc < 4; kc++) {
            split_pack_h(s_acc[2 * kc][0], s_acc[2 * kc][1], ph[kc][0], pl[kc][0]);
            split_pack_h(s_acc[2 * kc][2], s_acc[2 * kc][3], ph[kc][1], pl[kc][1]);
            split_pack_h(s_acc[2 * kc + 1][0], s_acc[2 * kc + 1][1], ph[kc][2], pl[kc][2]);
            split_pack_h(s_acc[2 * kc + 1][2], s_acc[2 * kc + 1][3], ph[kc][3], pl[kc][3]);
        }

        // ---- O += P @ V ----
#pragma unroll
        for (int njp = 0; njp < 8; njp++) {
#pragma unroll
            for (int kc = 0; kc < 4; kc++) {
                uint32_t v4[4];
                ldsm_x4(st + F_V + v_off[njp] + kc * 32, v4);
                int nj0 = njp * 2, nj1 = njp * 2 + 1;
                mma_f16(o[nj0], ph[kc], v4 + 0);
                mma_f16(o[nj1], ph[kc], v4 + 2);
                mma_f16(o[nj0], pl[kc], v4 + 0);
                mma_f16(o[nj1], pl[kc], v4 + 2);
            }
        }
        __syncthreads();  // reads of this stage done before it is rewritten
    }

    l0 += __shfl_xor_sync(0xffffffffu, l0, 1);
    l0 += __shfl_xor_sync(0xffffffffu, l0, 2);
    l1 += __shfl_xor_sync(0xffffffffu, l1, 1);
    l1 += __shfl_xor_sync(0xffffffffu, l1, 2);
    float i0 = 1.0f / l0, i1 = 1.0f / l1;
    int b = bh >> 4, h = bh & 15;
    int s0 = qt * 64 + warp_m + g;
    size_t r0 = ((size_t)b * SEQ + s0) * E_DIM + h * HD;
    size_t r1 = ((size_t)b * SEQ + s0 + 8) * E_DIM + h * HD;
#pragma unroll
    for (int nj = 0; nj < 16; nj++) {
        int d = nj * 8 + c * 2;
        split_store2h(g_attn_hi, g_attn_lo, r0 + d, o[nj][0] * i0, o[nj][1] * i0);
        split_store2h(g_attn_hi, g_attn_lo, r1 + d, o[nj][2] * i1, o[nj][3] * i1);
    }
}

// ---------------- launcher ---------------------------------------------------
extern "C" void kernel_launch(void* const* d_in, const int* in_sizes, int n_in,
                              void* d_out, int out_size) {
    const float* x = (const float*)d_in[0];
    const float* Wq = (const float*)d_in[1];
    const float* Wk = (const float*)d_in[2];
    const float* Wv = (const float*)d_in[3];
    const float* Wo = (const float*)d_in[4];
    float* out = (float*)d_out;

    cudaFuncSetAttribute(gemm_qkv_tc, cudaFuncAttributeMaxDynamicSharedMemorySize,
                         GEMM_SMEM);
    cudaFuncSetAttribute(gemm_out_tc, cudaFuncAttributeMaxDynamicSharedMemorySize,
                         GEMM_SMEM);
    cudaFuncSetAttribute(flash_mma_kernel,
                         cudaFuncAttributeMaxDynamicSharedMemorySize, FLASH_SMEM);

    rope_init_kernel<<<(SEQ * (HD / 2) + 255) / 256, 256>>>();

    {
        int n4 = MROWS * E_DIM / 4;
        convert_x_kernel<<<(n4 + 255) / 256, 256>>>((const float4*)x);
        int w4 = E_DIM * E_DIM / 4;
        dim3 gw((w4 + 255) / 256, 4);
        convert_w_kernel<<<gw, 256>>>((const float4*)Wq, (const float4*)Wk,
                                      (const float4*)Wv, (const float4*)Wo);
    }

    dim3 gqkv(E_DIM / GBN, MROWS / GBM, 3);
    gemm_qkv_tc<<<gqkv, 256, GEMM_SMEM>>>();

    dim3 gtr(SEQ / 32, HD / 32, NBATCH * NHEAD);
    transpose_v_kernel<<<gtr, dim3(32, 8)>>>();

    dim3 gfa(SEQ / 64, NBATCH * NHEAD);
    flash_mma_kernel<<<gfa, 128, FLASH_SMEM>>>();

    dim3 gout(E_DIM / GBN, MROWS / GBM);
    gemm_out_tc<<<gout, 256, GEMM_SMEM>>>(out);
}

// round 14
// speedup vs baseline: 2.0946x; 1.1848x over previous
#include <cuda_runtime.h>
#include <cuda_fp16.h>
#include <math.h>
#include <stdint.h>

#define E_DIM 2048
#define SEQ 2048
#define NBATCH 2
#define NHEAD 16
#define HD 128
#define MROWS (NBATCH * SEQ) /* 4096 */

// ---------------- scratch (device globals; no allocation allowed) ----------
__device__ __half g_x_hi[MROWS * E_DIM];
__device__ __half g_x_lo[MROWS * E_DIM];
__device__ __half g_w[4 * E_DIM * E_DIM];
__device__ __half g_qhi[MROWS * E_DIM];
__device__ __half g_qlo[MROWS * E_DIM];
__device__ __half g_k[MROWS * E_DIM];
__device__ __half g_v[MROWS * E_DIM];
__device__ __half g_vt[MROWS * E_DIM];
__device__ __half g_attn_hi[MROWS * E_DIM];
__device__ __half g_attn_lo[MROWS * E_DIM];
__device__ float g_cos[SEQ * (HD / 2)];
__device__ float g_sin[SEQ * (HD / 2)];

// ---------------- helpers ----------------------------------------------------
__device__ __forceinline__ uint32_t smem_u32(const void* p) {
    uint32_t a;
    asm("{ .reg .u64 t; cvta.to.shared.u64 t, %1; cvt.u32.u64 %0, t; }"
        : "=r"(a) : "l"(p));
    return a;
}
__device__ __forceinline__ void cp_async16(uint32_t dst, const void* src) {
    asm volatile("cp.async.cg.shared.global [%0], [%1], 16;"
                 :: "r"(dst), "l"(src));
}
#define CP_COMMIT() asm volatile("cp.async.commit_group;" ::: "memory")
#define CP_WAIT1() asm volatile("cp.async.wait_group 1;" ::: "memory")

__device__ __forceinline__ void ldsm_x4(uint32_t addr, uint32_t* r) {
    asm volatile("ldmatrix.sync.aligned.m8n8.x4.shared.b16 {%0,%1,%2,%3}, [%4];"
                 : "=r"(r[0]), "=r"(r[1]), "=r"(r[2]), "=r"(r[3]) : "r"(addr));
}

__device__ __forceinline__ void mma_f16(float* d, const uint32_t* a,
                                        const uint32_t* b) {
    asm volatile(
        "mma.sync.aligned.m16n8k16.row.col.f32.f16.f16.f32 "
        "{%0,%1,%2,%3}, {%4,%5,%6,%7}, {%8,%9}, {%0,%1,%2,%3};"
        : "+f"(d[0]), "+f"(d[1]), "+f"(d[2]), "+f"(d[3])
        : "r"(a[0]), "r"(a[1]), "r"(a[2]), "r"(a[3]), "r"(b[0]), "r"(b[1]));
}

__device__ __forceinline__ void split_pack_h(float x, float y, uint32_t& hi,
                                             uint32_t& lo) {
    __half hx = __float2half_rn(x), hy = __float2half_rn(y);
    __half2 h2(hx, hy);
    hi = *(uint32_t*)&h2;
    __half2 l2(__float2half_rn(x - __half2float(hx)),
               __float2half_rn(y - __half2float(hy)));
    lo = *(uint32_t*)&l2;
}

__device__ __forceinline__ uint32_t pack2h(float x, float y) {
    __half2 h(__float2half_rn(x), __float2half_rn(y));
    return *(uint32_t*)&h;
}

__device__ __forceinline__ void split_store2h(__half* hi, __half* lo,
                                              size_t idx, float x, float y) {
    uint32_t h, l;
    split_pack_h(x, y, h, l);
    *(uint32_t*)(hi + idx) = h;
    *(uint32_t*)(lo + idx) = l;
}

__device__ __forceinline__ void store2h(__half* dst, size_t idx, float x,
                                        float y) {
    *(uint32_t*)(dst + idx) = pack2h(x, y);
}

// ---------------- RoPE table ------------------------------------------------
__global__ void rope_init_kernel() {
    int idx = blockIdx.x * blockDim.x + threadIdx.x;
    if (idx >= SEQ * (HD / 2)) return;
    int pos = idx / (HD / 2);
    int i = idx % (HD / 2);
    double invd = pow(10000.0, -(double)(2 * i) / (double)HD);
    float inv = (float)invd;
    float ang = (float)pos * inv;
    g_cos[idx] = (float)cos((double)ang);
    g_sin[idx] = (float)sin((double)ang);
}

// ---------------- conversions ------------------------------------------------
__global__ void convert_x_kernel(const float4* __restrict__ src) {
    int i = blockIdx.x * blockDim.x + threadIdx.x;
    if (i >= MROWS * E_DIM / 4) return;
    float4 v = src[i];
    uint32_t h0, l0, h1, l1;
    split_pack_h(v.x, v.y, h0, l0);
    split_pack_h(v.z, v.w, h1, l1);
    ((uint32_t*)g_x_hi)[i * 2 + 0] = h0;
    ((uint32_t*)g_x_hi)[i * 2 + 1] = h1;
    ((uint32_t*)g_x_lo)[i * 2 + 0] = l0;
    ((uint32_t*)g_x_lo)[i * 2 + 1] = l1;
}

__global__ void convert_w_kernel(const float4* __restrict__ w0,
                                 const float4* __restrict__ w1,
                                 const float4* __restrict__ w2,
                                 const float4* __restrict__ w3) {
    int i = blockIdx.x * blockDim.x + threadIdx.x;
    if (i >= E_DIM * E_DIM / 4) return;
    int z = blockIdx.y;
    const float4* src = (z == 0) ? w0 : (z == 1) ? w1 : (z == 2) ? w2 : w3;
    float4 v = src[i];
    __half2 a(__float2half_rn(v.x), __float2half_rn(v.y));
    __half2 b(__float2half_rn(v.z), __float2half_rn(v.w));
    __half2* dst = (__half2*)(g_w + (size_t)z * E_DIM * E_DIM);
    dst[i * 2 + 0] = a;
    dst[i * 2 + 1] = b;
}

// ---------------- HMMA GEMM: 128x128, BK=32, 3-stage -------------------------
// ASPLIT=1: A = A_hi + A_lo (2-term); ASPLIT=0: A = A_hi only (1-term).
#define GBM 128
#define GBN 128
#define GBK 32
#define NCHUNK (E_DIM / GBK) /* 64 */
#define BSTR 80
#define TILE_BYTES (128 * BSTR)      /* 10240 */
#define STAGE_BYTES (3 * TILE_BYTES) /* 30720: A_hi, A_lo, B */
#define NSTAGE 3
#define GEMM_SMEM (NSTAGE * STAGE_BYTES) /* 92160 */

// mode: 0=Q (rope+scale, split out), 1=K (rope), 2=V, 3=fp32 out
template <int ASPLIT>
__device__ __forceinline__ void gemm_mma_body(
    const __half* __restrict__ Ahi, const __half* __restrict__ Alo,
    const __half* __restrict__ B, float* __restrict__ Cout, int mode) {
    extern __shared__ char smem[];
    uint32_t sbase = smem_u32(smem);
    int tid = threadIdx.x;
    int wid = tid >> 5;
    int lane = tid & 31;
    int m0 = blockIdx.y * GBM;
    int n0 = blockIdx.x * GBN;
    int warp_m = (wid & 3) * 32;
    int warp_n = (wid >> 2) * 64;

    int gidx = lane >> 2;

    int a_row = (lane & 7) + ((lane >> 3) & 1) * 8;
    int a_col = (lane >> 4) * 16;
    uint32_t a_off[2];
#pragma unroll
    for (int mi = 0; mi < 2; mi++)
        a_off[mi] = (uint32_t)((warp_m + mi * 16 + a_row) * BSTR + a_col);
    int b_row = (lane & 7) + ((lane >> 4) & 1) * 8;
    int b_col = ((lane >> 3) & 1) * 16;
    uint32_t b_off[4];
#pragma unroll
    for (int njp = 0; njp < 4; njp++)
        b_off[njp] = (uint32_t)((warp_n + njp * 16 + b_row) * BSTR + b_col);

    int r0i = tid >> 2;
    int c0i = tid & 3;
    int r1i = (tid + 256) >> 2;
    int c1i = tid & 3;
    uint32_t s0 = (uint32_t)(r0i * BSTR + c0i * 16);
    uint32_t s1 = (uint32_t)(r1i * BSTR + c1i * 16);
    const __half* pa_hi0 = Ahi + (size_t)(m0 + r0i) * E_DIM + c0i * 8;
    const __half* pa_hi1 = Ahi + (size_t)(m0 + r1i) * E_DIM + c1i * 8;
    const __half* pa_lo0 = Alo + (size_t)(m0 + r0i) * E_DIM + c0i * 8;
    const __half* pa_lo1 = Alo + (size_t)(m0 + r1i) * E_DIM + c1i * 8;
    const __half* pb0 = B + (size_t)(n0 + r0i) * E_DIM + c0i * 8;
    const __half* pb1 = B + (size_t)(n0 + r1i) * E_DIM + c1i * 8;

    float acc[2][8][4];
#pragma unroll
    for (int mi = 0; mi < 2; mi++)
#pragma unroll
        for (int nj = 0; nj < 8; nj++)
#pragma unroll
            for (int q = 0; q < 4; q++) acc[mi][nj][q] = 0.f;

#pragma unroll
    for (int s = 0; s < NSTAGE - 1; s++) {
        uint32_t st = sbase + s * STAGE_BYTES;
        int k0 = s * GBK;
        cp_async16(st + 0 * TILE_BYTES + s0, pa_hi0 + k0);
        cp_async16(st + 0 * TILE_BYTES + s1, pa_hi1 + k0);
        if (ASPLIT) {
            cp_async16(st + 1 * TILE_BYTES + s0, pa_lo0 + k0);
            cp_async16(st + 1 * TILE_BYTES + s1, pa_lo1 + k0);
        }
        cp_async16(st + 2 * TILE_BYTES + s0, pb0 + k0);
        cp_async16(st + 2 * TILE_BYTES + s1, pb1 + k0);
        CP_COMMIT();
    }

    int slot = 0, wslot = NSTAGE - 1;
    for (int c = 0; c < NCHUNK; c++) {
        CP_WAIT1();
        __syncthreads();

        uint32_t st = sbase + (uint32_t)slot * STAGE_BYTES;

#pragma unroll
        for (int kc = 0; kc < 2; kc++) {
            uint32_t ko = (uint32_t)(kc * 32);
            uint32_t ahi[2][4], alo[2][4];
#pragma unroll
            for (int mi = 0; mi < 2; mi++) {
                ldsm_x4(st + a_off[mi] + ko, ahi[mi]);
                if (ASPLIT) ldsm_x4(st + TILE_BYTES + a_off[mi] + ko, alo[mi]);
            }
#pragma unroll
            for (int njp = 0; njp < 4; njp++) {
                uint32_t b4[4];
                ldsm_x4(st + 2 * TILE_BYTES + b_off[njp] + ko, b4);
                int nj0 = njp * 2, nj1 = njp * 2 + 1;
                mma_f16(acc[0][nj0], ahi[0], b4 + 0);
                mma_f16(acc[1][nj0], ahi[1], b4 + 0);
                mma_f16(acc[0][nj1], ahi[0], b4 + 2);
                mma_f16(acc[1][nj1], ahi[1], b4 + 2);
                if (ASPLIT) {
                    mma_f16(acc[0][nj0], alo[0], b4 + 0);
                    mma_f16(acc[1][nj0], alo[1], b4 + 0);
                    mma_f16(acc[0][nj1], alo[0], b4 + 2);
                    mma_f16(acc[1][nj1], alo[1], b4 + 2);
                }
            }
        }

        if (c + NSTAGE - 1 < NCHUNK) {
            uint32_t sw = sbase + (uint32_t)wslot * STAGE_BYTES;
            int k0 = (c + NSTAGE - 1) * GBK;
            cp_async16(sw + 0 * TILE_BYTES + s0, pa_hi0 + k0);
            cp_async16(sw + 0 * TILE_BYTES + s1, pa_hi1 + k0);
            if (ASPLIT) {
                cp_async16(sw + 1 * TILE_BYTES + s0, pa_lo0 + k0);
                cp_async16(sw + 1 * TILE_BYTES + s1, pa_lo1 + k0);
            }
            cp_async16(sw + 2 * TILE_BYTES + s0, pb0 + k0);
            cp_async16(sw + 2 * TILE_BYTES + s1, pb1 + k0);
        }
        CP_COMMIT();
        slot = (slot + 1 == NSTAGE) ? 0 : slot + 1;
        wslot = (wslot + 1 == NSTAGE) ? 0 : wslot + 1;
    }

    int tig = lane & 3;
    const float qsc = (mode == 0) ? 0.08838834764831845f : 1.0f;

#pragma unroll
    for (int mi = 0; mi < 2; mi++) {
#pragma unroll
        for (int nj = 0; nj < 8; nj++) {
            int m = m0 + warp_m + mi * 16 + gidx;
            int n = n0 + warp_n + nj * 8 + tig * 2;
            float v0 = acc[mi][nj][0], v1 = acc[mi][nj][1];
            float v2 = acc[mi][nj][2], v3 = acc[mi][nj][3];
            if (mode <= 1) {
                int pi = (n & (HD - 1)) >> 1;
                int p0 = m & (SEQ - 1);
                int p8 = p0 + 8;
                float c0 = g_cos[p0 * (HD / 2) + pi], sn0 = g_sin[p0 * (HD / 2) + pi];
                float c8 = g_cos[p8 * (HD / 2) + pi], sn8 = g_sin[p8 * (HD / 2) + pi];
                float t0 = v0 * c0 - v1 * sn0, t1 = v0 * sn0 + v1 * c0;
                float t2 = v2 * c8 - v3 * sn8, t3 = v2 * sn8 + v3 * c8;
                v0 = t0 * qsc; v1 = t1 * qsc; v2 = t2 * qsc; v3 = t3 * qsc;
            }
            if (mode == 3) {
                *(float2*)&Cout[(size_t)m * E_DIM + n] = make_float2(v0, v1);
                *(float2*)&Cout[(size_t)(m + 8) * E_DIM + n] = make_float2(v2, v3);
            } else {
                int b = m >> 11, s = m & 2047, h = n >> 7, d = n & 127;
                size_t base0 = ((size_t)(b * NHEAD + h) * SEQ + s) * HD + d;
                size_t base1 = base0 + 8 * HD;
                if (mode == 0) {
                    split_store2h(g_qhi, g_qlo, base0, v0, v1);
                    split_store2h(g_qhi, g_qlo, base1, v2, v3);
                } else if (mode == 1) {
                    store2h(g_k, base0, v0, v1);
                    store2h(g_k, base1, v2, v3);
                } else {
                    store2h(g_v, base0, v0, v1);
                    store2h(g_v, base1, v2, v3);
                }
            }
        }
    }
}

__global__ __launch_bounds__(256, 2) void gemm_qkv_tc(void) {
    int z = blockIdx.z;
    const __half* b = g_w + (size_t)z * E_DIM * E_DIM;
    if (z == 0)
        gemm_mma_body<1>(g_x_hi, g_x_lo, b, nullptr, 0);  // Q: split X
    else
        gemm_mma_body<0>(g_x_hi, g_x_lo, b, nullptr, z);  // K,V: single X
}

__global__ __launch_bounds__(256, 2) void gemm_out_tc(float* __restrict__ out) {
    const __half* b = g_w + (size_t)3 * E_DIM * E_DIM;
    gemm_mma_body<1>(g_attn_hi, g_attn_lo, b, out, 3);
}

// ---------------- V transpose: [bh][s][d] -> [bh][d][s] ---------------------
__global__ void transpose_v_kernel() {
    __shared__ __half t[32][33];
    int bh = blockIdx.z;
    int tx = threadIdx.x, ty = threadIdx.y;
    int s0 = blockIdx.x * 32, d0 = blockIdx.y * 32;
#pragma unroll
    for (int i = 0; i < 32; i += 8)
        t[ty + i][tx] = g_v[((size_t)bh * SEQ + s0 + ty + i) * HD + d0 + tx];
    __syncthreads();
#pragma unroll
    for (int i = 0; i < 32; i += 8)
        g_vt[((size_t)bh * HD + d0 + ty + i) * SEQ + s0 + tx] = t[tx][ty + i];
}

// ---------------- Tensor-core flash attention (causal, cp.async DB) ---------
// 4 warps, q-tile 64, k-tile 64, 2-stage DB. Q split; P single.
#define FKT 64
#define KSTR2 272
#define VSTR3 144
#define F_K 0
#define F_V (64 * KSTR2)            /* 17408 */
#define F_STAGE (F_V + 128 * VSTR3) /* 35840 */
#define FLASH_SMEM (2 * F_STAGE)    /* 71680 */

__device__ __forceinline__ void flash_stage_load(uint32_t sst,
                                                 const __half* K,
                                                 const __half* Vt, int kt,
                                                 int tid) {
    int k0 = kt * FKT;
#pragma unroll
    for (int i = 0; i < 8; i++) {
        int idx = tid + i * 128;
        int row = idx >> 4, cc = idx & 15;
        cp_async16(sst + F_K + (uint32_t)(row * KSTR2 + cc * 16),
                   K + (size_t)(k0 + row) * HD + cc * 8);
    }
#pragma unroll
    for (int i = 0; i < 8; i++) {
        int idx = tid + i * 128;
        int row = idx >> 3, cc = idx & 7;
        cp_async16(sst + F_V + (uint32_t)(row * VSTR3 + cc * 16),
                   Vt + (size_t)row * SEQ + k0 + cc * 8);
    }
}

__global__ __launch_bounds__(128) void flash_mma_kernel() {
    extern __shared__ char sm[];
    uint32_t sm32 = smem_u32(sm);

    int tid = threadIdx.x;
    int wid = tid >> 5;
    int lane = tid & 31;
    int qt = (int)gridDim.x - 1 - (int)blockIdx.x;  // heavy tiles first
    int bh = blockIdx.y;
    int g = lane >> 2;
    int c = lane & 3;
    int warp_m = wid * 16;
    int nkt = qt + 1;

    int b_row = (lane & 7) + ((lane >> 4) & 1) * 8;
    int b_col = ((lane >> 3) & 1) * 16;
    uint32_t k_off[4], v_off[8];
#pragma unroll
    for (int njp = 0; njp < 4; njp++)
        k_off[njp] = (uint32_t)((njp * 16 + b_row) * KSTR2 + b_col);
#pragma unroll
    for (int njp = 0; njp < 8; njp++)
        v_off[njp] = (uint32_t)((njp * 16 + b_row) * VSTR3 + b_col);

    const __half* K = g_k + (size_t)bh * SEQ * HD;
    const __half* Vt = g_vt + (size_t)bh * HD * SEQ;

    flash_stage_load(sm32, K, Vt, 0, tid);
    CP_COMMIT();

    uint32_t qh[8][4], ql[8][4];
    {
        const __half* Qh = g_qhi + (size_t)bh * SEQ * HD + (size_t)qt * 64 * HD;
        const __half* Ql = g_qlo + (size_t)bh * SEQ * HD + (size_t)qt * 64 * HD;
        int r0 = (warp_m + g) * HD, r1 = (warp_m + g + 8) * HD;
#pragma unroll
        for (int kc = 0; kc < 8; kc++) {
            int c0 = kc * 16 + c * 2, c1 = c0 + 8;
            qh[kc][0] = *(const uint32_t*)(Qh + r0 + c0);
            qh[kc][1] = *(const uint32_t*)(Qh + r1 + c0);
            qh[kc][2] = *(const uint32_t*)(Qh + r0 + c1);
            qh[kc][3] = *(const uint32_t*)(Qh + r1 + c1);
            ql[kc][0] = *(const uint32_t*)(Ql + r0 + c0);
            ql[kc][1] = *(const uint32_t*)(Ql + r1 + c0);
            ql[kc][2] = *(const uint32_t*)(Ql + r0 + c1);
            ql[kc][3] = *(const uint32_t*)(Ql + r1 + c1);
        }
    }

    float o[16][4];
#pragma unroll
    for (int t = 0; t < 16; t++)
#pragma unroll
        for (int q = 0; q < 4; q++) o[t][q] = 0.f;
    float m0 = -1e30f, m1 = -1e30f, l0 = 0.f, l1 = 0.f;

    for (int kt = 0; kt < nkt; kt++) {
        if (kt + 1 < nkt)
            flash_stage_load(sm32 + ((kt + 1) & 1) * F_STAGE, K, Vt, kt + 1, tid);
        CP_COMMIT();
        CP_WAIT1();
        __syncthreads();

        uint32_t st = sm32 + (uint32_t)(kt & 1) * F_STAGE;

        // ---- S = Q @ K^T (16q x 64k per warp) ----
        float s_acc[8][4];
#pragma unroll
        for (int nj = 0; nj < 8; nj++)
#pragma unroll
            for (int q = 0; q < 4; q++) s_acc[nj][q] = 0.f;

#pragma unroll
        for (int kc = 0; kc < 8; kc++) {
#pragma unroll
            for (int njp = 0; njp < 4; njp++) {
                uint32_t b4[4];
                ldsm_x4(st + F_K + k_off[njp] + kc * 32, b4);
                int nj0 = njp * 2, nj1 = njp * 2 + 1;
                mma_f16(s_acc[nj0], qh[kc], b4 + 0);
                mma_f16(s_acc[nj1], qh[kc], b4 + 2);
                mma_f16(s_acc[nj0], ql[kc], b4 + 0);
                mma_f16(s_acc[nj1], ql[kc], b4 + 2);
            }
        }

        // ---- causal mask (diagonal tile only) ----
        if (kt == qt) {
            int row0 = qt * 64 + warp_m + g, row1 = row0 + 8;
            int colb = kt * FKT;
#pragma unroll
            for (int nj = 0; nj < 8; nj++) {
                int col = colb + nj * 8 + c * 2;
                if (col > row0) s_acc[nj][0] = -1e30f;
                if (col + 1 > row0) s_acc[nj][1] = -1e30f;
                if (col > row1) s_acc[nj][2] = -1e30f;
                if (col + 1 > row1) s_acc[nj][3] = -1e30f;
            }
        }

        // ---- online softmax ----
        float mt0 = -1e30f, mt1 = -1e30f;
#pragma unroll
        for (int nj = 0; nj < 8; nj++) {
            mt0 = fmaxf(mt0, fmaxf(s_acc[nj][0], s_acc[nj][1]));
            mt1 = fmaxf(mt1, fmaxf(s_acc[nj][2], s_acc[nj][3]));
        }
        mt0 = fmaxf(mt0, __shfl_xor_sync(0xffffffffu, mt0, 1));
        mt0 = fmaxf(mt0, __shfl_xor_sync(0xffffffffu, mt0, 2));
        mt1 = fmaxf(mt1, __shfl_xor_sync(0xffffffffu, mt1, 1));
        mt1 = fmaxf(mt1, __shfl_xor_sync(0xffffffffu, mt1, 2));
        float mn0 = fmaxf(m0, mt0), mn1 = fmaxf(m1, mt1);
        float a0 = __expf(m0 - mn0), a1 = __expf(m1 - mn1);
        m0 = mn0; m1 = mn1;
#pragma unroll
        for (int t = 0; t < 16; t++) {
            o[t][0] *= a0; o[t][1] *= a0;
            o[t][2] *= a1; o[t][3] *= a1;
        }
        float rs0 = 0.f, rs1 = 0.f;
#pragma unroll
        for (int nj = 0; nj < 8; nj++) {
            float p0 = __expf(s_acc[nj][0] - mn0);
            float p1 = __expf(s_acc[nj][1] - mn0);
            float p2 = __expf(s_acc[nj][2] - mn1);
            float p3 = __expf(s_acc[nj][3] - mn1);
            s_acc[nj][0] = p0; s_acc[nj][1] = p1;
            s_acc[nj][2] = p2; s_acc[nj][3] = p3;
            rs0 += p0 + p1; rs1 += p2 + p3;
        }
        l0 = l0 * a0 + rs0;
        l1 = l1 * a1 + rs1;

        // ---- P fragments (A-layout, single fp16) ----
        uint32_t ph[4][4];
#pragma unroll
        for (int kc = 0; kc < 4; kc++) {
            ph[kc][0] = pack2h(s_acc[2 * kc][0], s_acc[2 * kc][1]);
            ph[kc][1] = pack2h(s_acc[2 * kc][2], s_acc[2 * kc][3]);
            ph[kc][2] = pack2h(s_acc[2 * kc + 1][0], s_acc[2 * kc + 1][1]);
            ph[kc][3] = pack2h(s_acc[2 * kc + 1][2], s_acc[2 * kc + 1][3]);
        }

        // ---- O += P @ V ----
#pragma unroll
        for (int njp = 0; njp < 8; njp++) {
#pragma unroll
            for (int kc = 0; kc < 4; kc++) {
                uint32_t v4[4];
                ldsm_x4(st + F_V + v_off[njp] + kc * 32, v4);
                int nj0 = njp * 2, nj1 = njp * 2 + 1;
                mma_f16(o[nj0], ph[kc], v4 + 0);
                mma_f16(o[nj1], ph[kc], v4 + 2);
            }
        }
        __syncthreads();  // reads of this stage done before it is rewritten
    }

    l0 += __shfl_xor_sync(0xffffffffu, l0, 1);
    l0 += __shfl_xor_sync(0xffffffffu, l0, 2);
    l1 += __shfl_xor_sync(0xffffffffu, l1, 1);
    l1 += __shfl_xor_sync(0xffffffffu, l1, 2);
    float i0 = 1.0f / l0, i1 = 1.0f / l1;
    int b = bh >> 4, h = bh & 15;
    int s0 = qt * 64 + warp_m + g;
    size_t r0 = ((size_t)b * SEQ + s0) * E_DIM + h * HD;
    size_t r1 = ((size_t)b * SEQ + s0 + 8) * E_DIM + h * HD;
#pragma unroll
    for (int nj = 0; nj < 16; nj++) {
        int d = nj * 8 + c * 2;
        split_store2h(g_attn_hi, g_attn_lo, r0 + d, o[nj][0] * i0, o[nj][1] * i0);
        split_store2h(g_attn_hi, g_attn_lo, r1 + d, o[nj][2] * i1, o[nj][3] * i1);
    }
}

// ---------------- launcher ---------------------------------------------------
extern "C" void kernel_launch(void* const* d_in, const int* in_sizes, int n_in,
                              void* d_out, int out_size) {
    const float* x = (const float*)d_in[0];
    const float* Wq = (const float*)d_in[1];
    const float* Wk = (const float*)d_in[2];
    const float* Wv = (const float*)d_in[3];
    const float* Wo = (const float*)d_in[4];
    float* out = (float*)d_out;

    cudaFuncSetAttribute(gemm_qkv_tc, cudaFuncAttributeMaxDynamicSharedMemorySize,
                         GEMM_SMEM);
    cudaFuncSetAttribute(gemm_out_tc, cudaFuncAttributeMaxDynamicSharedMemorySize,
                         GEMM_SMEM);
    cudaFuncSetAttribute(flash_mma_kernel,
                         cudaFuncAttributeMaxDynamicSharedMemorySize, FLASH_SMEM);

    rope_init_kernel<<<(SEQ * (HD / 2) + 255) / 256, 256>>>();

    {
        int n4 = MROWS * E_DIM / 4;
        convert_x_kernel<<<(n4 + 255) / 256, 256>>>((const float4*)x);
        int w4 = E_DIM * E_DIM / 4;
        dim3 gw((w4 + 255) / 256, 4);
        convert_w_kernel<<<gw, 256>>>((const float4*)Wq, (const float4*)Wk,
                                      (const float4*)Wv, (const float4*)Wo);
    }

    dim3 gqkv(E_DIM / GBN, MROWS / GBM, 3);
    gemm_qkv_tc<<<gqkv, 256, GEMM_SMEM>>>();

    dim3 gtr(SEQ / 32, HD / 32, NBATCH * NHEAD);
    transpose_v_kernel<<<gtr, dim3(32, 8)>>>();

    dim3 gfa(SEQ / 64, NBATCH * NHEAD);
    flash_mma_kernel<<<gfa, 128, FLASH_SMEM>>>();

    dim3 gout(E_DIM / GBN, MROWS / GBM);
    gemm_out_tc<<<gout, 256, GEMM_SMEM>>>(out);
}

// round 15
// speedup vs baseline: 2.3216x; 1.1084x over previous
#include <cuda_runtime.h>
#include <cuda_fp16.h>
#include <math.h>
#include <stdint.h>

#define E_DIM 2048
#define SEQ 2048
#define NBATCH 2
#define NHEAD 16
#define HD 128
#define MROWS (NBATCH * SEQ) /* 4096 */

// ---------------- scratch (device globals; no allocation allowed) ----------
__device__ __half g_x_hi[MROWS * E_DIM];
__device__ __half g_x_lo[MROWS * E_DIM];
__device__ __half g_w[4 * E_DIM * E_DIM];
__device__ __half g_qhi[MROWS * E_DIM];
__device__ __half g_qlo[MROWS * E_DIM];
__device__ __half g_k[MROWS * E_DIM];
__device__ __half g_v[MROWS * E_DIM];
__device__ __half g_vt[MROWS * E_DIM];
__device__ __half g_attn[MROWS * E_DIM];   // single fp16 (this round's change)
__device__ float g_cos[SEQ * (HD / 2)];
__device__ float g_sin[SEQ * (HD / 2)];

// ---------------- helpers ----------------------------------------------------
__device__ __forceinline__ uint32_t smem_u32(const void* p) {
    uint32_t a;
    asm("{ .reg .u64 t; cvta.to.shared.u64 t, %1; cvt.u32.u64 %0, t; }"
        : "=r"(a) : "l"(p));
    return a;
}
__device__ __forceinline__ void cp_async16(uint32_t dst, const void* src) {
    asm volatile("cp.async.cg.shared.global [%0], [%1], 16;"
                 :: "r"(dst), "l"(src));
}
#define CP_COMMIT() asm volatile("cp.async.commit_group;" ::: "memory")
#define CP_WAIT1() asm volatile("cp.async.wait_group 1;" ::: "memory")

__device__ __forceinline__ void ldsm_x4(uint32_t addr, uint32_t* r) {
    asm volatile("ldmatrix.sync.aligned.m8n8.x4.shared.b16 {%0,%1,%2,%3}, [%4];"
                 : "=r"(r[0]), "=r"(r[1]), "=r"(r[2]), "=r"(r[3]) : "r"(addr));
}

__device__ __forceinline__ void mma_f16(float* d, const uint32_t* a,
                                        const uint32_t* b) {
    asm volatile(
        "mma.sync.aligned.m16n8k16.row.col.f32.f16.f16.f32 "
        "{%0,%1,%2,%3}, {%4,%5,%6,%7}, {%8,%9}, {%0,%1,%2,%3};"
        : "+f"(d[0]), "+f"(d[1]), "+f"(d[2]), "+f"(d[3])
        : "r"(a[0]), "r"(a[1]), "r"(a[2]), "r"(a[3]), "r"(b[0]), "r"(b[1]));
}

__device__ __forceinline__ void split_pack_h(float x, float y, uint32_t& hi,
                                             uint32_t& lo) {
    __half hx = __float2half_rn(x), hy = __float2half_rn(y);
    __half2 h2(hx, hy);
    hi = *(uint32_t*)&h2;
    __half2 l2(__float2half_rn(x - __half2float(hx)),
               __float2half_rn(y - __half2float(hy)));
    lo = *(uint32_t*)&l2;
}

__device__ __forceinline__ uint32_t pack2h(float x, float y) {
    __half2 h(__float2half_rn(x), __float2half_rn(y));
    return *(uint32_t*)&h;
}

__device__ __forceinline__ void split_store2h(__half* hi, __half* lo,
                                              size_t idx, float x, float y) {
    uint32_t h, l;
    split_pack_h(x, y, h, l);
    *(uint32_t*)(hi + idx) = h;
    *(uint32_t*)(lo + idx) = l;
}

__device__ __forceinline__ void store2h(__half* dst, size_t idx, float x,
                                        float y) {
    *(uint32_t*)(dst + idx) = pack2h(x, y);
}

// ---------------- RoPE table ------------------------------------------------
__global__ void rope_init_kernel() {
    int idx = blockIdx.x * blockDim.x + threadIdx.x;
    if (idx >= SEQ * (HD / 2)) return;
    int pos = idx / (HD / 2);
    int i = idx % (HD / 2);
    double invd = pow(10000.0, -(double)(2 * i) / (double)HD);
    float inv = (float)invd;
    float ang = (float)pos * inv;
    g_cos[idx] = (float)cos((double)ang);
    g_sin[idx] = (float)sin((double)ang);
}

// ---------------- conversions ------------------------------------------------
__global__ void convert_x_kernel(const float4* __restrict__ src) {
    int i = blockIdx.x * blockDim.x + threadIdx.x;
    if (i >= MROWS * E_DIM / 4) return;
    float4 v = src[i];
    uint32_t h0, l0, h1, l1;
    split_pack_h(v.x, v.y, h0, l0);
    split_pack_h(v.z, v.w, h1, l1);
    ((uint32_t*)g_x_hi)[i * 2 + 0] = h0;
    ((uint32_t*)g_x_hi)[i * 2 + 1] = h1;
    ((uint32_t*)g_x_lo)[i * 2 + 0] = l0;
    ((uint32_t*)g_x_lo)[i * 2 + 1] = l1;
}

__global__ void convert_w_kernel(const float4* __restrict__ w0,
                                 const float4* __restrict__ w1,
                                 const float4* __restrict__ w2,
                                 const float4* __restrict__ w3) {
    int i = blockIdx.x * blockDim.x + threadIdx.x;
    if (i >= E_DIM * E_DIM / 4) return;
    int z = blockIdx.y;
    const float4* src = (z == 0) ? w0 : (z == 1) ? w1 : (z == 2) ? w2 : w3;
    float4 v = src[i];
    __half2 a(__float2half_rn(v.x), __float2half_rn(v.y));
    __half2 b(__float2half_rn(v.z), __float2half_rn(v.w));
    __half2* dst = (__half2*)(g_w + (size_t)z * E_DIM * E_DIM);
    dst[i * 2 + 0] = a;
    dst[i * 2 + 1] = b;
}

// ---------------- HMMA GEMM: 128x128, BK=32, 3-stage -------------------------
#define GBM 128
#define GBN 128
#define GBK 32
#define NCHUNK (E_DIM / GBK) /* 64 */
#define BSTR 80
#define TILE_BYTES (128 * BSTR)      /* 10240 */
#define STAGE_BYTES (3 * TILE_BYTES) /* 30720: A_hi, A_lo, B */
#define NSTAGE 3
#define GEMM_SMEM (NSTAGE * STAGE_BYTES) /* 92160 */

// mode: 0=Q (rope+scale, split out), 1=K (rope), 2=V, 3=fp32 out
template <int ASPLIT>
__device__ __forceinline__ void gemm_mma_body(
    const __half* __restrict__ Ahi, const __half* __restrict__ Alo,
    const __half* __restrict__ B, float* __restrict__ Cout, int mode) {
    extern __shared__ char smem[];
    uint32_t sbase = smem_u32(smem);
    int tid = threadIdx.x;
    int wid = tid >> 5;
    int lane = tid & 31;
    int m0 = blockIdx.y * GBM;
    int n0 = blockIdx.x * GBN;
    int warp_m = (wid & 3) * 32;
    int warp_n = (wid >> 2) * 64;

    int gidx = lane >> 2;

    int a_row = (lane & 7) + ((lane >> 3) & 1) * 8;
    int a_col = (lane >> 4) * 16;
    uint32_t a_off[2];
#pragma unroll
    for (int mi = 0; mi < 2; mi++)
        a_off[mi] = (uint32_t)((warp_m + mi * 16 + a_row) * BSTR + a_col);
    int b_row = (lane & 7) + ((lane >> 4) & 1) * 8;
    int b_col = ((lane >> 3) & 1) * 16;
    uint32_t b_off[4];
#pragma unroll
    for (int njp = 0; njp < 4; njp++)
        b_off[njp] = (uint32_t)((warp_n + njp * 16 + b_row) * BSTR + b_col);

    int r0i = tid >> 2;
    int c0i = tid & 3;
    int r1i = (tid + 256) >> 2;
    int c1i = tid & 3;
    uint32_t s0 = (uint32_t)(r0i * BSTR + c0i * 16);
    uint32_t s1 = (uint32_t)(r1i * BSTR + c1i * 16);
    const __half* pa_hi0 = Ahi + (size_t)(m0 + r0i) * E_DIM + c0i * 8;
    const __half* pa_hi1 = Ahi + (size_t)(m0 + r1i) * E_DIM + c1i * 8;
    const __half* pa_lo0 = Alo + (size_t)(m0 + r0i) * E_DIM + c0i * 8;
    const __half* pa_lo1 = Alo + (size_t)(m0 + r1i) * E_DIM + c1i * 8;
    const __half* pb0 = B + (size_t)(n0 + r0i) * E_DIM + c0i * 8;
    const __half* pb1 = B + (size_t)(n0 + r1i) * E_DIM + c1i * 8;

    float acc[2][8][4];
#pragma unroll
    for (int mi = 0; mi < 2; mi++)
#pragma unroll
        for (int nj = 0; nj < 8; nj++)
#pragma unroll
            for (int q = 0; q < 4; q++) acc[mi][nj][q] = 0.f;

#pragma unroll
    for (int s = 0; s < NSTAGE - 1; s++) {
        uint32_t st = sbase + s * STAGE_BYTES;
        int k0 = s * GBK;
        cp_async16(st + 0 * TILE_BYTES + s0, pa_hi0 + k0);
        cp_async16(st + 0 * TILE_BYTES + s1, pa_hi1 + k0);
        if (ASPLIT) {
            cp_async16(st + 1 * TILE_BYTES + s0, pa_lo0 + k0);
            cp_async16(st + 1 * TILE_BYTES + s1, pa_lo1 + k0);
        }
        cp_async16(st + 2 * TILE_BYTES + s0, pb0 + k0);
        cp_async16(st + 2 * TILE_BYTES + s1, pb1 + k0);
        CP_COMMIT();
    }

    int slot = 0, wslot = NSTAGE - 1;
    for (int c = 0; c < NCHUNK; c++) {
        CP_WAIT1();
        __syncthreads();

        uint32_t st = sbase + (uint32_t)slot * STAGE_BYTES;

#pragma unroll
        for (int kc = 0; kc < 2; kc++) {
            uint32_t ko = (uint32_t)(kc * 32);
            uint32_t ahi[2][4], alo[2][4];
#pragma unroll
            for (int mi = 0; mi < 2; mi++) {
                ldsm_x4(st + a_off[mi] + ko, ahi[mi]);
                if (ASPLIT) ldsm_x4(st + TILE_BYTES + a_off[mi] + ko, alo[mi]);
            }
#pragma unroll
            for (int njp = 0; njp < 4; njp++) {
                uint32_t b4[4];
                ldsm_x4(st + 2 * TILE_BYTES + b_off[njp] + ko, b4);
                int nj0 = njp * 2, nj1 = njp * 2 + 1;
                mma_f16(acc[0][nj0], ahi[0], b4 + 0);
                mma_f16(acc[1][nj0], ahi[1], b4 + 0);
                mma_f16(acc[0][nj1], ahi[0], b4 + 2);
                mma_f16(acc[1][nj1], ahi[1], b4 + 2);
                if (ASPLIT) {
                    mma_f16(acc[0][nj0], alo[0], b4 + 0);
                    mma_f16(acc[1][nj0], alo[1], b4 + 0);
                    mma_f16(acc[0][nj1], alo[0], b4 + 2);
                    mma_f16(acc[1][nj1], alo[1], b4 + 2);
                }
            }
        }

        if (c + NSTAGE - 1 < NCHUNK) {
            uint32_t sw = sbase + (uint32_t)wslot * STAGE_BYTES;
            int k0 = (c + NSTAGE - 1) * GBK;
            cp_async16(sw + 0 * TILE_BYTES + s0, pa_hi0 + k0);
            cp_async16(sw + 0 * TILE_BYTES + s1, pa_hi1 + k0);
            if (ASPLIT) {
                cp_async16(sw + 1 * TILE_BYTES + s0, pa_lo0 + k0);
                cp_async16(sw + 1 * TILE_BYTES + s1, pa_lo1 + k0);
            }
            cp_async16(sw + 2 * TILE_BYTES + s0, pb0 + k0);
            cp_async16(sw + 2 * TILE_BYTES + s1, pb1 + k0);
        }
        CP_COMMIT();
        slot = (slot + 1 == NSTAGE) ? 0 : slot + 1;
        wslot = (wslot + 1 == NSTAGE) ? 0 : wslot + 1;
    }

    int tig = lane & 3;
    const float qsc = (mode == 0) ? 0.08838834764831845f : 1.0f;

#pragma unroll
    for (int mi = 0; mi < 2; mi++) {
#pragma unroll
        for (int nj = 0; nj < 8; nj++) {
            int m = m0 + warp_m + mi * 16 + gidx;
            int n = n0 + warp_n + nj * 8 + tig * 2;
            float v0 = acc[mi][nj][0], v1 = acc[mi][nj][1];
            float v2 = acc[mi][nj][2], v3 = acc[mi][nj][3];
            if (mode <= 1) {
                int pi = (n & (HD - 1)) >> 1;
                int p0 = m & (SEQ - 1);
                int p8 = p0 + 8;
                float c0 = g_cos[p0 * (HD / 2) + pi], sn0 = g_sin[p0 * (HD / 2) + pi];
                float c8 = g_cos[p8 * (HD / 2) + pi], sn8 = g_sin[p8 * (HD / 2) + pi];
                float t0 = v0 * c0 - v1 * sn0, t1 = v0 * sn0 + v1 * c0;
                float t2 = v2 * c8 - v3 * sn8, t3 = v2 * sn8 + v3 * c8;
                v0 = t0 * qsc; v1 = t1 * qsc; v2 = t2 * qsc; v3 = t3 * qsc;
            }
            if (mode == 3) {
                *(float2*)&Cout[(size_t)m * E_DIM + n] = make_float2(v0, v1);
                *(float2*)&Cout[(size_t)(m + 8) * E_DIM + n] = make_float2(v2, v3);
            } else {
                int b = m >> 11, s = m & 2047, h = n >> 7, d = n & 127;
                size_t base0 = ((size_t)(b * NHEAD + h) * SEQ + s) * HD + d;
                size_t base1 = base0 + 8 * HD;
                if (mode == 0) {
                    split_store2h(g_qhi, g_qlo, base0, v0, v1);
                    split_store2h(g_qhi, g_qlo, base1, v2, v3);
                } else if (mode == 1) {
                    store2h(g_k, base0, v0, v1);
                    store2h(g_k, base1, v2, v3);
                } else {
                    store2h(g_v, base0, v0, v1);
                    store2h(g_v, base1, v2, v3);
                }
            }
        }
    }
}

__global__ __launch_bounds__(256, 2) void gemm_qkv_tc(void) {
    int z = blockIdx.z;
    const __half* b = g_w + (size_t)z * E_DIM * E_DIM;
    if (z == 0)
        gemm_mma_body<1>(g_x_hi, g_x_lo, b, nullptr, 0);  // Q: split X
    else
        gemm_mma_body<0>(g_x_hi, g_x_lo, b, nullptr, z);  // K,V: single X
}

__global__ __launch_bounds__(256, 2) void gemm_out_tc(float* __restrict__ out) {
    const __half* b = g_w + (size_t)3 * E_DIM * E_DIM;
    gemm_mma_body<0>(g_attn, g_attn, b, out, 3);  // attn: single
}

// ---------------- V transpose: [bh][s][d] -> [bh][d][s] ---------------------
__global__ void transpose_v_kernel() {
    __shared__ __half t[32][33];
    int bh = blockIdx.z;
    int tx = threadIdx.x, ty = threadIdx.y;
    int s0 = blockIdx.x * 32, d0 = blockIdx.y * 32;
#pragma unroll
    for (int i = 0; i < 32; i += 8)
        t[ty + i][tx] = g_v[((size_t)bh * SEQ + s0 + ty + i) * HD + d0 + tx];
    __syncthreads();
#pragma unroll
    for (int i = 0; i < 32; i += 8)
        g_vt[((size_t)bh * HD + d0 + ty + i) * SEQ + s0 + tx] = t[tx][ty + i];
}

// ---------------- Tensor-core flash attention (causal, cp.async DB) ---------
// 4 warps, q-tile 64, k-tile 64, 2-stage DB. Q split; P single; attn single out.
#define FKT 64
#define KSTR2 272
#define VSTR3 144
#define F_K 0
#define F_V (64 * KSTR2)            /* 17408 */
#define F_STAGE (F_V + 128 * VSTR3) /* 35840 */
#define FLASH_SMEM (2 * F_STAGE)    /* 71680 */

__device__ __forceinline__ void flash_stage_load(uint32_t sst,
                                                 const __half* K,
                                                 const __half* Vt, int kt,
                                                 int tid) {
    int k0 = kt * FKT;
#pragma unroll
    for (int i = 0; i < 8; i++) {
        int idx = tid + i * 128;
        int row = idx >> 4, cc = idx & 15;
        cp_async16(sst + F_K + (uint32_t)(row * KSTR2 + cc * 16),
                   K + (size_t)(k0 + row) * HD + cc * 8);
    }
#pragma unroll
    for (int i = 0; i < 8; i++) {
        int idx = tid + i * 128;
        int row = idx >> 3, cc = idx & 7;
        cp_async16(sst + F_V + (uint32_t)(row * VSTR3 + cc * 16),
                   Vt + (size_t)row * SEQ + k0 + cc * 8);
    }
}

__global__ __launch_bounds__(128) void flash_mma_kernel() {
    extern __shared__ char sm[];
    uint32_t sm32 = smem_u32(sm);

    int tid = threadIdx.x;
    int wid = tid >> 5;
    int lane = tid & 31;
    int qt = (int)gridDim.x - 1 - (int)blockIdx.x;  // heavy tiles first
    int bh = blockIdx.y;
    int g = lane >> 2;
    int c = lane & 3;
    int warp_m = wid * 16;
    int nkt = qt + 1;

    int b_row = (lane & 7) + ((lane >> 4) & 1) * 8;
    int b_col = ((lane >> 3) & 1) * 16;
    uint32_t k_off[4], v_off[8];
#pragma unroll
    for (int njp = 0; njp < 4; njp++)
        k_off[njp] = (uint32_t)((njp * 16 + b_row) * KSTR2 + b_col);
#pragma unroll
    for (int njp = 0; njp < 8; njp++)
        v_off[njp] = (uint32_t)((njp * 16 + b_row) * VSTR3 + b_col);

    const __half* K = g_k + (size_t)bh * SEQ * HD;
    const __half* Vt = g_vt + (size_t)bh * HD * SEQ;

    flash_stage_load(sm32, K, Vt, 0, tid);
    CP_COMMIT();

    uint32_t qh[8][4], ql[8][4];
    {
        const __half* Qh = g_qhi + (size_t)bh * SEQ * HD + (size_t)qt * 64 * HD;
        const __half* Ql = g_qlo + (size_t)bh * SEQ * HD + (size_t)qt * 64 * HD;
        int r0 = (warp_m + g) * HD, r1 = (warp_m + g + 8) * HD;
#pragma unroll
        for (int kc = 0; kc < 8; kc++) {
            int c0 = kc * 16 + c * 2, c1 = c0 + 8;
            qh[kc][0] = *(const uint32_t*)(Qh + r0 + c0);
            qh[kc][1] = *(const uint32_t*)(Qh + r1 + c0);
            qh[kc][2] = *(const uint32_t*)(Qh + r0 + c1);
            qh[kc][3] = *(const uint32_t*)(Qh + r1 + c1);
            ql[kc][0] = *(const uint32_t*)(Ql + r0 + c0);
            ql[kc][1] = *(const uint32_t*)(Ql + r1 + c0);
            ql[kc][2] = *(const uint32_t*)(Ql + r0 + c1);
            ql[kc][3] = *(const uint32_t*)(Ql + r1 + c1);
        }
    }

    float o[16][4];
#pragma unroll
    for (int t = 0; t < 16; t++)
#pragma unroll
        for (int q = 0; q < 4; q++) o[t][q] = 0.f;
    float m0 = -1e30f, m1 = -1e30f, l0 = 0.f, l1 = 0.f;

    for (int kt = 0; kt < nkt; kt++) {
        if (kt + 1 < nkt)
            flash_stage_load(sm32 + ((kt + 1) & 1) * F_STAGE, K, Vt, kt + 1, tid);
        CP_COMMIT();
        CP_WAIT1();
        __syncthreads();

        uint32_t st = sm32 + (uint32_t)(kt & 1) * F_STAGE;

        // ---- S = Q @ K^T (16q x 64k per warp) ----
        float s_acc[8][4];
#pragma unroll
        for (int nj = 0; nj < 8; nj++)
#pragma unroll
            for (int q = 0; q < 4; q++) s_acc[nj][q] = 0.f;

#pragma unroll
        for (int kc = 0; kc < 8; kc++) {
#pragma unroll
            for (int njp = 0; njp < 4; njp++) {
                uint32_t b4[4];
                ldsm_x4(st + F_K + k_off[njp] + kc * 32, b4);
                int nj0 = njp * 2, nj1 = njp * 2 + 1;
                mma_f16(s_acc[nj0], qh[kc], b4 + 0);
                mma_f16(s_acc[nj1], qh[kc], b4 + 2);
                mma_f16(s_acc[nj0], ql[kc], b4 + 0);
                mma_f16(s_acc[nj1], ql[kc], b4 + 2);
            }
        }

        // ---- causal mask (diagonal tile only) ----
        if (kt == qt) {
            int row0 = qt * 64 + warp_m + g, row1 = row0 + 8;
            int colb = kt * FKT;
#pragma unroll
            for (int nj = 0; nj < 8; nj++) {
                int col = colb + nj * 8 + c * 2;
                if (col > row0) s_acc[nj][0] = -1e30f;
                if (col + 1 > row0) s_acc[nj][1] = -1e30f;
                if (col > row1) s_acc[nj][2] = -1e30f;
                if (col + 1 > row1) s_acc[nj][3] = -1e30f;
            }
        }

        // ---- online softmax ----
        float mt0 = -1e30f, mt1 = -1e30f;
#pragma unroll
        for (int nj = 0; nj < 8; nj++) {
            mt0 = fmaxf(mt0, fmaxf(s_acc[nj][0], s_acc[nj][1]));
            mt1 = fmaxf(mt1, fmaxf(s_acc[nj][2], s_acc[nj][3]));
        }
        mt0 = fmaxf(mt0, __shfl_xor_sync(0xffffffffu, mt0, 1));
        mt0 = fmaxf(mt0, __shfl_xor_sync(0xffffffffu, mt0, 2));
        mt1 = fmaxf(mt1, __shfl_xor_sync(0xffffffffu, mt1, 1));
        mt1 = fmaxf(mt1, __shfl_xor_sync(0xffffffffu, mt1, 2));
        float mn0 = fmaxf(m0, mt0), mn1 = fmaxf(m1, mt1);
        float a0 = __expf(m0 - mn0), a1 = __expf(m1 - mn1);
        m0 = mn0; m1 = mn1;
#pragma unroll
        for (int t = 0; t < 16; t++) {
            o[t][0] *= a0; o[t][1] *= a0;
            o[t][2] *= a1; o[t][3] *= a1;
        }
        float rs0 = 0.f, rs1 = 0.f;
#pragma unroll
        for (int nj = 0; nj < 8; nj++) {
            float p0 = __expf(s_acc[nj][0] - mn0);
            float p1 = __expf(s_acc[nj][1] - mn0);
            float p2 = __expf(s_acc[nj][2] - mn1);
            float p3 = __expf(s_acc[nj][3] - mn1);
            s_acc[nj][0] = p0; s_acc[nj][1] = p1;
            s_acc[nj][2] = p2; s_acc[nj][3] = p3;
            rs0 += p0 + p1; rs1 += p2 + p3;
        }
        l0 = l0 * a0 + rs0;
        l1 = l1 * a1 + rs1;

        // ---- P fragments (A-layout, single fp16) ----
        uint32_t ph[4][4];
#pragma unroll
        for (int kc = 0; kc < 4; kc++) {
            ph[kc][0] = pack2h(s_acc[2 * kc][0], s_acc[2 * kc][1]);
            ph[kc][1] = pack2h(s_acc[2 * kc][2], s_acc[2 * kc][3]);
            ph[kc][2] = pack2h(s_acc[2 * kc + 1][0], s_acc[2 * kc + 1][1]);
            ph[kc][3] = pack2h(s_acc[2 * kc + 1][2], s_acc[2 * kc + 1][3]);
        }

        // ---- O += P @ V ----
#pragma unroll
        for (int njp = 0; njp < 8; njp++) {
#pragma unroll
            for (int kc = 0; kc < 4; kc++) {
                uint32_t v4[4];
                ldsm_x4(st + F_V + v_off[njp] + kc * 32, v4);
                int nj0 = njp * 2, nj1 = njp * 2 + 1;
                mma_f16(o[nj0], ph[kc], v4 + 0);
                mma_f16(o[nj1], ph[kc], v4 + 2);
            }
        }
        __syncthreads();  // reads of this stage done before it is rewritten
    }

    l0 += __shfl_xor_sync(0xffffffffu, l0, 1);
    l0 += __shfl_xor_sync(0xffffffffu, l0, 2);
    l1 += __shfl_xor_sync(0xffffffffu, l1, 1);
    l1 += __shfl_xor_sync(0xffffffffu, l1, 2);
    float i0 = 1.0f / l0, i1 = 1.0f / l1;
    int b = bh >> 4, h = bh & 15;
    int s0 = qt * 64 + warp_m + g;
    size_t r0 = ((size_t)b * SEQ + s0) * E_DIM + h * HD;
    size_t r1 = ((size_t)b * SEQ + s0 + 8) * E_DIM + h * HD;
#pragma unroll
    for (int nj = 0; nj < 16; nj++) {
        int d = nj * 8 + c * 2;
        store2h(g_attn, r0 + d, o[nj][0] * i0, o[nj][1] * i0);
        store2h(g_attn, r1 + d, o[nj][2] * i1, o[nj][3] * i1);
    }
}

// ---------------- launcher ---------------------------------------------------
extern "C" void kernel_launch(void* const* d_in, const int* in_sizes, int n_in,
                              void* d_out, int out_size) {
    const float* x = (const float*)d_in[0];
    const float* Wq = (const float*)d_in[1];
    const float* Wk = (const float*)d_in[2];
    const float* Wv = (const float*)d_in[3];
    const float* Wo = (const float*)d_in[4];
    float* out = (float*)d_out;

    cudaFuncSetAttribute(gemm_qkv_tc, cudaFuncAttributeMaxDynamicSharedMemorySize,
                         GEMM_SMEM);
    cudaFuncSetAttribute(gemm_out_tc, cudaFuncAttributeMaxDynamicSharedMemorySize,
                         GEMM_SMEM);
    cudaFuncSetAttribute(flash_mma_kernel,
                         cudaFuncAttributeMaxDynamicSharedMemorySize, FLASH_SMEM);

    rope_init_kernel<<<(SEQ * (HD / 2) + 255) / 256, 256>>>();

    {
        int n4 = MROWS * E_DIM / 4;
        convert_x_kernel<<<(n4 + 255) / 256, 256>>>((const float4*)x);
        int w4 = E_DIM * E_DIM / 4;
        dim3 gw((w4 + 255) / 256, 4);
        convert_w_kernel<<<gw, 256>>>((const float4*)Wq, (const float4*)Wk,
                                      (const float4*)Wv, (const float4*)Wo);
    }

    dim3 gqkv(E_DIM / GBN, MROWS / GBM, 3);
    gemm_qkv_tc<<<gqkv, 256, GEMM_SMEM>>>();

    dim3 gtr(SEQ / 32, HD / 32, NBATCH * NHEAD);
    transpose_v_kernel<<<gtr, dim3(32, 8)>>>();

    dim3 gfa(SEQ / 64, NBATCH * NHEAD);
    flash_mma_kernel<<<gfa, 128, FLASH_SMEM>>>();

    dim3 gout(E_DIM / GBN, MROWS / GBM);
    gemm_out_tc<<<gout, 256, GEMM_SMEM>>>(out);
}

// round 16
// speedup vs baseline: 2.4591x; 1.0592x over previous
#include <cuda_runtime.h>
#include <cuda_fp16.h>
#include <math.h>
#include <stdint.h>

#define E_DIM 2048
#define SEQ 2048
#define NBATCH 2
#define NHEAD 16
#define HD 128
#define MROWS (NBATCH * SEQ) /* 4096 */

// ---------------- scratch (device globals; no allocation allowed) ----------
__device__ __half g_x_hi[MROWS * E_DIM];
__device__ __half g_x_lo[MROWS * E_DIM];
__device__ __half g_w[4 * E_DIM * E_DIM];
__device__ __half g_qhi[MROWS * E_DIM];
__device__ __half g_qlo[MROWS * E_DIM];
__device__ __half g_k[MROWS * E_DIM];
__device__ __half g_vt[MROWS * E_DIM];  // V transposed [bh][d][s], written by V GEMM
__device__ __half g_attn[MROWS * E_DIM];
__device__ float g_cos[SEQ * (HD / 2)];
__device__ float g_sin[SEQ * (HD / 2)];

// ---------------- helpers ----------------------------------------------------
__device__ __forceinline__ uint32_t smem_u32(const void* p) {
    uint32_t a;
    asm("{ .reg .u64 t; cvta.to.shared.u64 t, %1; cvt.u32.u64 %0, t; }"
        : "=r"(a) : "l"(p));
    return a;
}
__device__ __forceinline__ void cp_async16(uint32_t dst, const void* src) {
    asm volatile("cp.async.cg.shared.global [%0], [%1], 16;"
                 :: "r"(dst), "l"(src));
}
#define CP_COMMIT() asm volatile("cp.async.commit_group;" ::: "memory")
#define CP_WAIT1() asm volatile("cp.async.wait_group 1;" ::: "memory")

__device__ __forceinline__ void ldsm_x4(uint32_t addr, uint32_t* r) {
    asm volatile("ldmatrix.sync.aligned.m8n8.x4.shared.b16 {%0,%1,%2,%3}, [%4];"
                 : "=r"(r[0]), "=r"(r[1]), "=r"(r[2]), "=r"(r[3]) : "r"(addr));
}

__device__ __forceinline__ void mma_f16(float* d, const uint32_t* a,
                                        const uint32_t* b) {
    asm volatile(
        "mma.sync.aligned.m16n8k16.row.col.f32.f16.f16.f32 "
        "{%0,%1,%2,%3}, {%4,%5,%6,%7}, {%8,%9}, {%0,%1,%2,%3};"
        : "+f"(d[0]), "+f"(d[1]), "+f"(d[2]), "+f"(d[3])
        : "r"(a[0]), "r"(a[1]), "r"(a[2]), "r"(a[3]), "r"(b[0]), "r"(b[1]));
}

__device__ __forceinline__ void split_pack_h(float x, float y, uint32_t& hi,
                                             uint32_t& lo) {
    __half hx = __float2half_rn(x), hy = __float2half_rn(y);
    __half2 h2(hx, hy);
    hi = *(uint32_t*)&h2;
    __half2 l2(__float2half_rn(x - __half2float(hx)),
               __float2half_rn(y - __half2float(hy)));
    lo = *(uint32_t*)&l2;
}

__device__ __forceinline__ uint32_t pack2h(float x, float y) {
    __half2 h(__float2half_rn(x), __float2half_rn(y));
    return *(uint32_t*)&h;
}

__device__ __forceinline__ void split_store2h(__half* hi, __half* lo,
                                              size_t idx, float x, float y) {
    uint32_t h, l;
    split_pack_h(x, y, h, l);
    *(uint32_t*)(hi + idx) = h;
    *(uint32_t*)(lo + idx) = l;
}

__device__ __forceinline__ void store2h(__half* dst, size_t idx, float x,
                                        float y) {
    *(uint32_t*)(dst + idx) = pack2h(x, y);
}

// ---------------- RoPE table ------------------------------------------------
__global__ void rope_init_kernel() {
    int idx = blockIdx.x * blockDim.x + threadIdx.x;
    if (idx >= SEQ * (HD / 2)) return;
    int pos = idx / (HD / 2);
    int i = idx % (HD / 2);
    double invd = pow(10000.0, -(double)(2 * i) / (double)HD);
    float inv = (float)invd;
    float ang = (float)pos * inv;
    g_cos[idx] = (float)cos((double)ang);
    g_sin[idx] = (float)sin((double)ang);
}

// ---------------- conversions ------------------------------------------------
__global__ void convert_x_kernel(const float4* __restrict__ src) {
    int i = blockIdx.x * blockDim.x + threadIdx.x;
    if (i >= MROWS * E_DIM / 4) return;
    float4 v = src[i];
    uint32_t h0, l0, h1, l1;
    split_pack_h(v.x, v.y, h0, l0);
    split_pack_h(v.z, v.w, h1, l1);
    ((uint32_t*)g_x_hi)[i * 2 + 0] = h0;
    ((uint32_t*)g_x_hi)[i * 2 + 1] = h1;
    ((uint32_t*)g_x_lo)[i * 2 + 0] = l0;
    ((uint32_t*)g_x_lo)[i * 2 + 1] = l1;
}

__global__ void convert_w_kernel(const float4* __restrict__ w0,
                                 const float4* __restrict__ w1,
                                 const float4* __restrict__ w2,
                                 const float4* __restrict__ w3) {
    int i = blockIdx.x * blockDim.x + threadIdx.x;
    if (i >= E_DIM * E_DIM / 4) return;
    int z = blockIdx.y;
    const float4* src = (z == 0) ? w0 : (z == 1) ? w1 : (z == 2) ? w2 : w3;
    float4 v = src[i];
    __half2 a(__float2half_rn(v.x), __float2half_rn(v.y));
    __half2 b(__float2half_rn(v.z), __float2half_rn(v.w));
    __half2* dst = (__half2*)(g_w + (size_t)z * E_DIM * E_DIM);
    dst[i * 2 + 0] = a;
    dst[i * 2 + 1] = b;
}

// ================= GEMM common tile params ===================================
#define GBM 128
#define GBN 128

// ---- body32: BK=32, split-A (Q projection) ----------------------------------
#define GBK32 32
#define NCHUNK32 (E_DIM / GBK32) /* 64 */
#define BSTR32 80
#define TILE32 (128 * BSTR32)     /* 10240 */
#define STAGE32 (3 * TILE32)      /* 30720 */
#define NST32 3

// ---- body64: BK=64, single-A (K, V, out) ------------------------------------
#define GBK64 64
#define NCHUNK64 (E_DIM / GBK64) /* 32 */
#define BSTR64 144
#define TILE64 (128 * BSTR64)     /* 18432 */
#define STAGE64 (2 * TILE64)      /* 36864 */
#define NST64 3
#define GEMM_SMEM (NST64 * STAGE64) /* 110592 (max of both bodies) */

// common epilogue. mode: 0=Q (rope+scale, split), 1=K (rope), 2=V->g_vt, 3=fp32
__device__ __forceinline__ void gemm_epilogue(float acc[2][8][4], int m0,
                                              int n0, int warp_m, int warp_n,
                                              int gidx, int tig,
                                              float* __restrict__ Cout,
                                              int mode) {
    const float qsc = (mode == 0) ? 0.08838834764831845f : 1.0f;
#pragma unroll
    for (int mi = 0; mi < 2; mi++) {
#pragma unroll
        for (int nj = 0; nj < 8; nj++) {
            int m = m0 + warp_m + mi * 16 + gidx;
            int n = n0 + warp_n + nj * 8 + tig * 2;
            float v0 = acc[mi][nj][0], v1 = acc[mi][nj][1];
            float v2 = acc[mi][nj][2], v3 = acc[mi][nj][3];
            if (mode <= 1) {
                int pi = (n & (HD - 1)) >> 1;
                int p0 = m & (SEQ - 1);
                int p8 = p0 + 8;
                float c0 = g_cos[p0 * (HD / 2) + pi], sn0 = g_sin[p0 * (HD / 2) + pi];
                float c8 = g_cos[p8 * (HD / 2) + pi], sn8 = g_sin[p8 * (HD / 2) + pi];
                float t0 = v0 * c0 - v1 * sn0, t1 = v0 * sn0 + v1 * c0;
                float t2 = v2 * c8 - v3 * sn8, t3 = v2 * sn8 + v3 * c8;
                v0 = t0 * qsc; v1 = t1 * qsc; v2 = t2 * qsc; v3 = t3 * qsc;
            }
            if (mode == 3) {
                *(float2*)&Cout[(size_t)m * E_DIM + n] = make_float2(v0, v1);
                *(float2*)&Cout[(size_t)(m + 8) * E_DIM + n] = make_float2(v2, v3);
            } else {
                int b = m >> 11, s = m & 2047, h = n >> 7, d = n & 127;
                int bh = b * NHEAD + h;
                if (mode == 0) {
                    size_t base0 = ((size_t)bh * SEQ + s) * HD + d;
                    split_store2h(g_qhi, g_qlo, base0, v0, v1);
                    split_store2h(g_qhi, g_qlo, base0 + 8 * HD, v2, v3);
                } else if (mode == 1) {
                    size_t base0 = ((size_t)bh * SEQ + s) * HD + d;
                    store2h(g_k, base0, v0, v1);
                    store2h(g_k, base0 + 8 * HD, v2, v3);
                } else {
                    // V: write transposed [bh][d][s]
                    size_t tb = ((size_t)bh * HD + d) * SEQ + s;
                    g_vt[tb] = __float2half_rn(v0);
                    g_vt[tb + SEQ] = __float2half_rn(v1);
                    g_vt[tb + 8] = __float2half_rn(v2);
                    g_vt[tb + SEQ + 8] = __float2half_rn(v3);
                }
            }
        }
    }
}

__device__ __forceinline__ void gemm_body32_split(
    const __half* __restrict__ Ahi, const __half* __restrict__ Alo,
    const __half* __restrict__ B) {
    extern __shared__ char smem[];
    uint32_t sbase = smem_u32(smem);
    int tid = threadIdx.x;
    int wid = tid >> 5;
    int lane = tid & 31;
    int m0 = blockIdx.y * GBM;
    int n0 = blockIdx.x * GBN;
    int warp_m = (wid & 3) * 32;
    int warp_n = (wid >> 2) * 64;
    int gidx = lane >> 2;

    int a_row = (lane & 7) + ((lane >> 3) & 1) * 8;
    int a_col = (lane >> 4) * 16;
    uint32_t a_off[2];
#pragma unroll
    for (int mi = 0; mi < 2; mi++)
        a_off[mi] = (uint32_t)((warp_m + mi * 16 + a_row) * BSTR32 + a_col);
    int b_row = (lane & 7) + ((lane >> 4) & 1) * 8;
    int b_col = ((lane >> 3) & 1) * 16;
    uint32_t b_off[4];
#pragma unroll
    for (int njp = 0; njp < 4; njp++)
        b_off[njp] = (uint32_t)((warp_n + njp * 16 + b_row) * BSTR32 + b_col);

    int r0i = tid >> 2;
    int c0i = tid & 3;
    int r1i = (tid + 256) >> 2;
    uint32_t s0 = (uint32_t)(r0i * BSTR32 + c0i * 16);
    uint32_t s1 = (uint32_t)(r1i * BSTR32 + c0i * 16);
    const __half* pa_hi0 = Ahi + (size_t)(m0 + r0i) * E_DIM + c0i * 8;
    const __half* pa_hi1 = Ahi + (size_t)(m0 + r1i) * E_DIM + c0i * 8;
    const __half* pa_lo0 = Alo + (size_t)(m0 + r0i) * E_DIM + c0i * 8;
    const __half* pa_lo1 = Alo + (size_t)(m0 + r1i) * E_DIM + c0i * 8;
    const __half* pb0 = B + (size_t)(n0 + r0i) * E_DIM + c0i * 8;
    const __half* pb1 = B + (size_t)(n0 + r1i) * E_DIM + c0i * 8;

    float acc[2][8][4];
#pragma unroll
    for (int mi = 0; mi < 2; mi++)
#pragma unroll
        for (int nj = 0; nj < 8; nj++)
#pragma unroll
            for (int q = 0; q < 4; q++) acc[mi][nj][q] = 0.f;

#pragma unroll
    for (int s = 0; s < NST32 - 1; s++) {
        uint32_t st = sbase + s * STAGE32;
        int k0 = s * GBK32;
        cp_async16(st + 0 * TILE32 + s0, pa_hi0 + k0);
        cp_async16(st + 0 * TILE32 + s1, pa_hi1 + k0);
        cp_async16(st + 1 * TILE32 + s0, pa_lo0 + k0);
        cp_async16(st + 1 * TILE32 + s1, pa_lo1 + k0);
        cp_async16(st + 2 * TILE32 + s0, pb0 + k0);
        cp_async16(st + 2 * TILE32 + s1, pb1 + k0);
        CP_COMMIT();
    }

    int slot = 0, wslot = NST32 - 1;
    for (int c = 0; c < NCHUNK32; c++) {
        CP_WAIT1();
        __syncthreads();

        uint32_t st = sbase + (uint32_t)slot * STAGE32;
#pragma unroll
        for (int kc = 0; kc < 2; kc++) {
            uint32_t ko = (uint32_t)(kc * 32);
            uint32_t ahi[2][4], alo[2][4];
#pragma unroll
            for (int mi = 0; mi < 2; mi++) {
                ldsm_x4(st + a_off[mi] + ko, ahi[mi]);
                ldsm_x4(st + TILE32 + a_off[mi] + ko, alo[mi]);
            }
#pragma unroll
            for (int njp = 0; njp < 4; njp++) {
                uint32_t b4[4];
                ldsm_x4(st + 2 * TILE32 + b_off[njp] + ko, b4);
                int nj0 = njp * 2, nj1 = njp * 2 + 1;
                mma_f16(acc[0][nj0], ahi[0], b4 + 0);
                mma_f16(acc[1][nj0], ahi[1], b4 + 0);
                mma_f16(acc[0][nj1], ahi[0], b4 + 2);
                mma_f16(acc[1][nj1], ahi[1], b4 + 2);
                mma_f16(acc[0][nj0], alo[0], b4 + 0);
                mma_f16(acc[1][nj0], alo[1], b4 + 0);
                mma_f16(acc[0][nj1], alo[0], b4 + 2);
                mma_f16(acc[1][nj1], alo[1], b4 + 2);
            }
        }

        if (c + NST32 - 1 < NCHUNK32) {
            uint32_t sw = sbase + (uint32_t)wslot * STAGE32;
            int k0 = (c + NST32 - 1) * GBK32;
            cp_async16(sw + 0 * TILE32 + s0, pa_hi0 + k0);
            cp_async16(sw + 0 * TILE32 + s1, pa_hi1 + k0);
            cp_async16(sw + 1 * TILE32 + s0, pa_lo0 + k0);
            cp_async16(sw + 1 * TILE32 + s1, pa_lo1 + k0);
            cp_async16(sw + 2 * TILE32 + s0, pb0 + k0);
            cp_async16(sw + 2 * TILE32 + s1, pb1 + k0);
        }
        CP_COMMIT();
        slot = (slot + 1 == NST32) ? 0 : slot + 1;
        wslot = (wslot + 1 == NST32) ? 0 : wslot + 1;
    }

    gemm_epilogue(acc, m0, n0, warp_m, warp_n, gidx, lane & 3, nullptr, 0);
}

__device__ __forceinline__ void gemm_body64_single(
    const __half* __restrict__ A, const __half* __restrict__ B,
    float* __restrict__ Cout, int mode) {
    extern __shared__ char smem[];
    uint32_t sbase = smem_u32(smem);
    int tid = threadIdx.x;
    int wid = tid >> 5;
    int lane = tid & 31;
    int m0 = blockIdx.y * GBM;
    int n0 = blockIdx.x * GBN;
    int warp_m = (wid & 3) * 32;
    int warp_n = (wid >> 2) * 64;
    int gidx = lane >> 2;

    int a_row = (lane & 7) + ((lane >> 3) & 1) * 8;
    int a_col = (lane >> 4) * 16;
    uint32_t a_off[2];
#pragma unroll
    for (int mi = 0; mi < 2; mi++)
        a_off[mi] = (uint32_t)((warp_m + mi * 16 + a_row) * BSTR64 + a_col);
    int b_row = (lane & 7) + ((lane >> 4) & 1) * 8;
    int b_col = ((lane >> 3) & 1) * 16;
    uint32_t b_off[4];
#pragma unroll
    for (int njp = 0; njp < 4; njp++)
        b_off[njp] = (uint32_t)((warp_n + njp * 16 + b_row) * BSTR64 + b_col);

    // staging: per tile 128 rows x 8 cols of 16B = 1024 xfers; 4 per thread
    int rws[4], cws[4];
    uint32_t sws[4];
#pragma unroll
    for (int i = 0; i < 4; i++) {
        int idx = tid + i * 256;
        rws[i] = idx >> 3;
        cws[i] = idx & 7;
        sws[i] = (uint32_t)(rws[i] * BSTR64 + cws[i] * 16);
    }

    float acc[2][8][4];
#pragma unroll
    for (int mi = 0; mi < 2; mi++)
#pragma unroll
        for (int nj = 0; nj < 8; nj++)
#pragma unroll
            for (int q = 0; q < 4; q++) acc[mi][nj][q] = 0.f;

#pragma unroll
    for (int s = 0; s < NST64 - 1; s++) {
        uint32_t st = sbase + s * STAGE64;
        int k0 = s * GBK64;
#pragma unroll
        for (int i = 0; i < 4; i++) {
            cp_async16(st + sws[i],
                       A + (size_t)(m0 + rws[i]) * E_DIM + k0 + cws[i] * 8);
            cp_async16(st + TILE64 + sws[i],
                       B + (size_t)(n0 + rws[i]) * E_DIM + k0 + cws[i] * 8);
        }
        CP_COMMIT();
    }

    int slot = 0, wslot = NST64 - 1;
    for (int c = 0; c < NCHUNK64; c++) {
        CP_WAIT1();
        __syncthreads();

        uint32_t st = sbase + (uint32_t)slot * STAGE64;
#pragma unroll
        for (int kc = 0; kc < 4; kc++) {
            uint32_t ko = (uint32_t)(kc * 32);
            uint32_t a4[2][4];
#pragma unroll
            for (int mi = 0; mi < 2; mi++)
                ldsm_x4(st + a_off[mi] + ko, a4[mi]);
#pragma unroll
            for (int njp = 0; njp < 4; njp++) {
                uint32_t b4[4];
                ldsm_x4(st + TILE64 + b_off[njp] + ko, b4);
                int nj0 = njp * 2, nj1 = njp * 2 + 1;
                mma_f16(acc[0][nj0], a4[0], b4 + 0);
                mma_f16(acc[1][nj0], a4[1], b4 + 0);
                mma_f16(acc[0][nj1], a4[0], b4 + 2);
                mma_f16(acc[1][nj1], a4[1], b4 + 2);
            }
        }

        if (c + NST64 - 1 < NCHUNK64) {
            uint32_t sw = sbase + (uint32_t)wslot * STAGE64;
            int k0 = (c + NST64 - 1) * GBK64;
#pragma unroll
            for (int i = 0; i < 4; i++) {
                cp_async16(sw + sws[i],
                           A + (size_t)(m0 + rws[i]) * E_DIM + k0 + cws[i] * 8);
                cp_async16(sw + TILE64 + sws[i],
                           B + (size_t)(n0 + rws[i]) * E_DIM + k0 + cws[i] * 8);
            }
        }
        CP_COMMIT();
        slot = (slot + 1 == NST64) ? 0 : slot + 1;
        wslot = (wslot + 1 == NST64) ? 0 : wslot + 1;
    }

    gemm_epilogue(acc, m0, n0, warp_m, warp_n, gidx, lane & 3, Cout, mode);
}

__global__ __launch_bounds__(256, 2) void gemm_qkv_tc(void) {
    int z = blockIdx.z;
    const __half* b = g_w + (size_t)z * E_DIM * E_DIM;
    if (z == 0)
        gemm_body32_split(g_x_hi, g_x_lo, b);  // Q: 2-term, BK=32
    else
        gemm_body64_single(g_x_hi, b, nullptr, z);  // K,V: 1-term, BK=64
}

__global__ __launch_bounds__(256, 2) void gemm_out_tc(float* __restrict__ out) {
    const __half* b = g_w + (size_t)3 * E_DIM * E_DIM;
    gemm_body64_single(g_attn, b, out, 3);
}

// ---------------- Tensor-core flash attention (causal, cp.async DB) ---------
// 4 warps, q-tile 64, k-tile 64, 2-stage DB. Q split; P single; attn single out.
#define FKT 64
#define KSTR2 272
#define VSTR3 144
#define F_K 0
#define F_V (64 * KSTR2)            /* 17408 */
#define F_STAGE (F_V + 128 * VSTR3) /* 35840 */
#define FLASH_SMEM (2 * F_STAGE)    /* 71680 */

__device__ __forceinline__ void flash_stage_load(uint32_t sst,
                                                 const __half* K,
                                                 const __half* Vt, int kt,
                                                 int tid) {
    int k0 = kt * FKT;
#pragma unroll
    for (int i = 0; i < 8; i++) {
        int idx = tid + i * 128;
        int row = idx >> 4, cc = idx & 15;
        cp_async16(sst + F_K + (uint32_t)(row * KSTR2 + cc * 16),
                   K + (size_t)(k0 + row) * HD + cc * 8);
    }
#pragma unroll
    for (int i = 0; i < 8; i++) {
        int idx = tid + i * 128;
        int row = idx >> 3, cc = idx & 7;
        cp_async16(sst + F_V + (uint32_t)(row * VSTR3 + cc * 16),
                   Vt + (size_t)row * SEQ + k0 + cc * 8);
    }
}

__global__ __launch_bounds__(128) void flash_mma_kernel() {
    extern __shared__ char sm[];
    uint32_t sm32 = smem_u32(sm);

    int tid = threadIdx.x;
    int wid = tid >> 5;
    int lane = tid & 31;
    int qt = (int)gridDim.x - 1 - (int)blockIdx.x;  // heavy tiles first
    int bh = blockIdx.y;
    int g = lane >> 2;
    int c = lane & 3;
    int warp_m = wid * 16;
    int nkt = qt + 1;

    int b_row = (lane & 7) + ((lane >> 4) & 1) * 8;
    int b_col = ((lane >> 3) & 1) * 16;
    uint32_t k_off[4], v_off[8];
#pragma unroll
    for (int njp = 0; njp < 4; njp++)
        k_off[njp] = (uint32_t)((njp * 16 + b_row) * KSTR2 + b_col);
#pragma unroll
    for (int njp = 0; njp < 8; njp++)
        v_off[njp] = (uint32_t)((njp * 16 + b_row) * VSTR3 + b_col);

    const __half* K = g_k + (size_t)bh * SEQ * HD;
    const __half* Vt = g_vt + (size_t)bh * HD * SEQ;

    flash_stage_load(sm32, K, Vt, 0, tid);
    CP_COMMIT();

    uint32_t qh[8][4], ql[8][4];
    {
        const __half* Qh = g_qhi + (size_t)bh * SEQ * HD + (size_t)qt * 64 * HD;
        const __half* Ql = g_qlo + (size_t)bh * SEQ * HD + (size_t)qt * 64 * HD;
        int r0 = (warp_m + g) * HD, r1 = (warp_m + g + 8) * HD;
#pragma unroll
        for (int kc = 0; kc < 8; kc++) {
            int c0 = kc * 16 + c * 2, c1 = c0 + 8;
            qh[kc][0] = *(const uint32_t*)(Qh + r0 + c0);
            qh[kc][1] = *(const uint32_t*)(Qh + r1 + c0);
            qh[kc][2] = *(const uint32_t*)(Qh + r0 + c1);
            qh[kc][3] = *(const uint32_t*)(Qh + r1 + c1);
            ql[kc][0] = *(const uint32_t*)(Ql + r0 + c0);
            ql[kc][1] = *(const uint32_t*)(Ql + r1 + c0);
            ql[kc][2] = *(const uint32_t*)(Ql + r0 + c1);
            ql[kc][3] = *(const uint32_t*)(Ql + r1 + c1);
        }
    }

    float o[16][4];
#pragma unroll
    for (int t = 0; t < 16; t++)
#pragma unroll
        for (int q = 0; q < 4; q++) o[t][q] = 0.f;
    float m0 = -1e30f, m1 = -1e30f, l0 = 0.f, l1 = 0.f;

    for (int kt = 0; kt < nkt; kt++) {
        if (kt + 1 < nkt)
            flash_stage_load(sm32 + ((kt + 1) & 1) * F_STAGE, K, Vt, kt + 1, tid);
        CP_COMMIT();
        CP_WAIT1();
        __syncthreads();

        uint32_t st = sm32 + (uint32_t)(kt & 1) * F_STAGE;

        float s_acc[8][4];
#pragma unroll
        for (int nj = 0; nj < 8; nj++)
#pragma unroll
            for (int q = 0; q < 4; q++) s_acc[nj][q] = 0.f;

#pragma unroll
        for (int kc = 0; kc < 8; kc++) {
#pragma unroll
            for (int njp = 0; njp < 4; njp++) {
                uint32_t b4[4];
                ldsm_x4(st + F_K + k_off[njp] + kc * 32, b4);
                int nj0 = njp * 2, nj1 = njp * 2 + 1;
                mma_f16(s_acc[nj0], qh[kc], b4 + 0);
                mma_f16(s_acc[nj1], qh[kc], b4 + 2);
                mma_f16(s_acc[nj0], ql[kc], b4 + 0);
                mma_f16(s_acc[nj1], ql[kc], b4 + 2);
            }
        }

        if (kt == qt) {
            int row0 = qt * 64 + warp_m + g, row1 = row0 + 8;
            int colb = kt * FKT;
#pragma unroll
            for (int nj = 0; nj < 8; nj++) {
                int col = colb + nj * 8 + c * 2;
                if (col > row0) s_acc[nj][0] = -1e30f;
                if (col + 1 > row0) s_acc[nj][1] = -1e30f;
                if (col > row1) s_acc[nj][2] = -1e30f;
                if (col + 1 > row1) s_acc[nj][3] = -1e30f;
            }
        }

        float mt0 = -1e30f, mt1 = -1e30f;
#pragma unroll
        for (int nj = 0; nj < 8; nj++) {
            mt0 = fmaxf(mt0, fmaxf(s_acc[nj][0], s_acc[nj][1]));
            mt1 = fmaxf(mt1, fmaxf(s_acc[nj][2], s_acc[nj][3]));
        }
        mt0 = fmaxf(mt0, __shfl_xor_sync(0xffffffffu, mt0, 1));
        mt0 = fmaxf(mt0, __shfl_xor_sync(0xffffffffu, mt0, 2));
        mt1 = fmaxf(mt1, __shfl_xor_sync(0xffffffffu, mt1, 1));
        mt1 = fmaxf(mt1, __shfl_xor_sync(0xffffffffu, mt1, 2));
        float mn0 = fmaxf(m0, mt0), mn1 = fmaxf(m1, mt1);
        float a0 = __expf(m0 - mn0), a1 = __expf(m1 - mn1);
        m0 = mn0; m1 = mn1;
#pragma unroll
        for (int t = 0; t < 16; t++) {
            o[t][0] *= a0; o[t][1] *= a0;
            o[t][2] *= a1; o[t][3] *= a1;
        }
        float rs0 = 0.f, rs1 = 0.f;
#pragma unroll
        for (int nj = 0; nj < 8; nj++) {
            float p0 = __expf(s_acc[nj][0] - mn0);
            float p1 = __expf(s_acc[nj][1] - mn0);
            float p2 = __expf(s_acc[nj][2] - mn1);
            float p3 = __expf(s_acc[nj][3] - mn1);
            s_acc[nj][0] = p0; s_acc[nj][1] = p1;
            s_acc[nj][2] = p2; s_acc[nj][3] = p3;
            rs0 += p0 + p1; rs1 += p2 + p3;
        }
        l0 = l0 * a0 + rs0;
        l1 = l1 * a1 + rs1;

        uint32_t ph[4][4];
#pragma unroll
        for (int kc = 0; kc < 4; kc++) {
            ph[kc][0] = pack2h(s_acc[2 * kc][0], s_acc[2 * kc][1]);
            ph[kc][1] = pack2h(s_acc[2 * kc][2], s_acc[2 * kc][3]);
            ph[kc][2] = pack2h(s_acc[2 * kc + 1][0], s_acc[2 * kc + 1][1]);
            ph[kc][3] = pack2h(s_acc[2 * kc + 1][2], s_acc[2 * kc + 1][3]);
        }

#pragma unroll
        for (int njp = 0; njp < 8; njp++) {
#pragma unroll
            for (int kc = 0; kc < 4; kc++) {
                uint32_t v4[4];
                ldsm_x4(st + F_V + v_off[njp] + kc * 32, v4);
                int nj0 = njp * 2, nj1 = njp * 2 + 1;
                mma_f16(o[nj0], ph[kc], v4 + 0);
                mma_f16(o[nj1], ph[kc], v4 + 2);
            }
        }
        __syncthreads();
    }

    l0 += __shfl_xor_sync(0xffffffffu, l0, 1);
    l0 += __shfl_xor_sync(0xffffffffu, l0, 2);
    l1 += __shfl_xor_sync(0xffffffffu, l1, 1);
    l1 += __shfl_xor_sync(0xffffffffu, l1, 2);
    float i0 = 1.0f / l0, i1 = 1.0f / l1;
    int b = bh >> 4, h = bh & 15;
    int s0 = qt * 64 + warp_m + g;
    size_t r0 = ((size_t)b * SEQ + s0) * E_DIM + h * HD;
    size_t r1 = ((size_t)b * SEQ + s0 + 8) * E_DIM + h * HD;
#pragma unroll
    for (int nj = 0; nj < 16; nj++) {
        int d = nj * 8 + c * 2;
        store2h(g_attn, r0 + d, o[nj][0] * i0, o[nj][1] * i0);
        store2h(g_attn, r1 + d, o[nj][2] * i1, o[nj][3] * i1);
    }
}

// ---------------- launcher ---------------------------------------------------
extern "C" void kernel_launch(void* const* d_in, const int* in_sizes, int n_in,
                              void* d_out, int out_size) {
    const float* x = (const float*)d_in[0];
    const float* Wq = (const float*)d_in[1];
    const float* Wk = (const float*)d_in[2];
    const float* Wv = (const float*)d_in[3];
    const float* Wo = (const float*)d_in[4];
    float* out = (float*)d_out;

    cudaFuncSetAttribute(gemm_qkv_tc, cudaFuncAttributeMaxDynamicSharedMemorySize,
                         GEMM_SMEM);
    cudaFuncSetAttribute(gemm_out_tc, cudaFuncAttributeMaxDynamicSharedMemorySize,
                         GEMM_SMEM);
    cudaFuncSetAttribute(flash_mma_kernel,
                         cudaFuncAttributeMaxDynamicSharedMemorySize, FLASH_SMEM);

    rope_init_kernel<<<(SEQ * (HD / 2) + 255) / 256, 256>>>();

    {
        int n4 = MROWS * E_DIM / 4;
        convert_x_kernel<<<(n4 + 255) / 256, 256>>>((const float4*)x);
        int w4 = E_DIM * E_DIM / 4;
        dim3 gw((w4 + 255) / 256, 4);
        convert_w_kernel<<<gw, 256>>>((const float4*)Wq, (const float4*)Wk,
                                      (const float4*)Wv, (const float4*)Wo);
    }

    dim3 gqkv(E_DIM / GBN, MROWS / GBM, 3);
    gemm_qkv_tc<<<gqkv, 256, GEMM_SMEM>>>();

    dim3 gfa(SEQ / 64, NBATCH * NHEAD);
    flash_mma_kernel<<<gfa, 128, FLASH_SMEM>>>();

    dim3 gout(E_DIM / GBN, MROWS / GBM);
    gemm_out_tc<<<gout, 256, GEMM_SMEM>>>(out);
}

// round 17
// speedup vs baseline: 2.7670x; 1.1252x over previous
#include <cuda_runtime.h>
#include <cuda_fp16.h>
#include <math.h>
#include <stdint.h>

#define E_DIM 2048
#define SEQ 2048
#define NBATCH 2
#define NHEAD 16
#define HD 128
#define MROWS (NBATCH * SEQ) /* 4096 */

// ---------------- scratch (device globals; no allocation allowed) ----------
__device__ __half g_x[MROWS * E_DIM];
__device__ __half g_w[4 * E_DIM * E_DIM];
__device__ __half g_q[MROWS * E_DIM];   // [bh][s][d], rope+scale applied
__device__ __half g_k[MROWS * E_DIM];   // [bh][s][d], rope applied
__device__ __half g_vt[MROWS * E_DIM];  // V transposed [bh][d][s]
__device__ __half g_attn[MROWS * E_DIM];
__device__ float g_cos[SEQ * (HD / 2)];
__device__ float g_sin[SEQ * (HD / 2)];

// ---------------- helpers ----------------------------------------------------
__device__ __forceinline__ uint32_t smem_u32(const void* p) {
    uint32_t a;
    asm("{ .reg .u64 t; cvta.to.shared.u64 t, %1; cvt.u32.u64 %0, t; }"
        : "=r"(a) : "l"(p));
    return a;
}
__device__ __forceinline__ void cp_async16(uint32_t dst, const void* src) {
    asm volatile("cp.async.cg.shared.global [%0], [%1], 16;"
                 :: "r"(dst), "l"(src));
}
#define CP_COMMIT() asm volatile("cp.async.commit_group;" ::: "memory")
#define CP_WAIT1() asm volatile("cp.async.wait_group 1;" ::: "memory")

__device__ __forceinline__ void ldsm_x4(uint32_t addr, uint32_t* r) {
    asm volatile("ldmatrix.sync.aligned.m8n8.x4.shared.b16 {%0,%1,%2,%3}, [%4];"
                 : "=r"(r[0]), "=r"(r[1]), "=r"(r[2]), "=r"(r[3]) : "r"(addr));
}

__device__ __forceinline__ void mma_f16(float* d, const uint32_t* a,
                                        const uint32_t* b) {
    asm volatile(
        "mma.sync.aligned.m16n8k16.row.col.f32.f16.f16.f32 "
        "{%0,%1,%2,%3}, {%4,%5,%6,%7}, {%8,%9}, {%0,%1,%2,%3};"
        : "+f"(d[0]), "+f"(d[1]), "+f"(d[2]), "+f"(d[3])
        : "r"(a[0]), "r"(a[1]), "r"(a[2]), "r"(a[3]), "r"(b[0]), "r"(b[1]));
}

__device__ __forceinline__ uint32_t pack2h(float x, float y) {
    __half2 h(__float2half_rn(x), __float2half_rn(y));
    return *(uint32_t*)&h;
}

__device__ __forceinline__ void store2h(__half* dst, size_t idx, float x,
                                        float y) {
    *(uint32_t*)(dst + idx) = pack2h(x, y);
}

// ---------------- RoPE table ------------------------------------------------
__global__ void rope_init_kernel() {
    int idx = blockIdx.x * blockDim.x + threadIdx.x;
    if (idx >= SEQ * (HD / 2)) return;
    int pos = idx / (HD / 2);
    int i = idx % (HD / 2);
    double invd = pow(10000.0, -(double)(2 * i) / (double)HD);
    float inv = (float)invd;
    float ang = (float)pos * inv;
    g_cos[idx] = (float)cos((double)ang);
    g_sin[idx] = (float)sin((double)ang);
}

// ---------------- conversions ------------------------------------------------
__global__ void convert_x_kernel(const float4* __restrict__ src) {
    int i = blockIdx.x * blockDim.x + threadIdx.x;
    if (i >= MROWS * E_DIM / 4) return;
    float4 v = src[i];
    ((uint32_t*)g_x)[i * 2 + 0] = pack2h(v.x, v.y);
    ((uint32_t*)g_x)[i * 2 + 1] = pack2h(v.z, v.w);
}

__global__ void convert_w_kernel(const float4* __restrict__ w0,
                                 const float4* __restrict__ w1,
                                 const float4* __restrict__ w2,
                                 const float4* __restrict__ w3) {
    int i = blockIdx.x * blockDim.x + threadIdx.x;
    if (i >= E_DIM * E_DIM / 4) return;
    int z = blockIdx.y;
    const float4* src = (z == 0) ? w0 : (z == 1) ? w1 : (z == 2) ? w2 : w3;
    float4 v = src[i];
    uint32_t* dst = (uint32_t*)(g_w + (size_t)z * E_DIM * E_DIM);
    dst[i * 2 + 0] = pack2h(v.x, v.y);
    dst[i * 2 + 1] = pack2h(v.z, v.w);
}

// ---------------- HMMA GEMM: 128x128, BK=64, 1-term, 3-stage -----------------
#define GBM 128
#define GBN 128
#define GBK64 64
#define NCHUNK64 (E_DIM / GBK64) /* 32 */
#define BSTR64 144
#define TILE64 (128 * BSTR64)     /* 18432 */
#define STAGE64 (2 * TILE64)      /* 36864 */
#define NST64 3
#define GEMM_SMEM (NST64 * STAGE64) /* 110592 */

// mode: 0=Q (rope+scale), 1=K (rope), 2=V->g_vt transposed, 3=fp32 out
__device__ __forceinline__ void gemm_body64_single(
    const __half* __restrict__ A, const __half* __restrict__ B,
    float* __restrict__ Cout, int mode) {
    extern __shared__ char smem[];
    uint32_t sbase = smem_u32(smem);
    int tid = threadIdx.x;
    int wid = tid >> 5;
    int lane = tid & 31;
    int m0 = blockIdx.y * GBM;
    int n0 = blockIdx.x * GBN;
    int warp_m = (wid & 3) * 32;
    int warp_n = (wid >> 2) * 64;
    int gidx = lane >> 2;
    int tig = lane & 3;

    int a_row = (lane & 7) + ((lane >> 3) & 1) * 8;
    int a_col = (lane >> 4) * 16;
    uint32_t a_off[2];
#pragma unroll
    for (int mi = 0; mi < 2; mi++)
        a_off[mi] = (uint32_t)((warp_m + mi * 16 + a_row) * BSTR64 + a_col);
    int b_row = (lane & 7) + ((lane >> 4) & 1) * 8;
    int b_col = ((lane >> 3) & 1) * 16;
    uint32_t b_off[4];
#pragma unroll
    for (int njp = 0; njp < 4; njp++)
        b_off[njp] = (uint32_t)((warp_n + njp * 16 + b_row) * BSTR64 + b_col);

    int rws[4], cws[4];
    uint32_t sws[4];
#pragma unroll
    for (int i = 0; i < 4; i++) {
        int idx = tid + i * 256;
        rws[i] = idx >> 3;
        cws[i] = idx & 7;
        sws[i] = (uint32_t)(rws[i] * BSTR64 + cws[i] * 16);
    }

    float acc[2][8][4];
#pragma unroll
    for (int mi = 0; mi < 2; mi++)
#pragma unroll
        for (int nj = 0; nj < 8; nj++)
#pragma unroll
            for (int q = 0; q < 4; q++) acc[mi][nj][q] = 0.f;

#pragma unroll
    for (int s = 0; s < NST64 - 1; s++) {
        uint32_t st = sbase + s * STAGE64;
        int k0 = s * GBK64;
#pragma unroll
        for (int i = 0; i < 4; i++) {
            cp_async16(st + sws[i],
                       A + (size_t)(m0 + rws[i]) * E_DIM + k0 + cws[i] * 8);
            cp_async16(st + TILE64 + sws[i],
                       B + (size_t)(n0 + rws[i]) * E_DIM + k0 + cws[i] * 8);
        }
        CP_COMMIT();
    }

    int slot = 0, wslot = NST64 - 1;
    for (int c = 0; c < NCHUNK64; c++) {
        CP_WAIT1();
        __syncthreads();

        uint32_t st = sbase + (uint32_t)slot * STAGE64;
#pragma unroll
        for (int kc = 0; kc < 4; kc++) {
            uint32_t ko = (uint32_t)(kc * 32);
            uint32_t a4[2][4];
#pragma unroll
            for (int mi = 0; mi < 2; mi++)
                ldsm_x4(st + a_off[mi] + ko, a4[mi]);
#pragma unroll
            for (int njp = 0; njp < 4; njp++) {
                uint32_t b4[4];
                ldsm_x4(st + TILE64 + b_off[njp] + ko, b4);
                int nj0 = njp * 2, nj1 = njp * 2 + 1;
                mma_f16(acc[0][nj0], a4[0], b4 + 0);
                mma_f16(acc[1][nj0], a4[1], b4 + 0);
                mma_f16(acc[0][nj1], a4[0], b4 + 2);
                mma_f16(acc[1][nj1], a4[1], b4 + 2);
            }
        }

        if (c + NST64 - 1 < NCHUNK64) {
            uint32_t sw = sbase + (uint32_t)wslot * STAGE64;
            int k0 = (c + NST64 - 1) * GBK64;
#pragma unroll
            for (int i = 0; i < 4; i++) {
                cp_async16(sw + sws[i],
                           A + (size_t)(m0 + rws[i]) * E_DIM + k0 + cws[i] * 8);
                cp_async16(sw + TILE64 + sws[i],
                           B + (size_t)(n0 + rws[i]) * E_DIM + k0 + cws[i] * 8);
            }
        }
        CP_COMMIT();
        slot = (slot + 1 == NST64) ? 0 : slot + 1;
        wslot = (wslot + 1 == NST64) ? 0 : wslot + 1;
    }

    // epilogue
    const float qsc = (mode == 0) ? 0.08838834764831845f : 1.0f;
#pragma unroll
    for (int mi = 0; mi < 2; mi++) {
#pragma unroll
        for (int nj = 0; nj < 8; nj++) {
            int m = m0 + warp_m + mi * 16 + gidx;
            int n = n0 + warp_n + nj * 8 + tig * 2;
            float v0 = acc[mi][nj][0], v1 = acc[mi][nj][1];
            float v2 = acc[mi][nj][2], v3 = acc[mi][nj][3];
            if (mode <= 1) {
                int pi = (n & (HD - 1)) >> 1;
                int p0 = m & (SEQ - 1);
                int p8 = p0 + 8;
                float c0 = g_cos[p0 * (HD / 2) + pi], sn0 = g_sin[p0 * (HD / 2) + pi];
                float c8 = g_cos[p8 * (HD / 2) + pi], sn8 = g_sin[p8 * (HD / 2) + pi];
                float t0 = v0 * c0 - v1 * sn0, t1 = v0 * sn0 + v1 * c0;
                float t2 = v2 * c8 - v3 * sn8, t3 = v2 * sn8 + v3 * c8;
                v0 = t0 * qsc; v1 = t1 * qsc; v2 = t2 * qsc; v3 = t3 * qsc;
            }
            if (mode == 3) {
                *(float2*)&Cout[(size_t)m * E_DIM + n] = make_float2(v0, v1);
                *(float2*)&Cout[(size_t)(m + 8) * E_DIM + n] = make_float2(v2, v3);
            } else {
                int b = m >> 11, s = m & 2047, h = n >> 7, d = n & 127;
                int bh = b * NHEAD + h;
                if (mode == 2) {
                    size_t tb = ((size_t)bh * HD + d) * SEQ + s;
                    g_vt[tb] = __float2half_rn(v0);
                    g_vt[tb + SEQ] = __float2half_rn(v1);
                    g_vt[tb + 8] = __float2half_rn(v2);
                    g_vt[tb + SEQ + 8] = __float2half_rn(v3);
                } else {
                    __half* dst = (mode == 0) ? g_q : g_k;
                    size_t base0 = ((size_t)bh * SEQ + s) * HD + d;
                    store2h(dst, base0, v0, v1);
                    store2h(dst, base0 + 8 * HD, v2, v3);
                }
            }
        }
    }
}

__global__ __launch_bounds__(256, 2) void gemm_qkv_tc(void) {
    int z = blockIdx.z;
    const __half* b = g_w + (size_t)z * E_DIM * E_DIM;
    gemm_body64_single(g_x, b, nullptr, z);
}

__global__ __launch_bounds__(256, 2) void gemm_out_tc(float* __restrict__ out) {
    const __half* b = g_w + (size_t)3 * E_DIM * E_DIM;
    gemm_body64_single(g_attn, b, out, 3);
}

// ---------------- Tensor-core flash attention (causal, cp.async DB) ---------
// 4 warps, q-tile 64, k-tile 64, 2-stage DB. All operands single fp16.
#define FKT 64
#define KSTR2 272
#define VSTR3 144
#define F_K 0
#define F_V (64 * KSTR2)            /* 17408 */
#define F_STAGE (F_V + 128 * VSTR3) /* 35840 */
#define FLASH_SMEM (2 * F_STAGE)    /* 71680 */

__device__ __forceinline__ void flash_stage_load(uint32_t sst,
                                                 const __half* K,
                                                 const __half* Vt, int kt,
                                                 int tid) {
    int k0 = kt * FKT;
#pragma unroll
    for (int i = 0; i < 8; i++) {
        int idx = tid + i * 128;
        int row = idx >> 4, cc = idx & 15;
        cp_async16(sst + F_K + (uint32_t)(row * KSTR2 + cc * 16),
                   K + (size_t)(k0 + row) * HD + cc * 8);
    }
#pragma unroll
    for (int i = 0; i < 8; i++) {
        int idx = tid + i * 128;
        int row = idx >> 3, cc = idx & 7;
        cp_async16(sst + F_V + (uint32_t)(row * VSTR3 + cc * 16),
                   Vt + (size_t)row * SEQ + k0 + cc * 8);
    }
}

__global__ __launch_bounds__(128) void flash_mma_kernel() {
    extern __shared__ char sm[];
    uint32_t sm32 = smem_u32(sm);

    int tid = threadIdx.x;
    int wid = tid >> 5;
    int lane = tid & 31;
    int qt = (int)gridDim.x - 1 - (int)blockIdx.x;  // heavy tiles first
    int bh = blockIdx.y;
    int g = lane >> 2;
    int c = lane & 3;
    int warp_m = wid * 16;
    int nkt = qt + 1;

    int b_row = (lane & 7) + ((lane >> 4) & 1) * 8;
    int b_col = ((lane >> 3) & 1) * 16;
    uint32_t k_off[4], v_off[8];
#pragma unroll
    for (int njp = 0; njp < 4; njp++)
        k_off[njp] = (uint32_t)((njp * 16 + b_row) * KSTR2 + b_col);
#pragma unroll
    for (int njp = 0; njp < 8; njp++)
        v_off[njp] = (uint32_t)((njp * 16 + b_row) * VSTR3 + b_col);

    const __half* K = g_k + (size_t)bh * SEQ * HD;
    const __half* Vt = g_vt + (size_t)bh * HD * SEQ;

    flash_stage_load(sm32, K, Vt, 0, tid);
    CP_COMMIT();

    uint32_t qh[8][4];
    {
        const __half* Q = g_q + (size_t)bh * SEQ * HD + (size_t)qt * 64 * HD;
        int r0 = (warp_m + g) * HD, r1 = (warp_m + g + 8) * HD;
#pragma unroll
        for (int kc = 0; kc < 8; kc++) {
            int c0 = kc * 16 + c * 2, c1 = c0 + 8;
            qh[kc][0] = *(const uint32_t*)(Q + r0 + c0);
            qh[kc][1] = *(const uint32_t*)(Q + r1 + c0);
            qh[kc][2] = *(const uint32_t*)(Q + r0 + c1);
            qh[kc][3] = *(const uint32_t*)(Q + r1 + c1);
        }
    }

    float o[16][4];
#pragma unroll
    for (int t = 0; t < 16; t++)
#pragma unroll
        for (int q = 0; q < 4; q++) o[t][q] = 0.f;
    float m0 = -1e30f, m1 = -1e30f, l0 = 0.f, l1 = 0.f;

    for (int kt = 0; kt < nkt; kt++) {
        if (kt + 1 < nkt)
            flash_stage_load(sm32 + ((kt + 1) & 1) * F_STAGE, K, Vt, kt + 1, tid);
        CP_COMMIT();
        CP_WAIT1();
        __syncthreads();

        uint32_t st = sm32 + (uint32_t)(kt & 1) * F_STAGE;

        // ---- S = Q @ K^T (16q x 64k per warp) ----
        float s_acc[8][4];
#pragma unroll
        for (int nj = 0; nj < 8; nj++)
#pragma unroll
            for (int q = 0; q < 4; q++) s_acc[nj][q] = 0.f;

#pragma unroll
        for (int kc = 0; kc < 8; kc++) {
#pragma unroll
            for (int njp = 0; njp < 4; njp++) {
                uint32_t b4[4];
                ldsm_x4(st + F_K + k_off[njp] + kc * 32, b4);
                mma_f16(s_acc[njp * 2], qh[kc], b4 + 0);
                mma_f16(s_acc[njp * 2 + 1], qh[kc], b4 + 2);
            }
        }

        // ---- causal mask (diagonal tile only) ----
        if (kt == qt) {
            int row0 = qt * 64 + warp_m + g, row1 = row0 + 8;
            int colb = kt * FKT;
#pragma unroll
            for (int nj = 0; nj < 8; nj++) {
                int col = colb + nj * 8 + c * 2;
                if (col > row0) s_acc[nj][0] = -1e30f;
                if (col + 1 > row0) s_acc[nj][1] = -1e30f;
                if (col > row1) s_acc[nj][2] = -1e30f;
                if (col + 1 > row1) s_acc[nj][3] = -1e30f;
            }
        }

        // ---- online softmax ----
        float mt0 = -1e30f, mt1 = -1e30f;
#pragma unroll
        for (int nj = 0; nj < 8; nj++) {
            mt0 = fmaxf(mt0, fmaxf(s_acc[nj][0], s_acc[nj][1]));
            mt1 = fmaxf(mt1, fmaxf(s_acc[nj][2], s_acc[nj][3]));
        }
        mt0 = fmaxf(mt0, __shfl_xor_sync(0xffffffffu, mt0, 1));
        mt0 = fmaxf(mt0, __shfl_xor_sync(0xffffffffu, mt0, 2));
        mt1 = fmaxf(mt1, __shfl_xor_sync(0xffffffffu, mt1, 1));
        mt1 = fmaxf(mt1, __shfl_xor_sync(0xffffffffu, mt1, 2));
        float mn0 = fmaxf(m0, mt0), mn1 = fmaxf(m1, mt1);
        float a0 = __expf(m0 - mn0), a1 = __expf(m1 - mn1);
        m0 = mn0; m1 = mn1;
#pragma unroll
        for (int t = 0; t < 16; t++) {
            o[t][0] *= a0; o[t][1] *= a0;
            o[t][2] *= a1; o[t][3] *= a1;
        }
        float rs0 = 0.f, rs1 = 0.f;
#pragma unroll
        for (int nj = 0; nj < 8; nj++) {
            float p0 = __expf(s_acc[nj][0] - mn0);
            float p1 = __expf(s_acc[nj][1] - mn0);
            float p2 = __expf(s_acc[nj][2] - mn1);
            float p3 = __expf(s_acc[nj][3] - mn1);
            s_acc[nj][0] = p0; s_acc[nj][1] = p1;
            s_acc[nj][2] = p2; s_acc[nj][3] = p3;
            rs0 += p0 + p1; rs1 += p2 + p3;
        }
        l0 = l0 * a0 + rs0;
        l1 = l1 * a1 + rs1;

        // ---- P fragments (A-layout, single fp16) ----
        uint32_t ph[4][4];
#pragma unroll
        for (int kc = 0; kc < 4; kc++) {
            ph[kc][0] = pack2h(s_acc[2 * kc][0], s_acc[2 * kc][1]);
            ph[kc][1] = pack2h(s_acc[2 * kc][2], s_acc[2 * kc][3]);
            ph[kc][2] = pack2h(s_acc[2 * kc + 1][0], s_acc[2 * kc + 1][1]);
            ph[kc][3] = pack2h(s_acc[2 * kc + 1][2], s_acc[2 * kc + 1][3]);
        }

        // ---- O += P @ V ----
#pragma unroll
        for (int njp = 0; njp < 8; njp++) {
#pragma unroll
            for (int kc = 0; kc < 4; kc++) {
                uint32_t v4[4];
                ldsm_x4(st + F_V + v_off[njp] + kc * 32, v4);
                mma_f16(o[njp * 2], ph[kc], v4 + 0);
                mma_f16(o[njp * 2 + 1], ph[kc], v4 + 2);
            }
        }
        __syncthreads();  // reads of this stage done before it is rewritten
    }

    l0 += __shfl_xor_sync(0xffffffffu, l0, 1);
    l0 += __shfl_xor_sync(0xffffffffu, l0, 2);
    l1 += __shfl_xor_sync(0xffffffffu, l1, 1);
    l1 += __shfl_xor_sync(0xffffffffu, l1, 2);
    float i0 = 1.0f / l0, i1 = 1.0f / l1;
    int b = bh >> 4, h = bh & 15;
    int s0 = qt * 64 + warp_m + g;
    size_t r0 = ((size_t)b * SEQ + s0) * E_DIM + h * HD;
    size_t r1 = ((size_t)b * SEQ + s0 + 8) * E_DIM + h * HD;
#pragma unroll
    for (int nj = 0; nj < 16; nj++) {
        int d = nj * 8 + c * 2;
        store2h(g_attn, r0 + d, o[nj][0] * i0, o[nj][1] * i0);
        store2h(g_attn, r1 + d, o[nj][2] * i1, o[nj][3] * i1);
    }
}

// ---------------- launcher ---------------------------------------------------
extern "C" void kernel_launch(void* const* d_in, const int* in_sizes, int n_in,
                              void* d_out, int out_size) {
    const float* x = (const float*)d_in[0];
    const float* Wq = (const float*)d_in[1];
    const float* Wk = (const float*)d_in[2];
    const float* Wv = (const float*)d_in[3];
    const float* Wo = (const float*)d_in[4];
    float* out = (float*)d_out;

    cudaFuncSetAttribute(gemm_qkv_tc, cudaFuncAttributeMaxDynamicSharedMemorySize,
                         GEMM_SMEM);
    cudaFuncSetAttribute(gemm_out_tc, cudaFuncAttributeMaxDynamicSharedMemorySize,
                         GEMM_SMEM);
    cudaFuncSetAttribute(flash_mma_kernel,
                         cudaFuncAttributeMaxDynamicSharedMemorySize, FLASH_SMEM);

    rope_init_kernel<<<(SEQ * (HD / 2) + 255) / 256, 256>>>();

    {
        int n4 = MROWS * E_DIM / 4;
        convert_x_kernel<<<(n4 + 255) / 256, 256>>>((const float4*)x);
        int w4 = E_DIM * E_DIM / 4;
        dim3 gw((w4 + 255) / 256, 4);
        convert_w_kernel<<<gw, 256>>>((const float4*)Wq, (const float4*)Wk,
                                      (const float4*)Wv, (const float4*)Wo);
    }

    dim3 gqkv(E_DIM / GBN, MROWS / GBM, 3);
    gemm_qkv_tc<<<gqkv, 256, GEMM_SMEM>>>();

    dim3 gfa(SEQ / 64, NBATCH * NHEAD);
    flash_mma_kernel<<<gfa, 128, FLASH_SMEM>>>();

    dim3 gout(E_DIM / GBN, MROWS / GBM);
    gemm_out_tc<<<gout, 256, GEMM_SMEM>>>(out);
}